// round 8
// baseline (speedup 1.0000x reference)
#include <cuda_runtime.h>
#include <cuda_bf16.h>
#include <math.h>
#include <stdint.h>

#define B  4096
#define T  50
#define U  128
#define N3 384
#define BT (B*T)
#define BN_EPS 1e-3f
#define LEAKY  3e-4f

// ------------ scratch (device globals; no allocation allowed) ------------
__device__ float g_Xp[BT*N3];        // GRU input projection
__device__ float g_hs[BT*U];         // GRU hidden states
__device__ float g_X3[BT*N3];        // AUGRU input projections
__device__ float g_ats[BT];          // attention scores
__device__ float g_hfin[B*U];        // AUGRU final state
__device__ float g_newsterm[B*U];    // news@(W1B+W1C)+b1
__device__ float g_Wau[U*N3];        // packed input  [Wu|Wr|Wc]
__device__ float g_Uau[U*N3];        // packed recur  [Uu|Ur|Uc]
__device__ float g_bau[N3];          // packed [bu|br|bc]
__device__ float g_Wcat[2*U*U];      // [W1A-W1B ; W1D]  (256 x 128)
__device__ float g_W1bc[U*U];        // W1B + W1C
__device__ uint32_t g_Ubf_gru[24576];// bf16 fragment-ordered gru_U   (96 KB)
__device__ uint32_t g_Ubf_au[24576]; // bf16 fragment-ordered [Uu|Ur|Uc]
__device__ float g_Wp_gruW[128*N3];  // tf32 fragment-ordered gru_W
__device__ float g_Wp_au[128*N3];    // tf32 fragment-ordered [Wu|Wr|Wc]
__device__ float g_Wp_1bc[128*128];  // tf32 fragment-ordered W1B+W1C
__device__ float g_Wp_cat[256*128];  // tf32 fragment-ordered Wcat (K=256)
__device__ float g_Wp_att2[128*64];  // tf32 fragment-ordered att_W2

__device__ __forceinline__ float sigf(float x){ return 1.f/(1.f+expf(-x)); }
__device__ __forceinline__ float tanha(float x){
  float y; asm("tanh.approx.f32 %0, %1;" : "=f"(y) : "f"(x)); return y;
}
__device__ __forceinline__ float sigt(float x){ return fmaf(tanha(0.5f*x), 0.5f, 0.5f); }
__device__ __forceinline__ float tf32r(float f){
  uint32_t r; asm("cvt.rna.tf32.f32 %0, %1;" : "=r"(r) : "f"(f));
  return __uint_as_float(r);
}
__device__ __forceinline__ uint32_t bf2(float lo, float hi){
  __nv_bfloat162 v;
  v.x = __float2bfloat16(lo); v.y = __float2bfloat16(hi);
  return *(uint32_t*)&v;
}
__device__ __forceinline__ void mma8(float* d, const uint32_t* a, const uint32_t* b){
  asm volatile("mma.sync.aligned.m16n8k8.row.col.f32.tf32.tf32.f32 "
               "{%0,%1,%2,%3}, {%4,%5,%6,%7}, {%8,%9}, {%0,%1,%2,%3};"
               : "+f"(d[0]), "+f"(d[1]), "+f"(d[2]), "+f"(d[3])
               : "r"(a[0]), "r"(a[1]), "r"(a[2]), "r"(a[3]), "r"(b[0]), "r"(b[1]));
}
__device__ __forceinline__ void mma16(float* d, const uint32_t* a, const uint32_t* b){
  asm volatile("mma.sync.aligned.m16n8k16.row.col.f32.bf16.bf16.f32 "
               "{%0,%1,%2,%3}, {%4,%5,%6,%7}, {%8,%9}, {%0,%1,%2,%3};"
               : "+f"(d[0]), "+f"(d[1]), "+f"(d[2]), "+f"(d[3])
               : "r"(a[0]), "r"(a[1]), "r"(a[2]), "r"(a[3]), "r"(b[0]), "r"(b[1]));
}

// ------------------------------- prep -------------------------------
__global__ void prep_kernel(const float* __restrict__ Wu, const float* __restrict__ bu,
                            const float* __restrict__ Wr, const float* __restrict__ br,
                            const float* __restrict__ Wc, const float* __restrict__ bc,
                            const float* __restrict__ Uu, const float* __restrict__ Ur,
                            const float* __restrict__ Uc,
                            const float* __restrict__ attW1) {
  int id = blockIdx.x*blockDim.x + threadIdx.x;
  if (id < U*N3) {
    int k = id / N3, c = id % N3;
    float w, u;
    if (c < 128)      { w = Wu[k*128 + c];       u = Uu[k*128 + c]; }
    else if (c < 256) { w = Wr[k*128 + (c-128)]; u = Ur[k*128 + (c-128)]; }
    else              { w = Wc[k*128 + (c-256)]; u = Uc[k*128 + (c-256)]; }
    g_Wau[id] = w;
    g_Uau[id] = u;
  }
  if (id < N3)
    g_bau[id] = (id < 128) ? bu[id] : (id < 256 ? br[id-128] : bc[id-256]);
  if (id < 2*U*U) {
    int k = id / 128, c = id % 128;
    float v;
    if (k < 128) v = attW1[k*128 + c] - attW1[U*U + k*128 + c];     // W1A - W1B
    else         v = attW1[3*U*U + (k-128)*128 + c];                // W1D
    g_Wcat[id] = v;
  }
  if (id < U*U)
    g_W1bc[id] = attW1[U*U + id] + attW1[2*U*U + id];
}

// --------------- pack weights fragment-ordered, one launch ---------------
__device__ __forceinline__ void pack_one(const float* __restrict__ Um, float* __restrict__ P,
                                         int N, int idx) {
  int q = idx & 3, lane = (idx >> 2) & 31;
  int Ntp = N >> 4;
  int tp = (idx >> 7) % Ntp, k8 = (idx >> 7) / Ntp;
  int tile = 2*tp + (q >> 1), r = q & 1;
  int k = k8*8 + (lane & 3) + 4*r;
  int n = tile*8 + (lane >> 2);
  P[idx] = tf32r(Um[k*N + n]);
}
__device__ __forceinline__ void pack_bf16_one(const float* __restrict__ Um,
                                              uint32_t* __restrict__ P, int idx) {
  int q = idx & 3, lane = (idx >> 2) & 31;
  int tp = (idx >> 7) % 24, k16 = (idx >> 7) / 24;
  int tile = 2*tp + (q >> 1), r = q & 1;
  int k = k16*16 + 2*(lane & 3) + 8*r;
  int n = tile*8 + (lane >> 2);
  P[idx] = bf2(Um[k*N3 + n], Um[(k+1)*N3 + n]);
}

__global__ void pack_all(const float* __restrict__ gruU, const float* __restrict__ gruW,
                         const float* __restrict__ attW2) {
  int idx = blockIdx.x*256 + threadIdx.x;   // 204800 total
  if (idx < 24576)        pack_bf16_one(gruU,  g_Ubf_gru, idx);
  else if (idx < 49152)   pack_bf16_one(g_Uau, g_Ubf_au,  idx - 24576);
  else if (idx < 98304)   pack_one(gruW,    g_Wp_gruW,   384, idx - 49152);
  else if (idx < 147456)  pack_one(g_Wau,   g_Wp_au,     384, idx - 98304);
  else if (idx < 163840)  pack_one(g_W1bc,  g_Wp_1bc,    128, idx - 147456);
  else if (idx < 196608)  pack_one(g_Wcat,  g_Wp_cat,    128, idx - 163840);
  else if (idx < 204800)  pack_one(attW2,   g_Wp_att2,   64,  idx - 196608);
}

// --------------------- tf32 GEMM, packed-B, K=128 ---------------------
__global__ void gemm_v2(const float* __restrict__ A, int P, long long GS, int RS,
                        const float* __restrict__ Bpk, int Ntp,
                        const float* __restrict__ bias, float* __restrict__ C, int ldc) {
  extern __shared__ float sm[];
  float* As = sm;               // 64 x 132
  float* Bp = sm + 64*132;      // 16384 floats
  const int m0 = blockIdx.x * 64;
  const int c0 = blockIdx.y * 128;
  const int tp0 = blockIdx.y * 8;
  const int tid = threadIdx.x;          // 256
  const int kq = tid >> 5, cq = tid & 31;
  const int lane = tid & 31, wid = tid >> 5;
  const int wm = wid & 1, wn = wid >> 1;
  const int g = lane >> 2, t4 = lane & 3;

  #pragma unroll
  for (int it = 0; it < 8; ++it) {
    int r = kq + 8*it;
    int m = m0 + r;
    const float* ap = A + (long long)(m/P)*GS + (long long)(m%P)*RS;
    float4 v = *(const float4*)(ap + 4*cq);
    float* dst = As + r*132 + 4*cq;
    dst[0]=tf32r(v.x); dst[1]=tf32r(v.y); dst[2]=tf32r(v.z); dst[3]=tf32r(v.w);
  }
  {
    const float4* src = (const float4*)Bpk;
    float4* dst = (float4*)Bp;
    #pragma unroll
    for (int it = 0; it < 16; ++it) {
      int f = it*256 + tid;
      int k8 = f >> 8, rem = f & 255;
      dst[f] = src[((long long)k8*Ntp + tp0)*32 + rem];
    }
  }
  __syncthreads();

  float acc[2][4][4];
  #pragma unroll
  for (int mt=0;mt<2;mt++)
    #pragma unroll
    for (int nt=0;nt<4;nt++)
      #pragma unroll
      for (int q=0;q<4;q++) acc[mt][nt][q] = 0.f;

  const float4* bp4 = (const float4*)Bp;
  #pragma unroll
  for (int k8 = 0; k8 < 16; ++k8) {
    uint32_t a[2][4];
    #pragma unroll
    for (int mt=0;mt<2;mt++) {
      const float* ap = As + (wm*32 + mt*16 + g)*132 + k8*8 + t4;
      a[mt][0] = __float_as_uint(ap[0]);
      a[mt][1] = __float_as_uint(ap[8*132]);
      a[mt][2] = __float_as_uint(ap[4]);
      a[mt][3] = __float_as_uint(ap[8*132+4]);
    }
    float4 b40 = bp4[(k8*8 + wn*2    )*32 + lane];
    float4 b41 = bp4[(k8*8 + wn*2 + 1)*32 + lane];
    uint32_t bb[4][2];
    bb[0][0]=__float_as_uint(b40.x); bb[0][1]=__float_as_uint(b40.y);
    bb[1][0]=__float_as_uint(b40.z); bb[1][1]=__float_as_uint(b40.w);
    bb[2][0]=__float_as_uint(b41.x); bb[2][1]=__float_as_uint(b41.y);
    bb[3][0]=__float_as_uint(b41.z); bb[3][1]=__float_as_uint(b41.w);
    #pragma unroll
    for (int mt=0;mt<2;mt++)
      #pragma unroll
      for (int nt=0;nt<4;nt++)
        mma8(acc[mt][nt], a[mt], bb[nt]);
  }
  #pragma unroll
  for (int mt=0;mt<2;mt++) {
    int row0 = m0 + wm*32 + mt*16 + g;
    #pragma unroll
    for (int nt=0;nt<4;nt++) {
      int col = c0 + wn*32 + nt*8 + 2*t4;
      #pragma unroll
      for (int h=0; h<2; ++h) {
        int row = row0 + 8*h;
        float2 o = {acc[mt][nt][2*h+0] + bias[col], acc[mt][nt][2*h+1] + bias[col+1]};
        *(float2*)(C + (long long)row*ldc + col) = o;
      }
    }
  }
}

// -------------------- GRU scan, bf16 tensor-core (16 rows/CTA, 2 CTAs/SM) --------------------
#define A_STRIDE 136
#define A_BUF16  (16*A_STRIDE)   // bf16 elements per buffer
__global__ __launch_bounds__(256, 2)
void gru_scan_mma(const float* __restrict__ Xp, const uint32_t* __restrict__ Bpack,
                  const float* __restrict__ brec, float* __restrict__ hs) {
  extern __shared__ char smc[];
  uint32_t* Bp = (uint32_t*)smc;                       // 24576 u32
  __nv_bfloat16* Ab = (__nv_bfloat16*)(smc + 98304);   // 2 * A_BUF16
  const int tid = threadIdx.x;    // 256
  const int w = tid >> 5, lane = tid & 31;
  const int g = lane >> 2, t4 = lane & 3;
  const int b0 = blockIdx.x * 16;
  #pragma unroll
  for (int it = 0; it < 24; ++it)
    ((float4*)Bp)[it*256 + tid] = ((const float4*)Bpack)[it*256 + tid];
  for (int i = tid; i < A_BUF16; i += 256) ((uint32_t*)Ab)[i] = 0u;   // 2*A_BUF16 bf16 = A_BUF16 u32
  float2 bz[2], brr[2], bh[2];
  #pragma unroll
  for (int nt=0; nt<2; ++nt) {
    int c = (2*w+nt)*8 + 2*t4;
    bz[nt]  = *(const float2*)(brec + c);
    brr[nt] = *(const float2*)(brec + 128 + c);
    bh[nt]  = *(const float2*)(brec + 256 + c);
  }
  float h[2][2][2];   // [rh][nt][2]
  #pragma unroll
  for (int a2=0;a2<2;a2++)
    #pragma unroll
    for (int a3=0;a3<2;a3++) { h[a2][a3][0]=0.f; h[a2][a3][1]=0.f; }
  __syncthreads();

  for (int t = 0; t < T; ++t) {
    const __nv_bfloat16* Ar = Ab + (t & 1) * A_BUF16;
    __nv_bfloat16* Aw = Ab + ((t & 1) ^ 1) * A_BUF16;
    float2 xz[2][2], xr[2][2], xh[2][2];
    #pragma unroll
    for (int rh=0;rh<2;rh++) {
      long long base = ((long long)(b0 + rh*8 + g)*T + t)*N3 + 2*t4;
      #pragma unroll
      for (int nt=0;nt<2;nt++) {
        int c = (2*w+nt)*8;
        xz[rh][nt] = *(const float2*)(Xp + base + c);
        xr[rh][nt] = *(const float2*)(Xp + base + 128 + c);
        xh[rh][nt] = *(const float2*)(Xp + base + 256 + c);
      }
    }
    float acc[6][4];
    #pragma unroll
    for (int j=0;j<6;j++)
      #pragma unroll
      for (int q=0;q<4;q++) acc[j][q] = 0.f;
    #pragma unroll
    for (int k16=0;k16<8;++k16) {
      uint32_t a[4];
      const __nv_bfloat16* ap = Ar + g*A_STRIDE + k16*16 + 2*t4;
      a[0] = *(const uint32_t*)(ap);
      a[1] = *(const uint32_t*)(ap + 8*A_STRIDE);
      a[2] = *(const uint32_t*)(ap + 8);
      a[3] = *(const uint32_t*)(ap + 8*A_STRIDE + 8);
      uint4 bv0 = ((const uint4*)Bp)[(k16*24 +      w)*32 + lane];
      uint4 bv1 = ((const uint4*)Bp)[(k16*24 +  8 + w)*32 + lane];
      uint4 bv2 = ((const uint4*)Bp)[(k16*24 + 16 + w)*32 + lane];
      uint32_t bb[6][2];
      bb[0][0]=bv0.x; bb[0][1]=bv0.y; bb[1][0]=bv0.z; bb[1][1]=bv0.w;
      bb[2][0]=bv1.x; bb[2][1]=bv1.y; bb[3][0]=bv1.z; bb[3][1]=bv1.w;
      bb[4][0]=bv2.x; bb[4][1]=bv2.y; bb[5][0]=bv2.z; bb[5][1]=bv2.w;
      #pragma unroll
      for (int j=0;j<6;j++)
        mma16(acc[j], a, bb[j]);
    }
    #pragma unroll
    for (int rh=0;rh<2;rh++) {
      int row = rh*8 + g;
      long long grow = ((long long)(b0+row)*T + t)*128;
      #pragma unroll
      for (int nt=0;nt<2;nt++) {
        int c = (2*w+nt)*8 + 2*t4;
        float hn0, hn1;
        {
          float z  = sigt(xz[rh][nt].x + acc[nt][rh*2]     + bz[nt].x);
          float r  = sigt(xr[rh][nt].x + acc[2+nt][rh*2]   + brr[nt].x);
          float hc = tanha(xh[rh][nt].x + r*(acc[4+nt][rh*2] + bh[nt].x));
          float ho = h[rh][nt][0];
          hn0 = z*ho + (1.f - z)*hc;
          h[rh][nt][0] = hn0;
        }
        {
          float z  = sigt(xz[rh][nt].y + acc[nt][rh*2+1]     + bz[nt].y);
          float r  = sigt(xr[rh][nt].y + acc[2+nt][rh*2+1]   + brr[nt].y);
          float hc = tanha(xh[rh][nt].y + r*(acc[4+nt][rh*2+1] + bh[nt].y));
          float ho = h[rh][nt][1];
          hn1 = z*ho + (1.f - z)*hc;
          h[rh][nt][1] = hn1;
        }
        float2 o = {hn0, hn1};
        *(float2*)(hs + grow + c) = o;
        *(uint32_t*)(Aw + row*A_STRIDE + c) = bf2(hn0, hn1);
      }
    }
    __syncthreads();
  }
}

// -------------------- AUGRU scan, bf16 tensor-core (16 rows/CTA) --------------------
__global__ __launch_bounds__(256, 2)
void augru_scan_mma(const float* __restrict__ X3, const uint32_t* __restrict__ Bpack) {
  extern __shared__ char smc[];
  uint32_t* Bp = (uint32_t*)smc;
  __nv_bfloat16* Ab = (__nv_bfloat16*)(smc + 98304);
  const int tid = threadIdx.x;
  const int w = tid >> 5, lane = tid & 31;
  const int g = lane >> 2, t4 = lane & 3;
  const int b0 = blockIdx.x * 16;
  #pragma unroll
  for (int it = 0; it < 24; ++it)
    ((float4*)Bp)[it*256 + tid] = ((const float4*)Bpack)[it*256 + tid];
  for (int i = tid; i < A_BUF16; i += 256) ((uint32_t*)Ab)[i] = 0u;
  float h[2][2][2];
  #pragma unroll
  for (int a2=0;a2<2;a2++)
    #pragma unroll
    for (int a3=0;a3<2;a3++) { h[a2][a3][0]=0.f; h[a2][a3][1]=0.f; }
  __syncthreads();

  for (int t = 0; t < T; ++t) {
    const __nv_bfloat16* Ar = Ab + (t & 1) * A_BUF16;
    __nv_bfloat16* Aw = Ab + ((t & 1) ^ 1) * A_BUF16;
    float2 xu[2][2], xr[2][2], xc[2][2];
    float at[2];
    #pragma unroll
    for (int rh=0;rh<2;rh++) {
      long long rowg = (long long)(b0 + rh*8 + g)*T + t;
      at[rh] = g_ats[rowg];
      long long base = rowg*N3 + 2*t4;
      #pragma unroll
      for (int nt=0;nt<2;nt++) {
        int c = (2*w+nt)*8;
        xu[rh][nt] = *(const float2*)(X3 + base + c);
        xr[rh][nt] = *(const float2*)(X3 + base + 128 + c);
        xc[rh][nt] = *(const float2*)(X3 + base + 256 + c);
      }
    }
    float acc[6][4];
    #pragma unroll
    for (int j=0;j<6;j++)
      #pragma unroll
      for (int q=0;q<4;q++) acc[j][q] = 0.f;
    #pragma unroll
    for (int k16=0;k16<8;++k16) {
      uint32_t a[4];
      const __nv_bfloat16* ap = Ar + g*A_STRIDE + k16*16 + 2*t4;
      a[0] = *(const uint32_t*)(ap);
      a[1] = *(const uint32_t*)(ap + 8*A_STRIDE);
      a[2] = *(const uint32_t*)(ap + 8);
      a[3] = *(const uint32_t*)(ap + 8*A_STRIDE + 8);
      uint4 bv0 = ((const uint4*)Bp)[(k16*24 +      w)*32 + lane];
      uint4 bv1 = ((const uint4*)Bp)[(k16*24 +  8 + w)*32 + lane];
      uint4 bv2 = ((const uint4*)Bp)[(k16*24 + 16 + w)*32 + lane];
      uint32_t bb[6][2];
      bb[0][0]=bv0.x; bb[0][1]=bv0.y; bb[1][0]=bv0.z; bb[1][1]=bv0.w;
      bb[2][0]=bv1.x; bb[2][1]=bv1.y; bb[3][0]=bv1.z; bb[3][1]=bv1.w;
      bb[4][0]=bv2.x; bb[4][1]=bv2.y; bb[5][0]=bv2.z; bb[5][1]=bv2.w;
      #pragma unroll
      for (int j=0;j<6;j++)
        mma16(acc[j], a, bb[j]);
    }
    #pragma unroll
    for (int rh=0;rh<2;rh++) {
      int row = rh*8 + g;
      float atv = at[rh];
      #pragma unroll
      for (int nt=0;nt<2;nt++) {
        int c = (2*w+nt)*8 + 2*t4;
        float hn0, hn1;
        {
          float u  = sigt(xu[rh][nt].x + acc[nt][rh*2]);
          float r  = sigt(xr[rh][nt].x + acc[2+nt][rh*2]);
          float cc = tanha(xc[rh][nt].x + r*acc[4+nt][rh*2]);
          float uu = atv*u;
          float ho = h[rh][nt][0];
          hn0 = (1.f - uu)*ho + uu*cc;
          h[rh][nt][0] = hn0;
        }
        {
          float u  = sigt(xu[rh][nt].y + acc[nt][rh*2+1]);
          float r  = sigt(xr[rh][nt].y + acc[2+nt][rh*2+1]);
          float cc = tanha(xc[rh][nt].y + r*acc[4+nt][rh*2+1]);
          float uu = atv*u;
          float ho = h[rh][nt][1];
          hn1 = (1.f - uu)*ho + uu*cc;
          h[rh][nt][1] = hn1;
        }
        *(uint32_t*)(Aw + row*A_STRIDE + c) = bf2(hn0, hn1);
      }
    }
    __syncthreads();
  }
  #pragma unroll
  for (int rh=0;rh<2;rh++) {
    int row = rh*8 + g;
    #pragma unroll
    for (int nt=0;nt<2;nt++) {
      int c = (2*w+nt)*8 + 2*t4;
      float2 o = {h[rh][nt][0], h[rh][nt][1]};
      *(float2*)(g_hfin + (long long)(b0+row)*128 + c) = o;
    }
  }
}

// ------------- fused attention: hs,news -> a1 -> a2 -> ats -------------
__global__ __launch_bounds__(256, 1)
void att_fused(const float* __restrict__ hs, const float* __restrict__ inputs,
               const float* __restrict__ Wcatp, const float* __restrict__ W2p,
               const float* __restrict__ b2, const float* __restrict__ W3,
               const float* __restrict__ b3, const float* __restrict__ nterm) {
  extern __shared__ float sm[];
  float* As  = sm;                 // 64*260 = 16640
  float* Bp  = sm + 16640;         // 16384 (reused as a1s, stride 132)
  float* W2s = Bp + 16384;         // 8192 (packed W2 fragments)
  float* a2s = W2s + 8192;         // 64*68 = 4352
  float* W3s = a2s + 4352;         // 64
  const int tid = threadIdx.x;     // 256
  const int lane = tid & 31, wid = tid >> 5;
  const int wm = wid & 1, wn = wid >> 1;
  const int wm3 = wid & 3, wn3 = wid >> 2;
  const int g = lane >> 2, t4 = lane & 3;
  const float b3v = b3[0];

  {
    const float4* src = (const float4*)W2p;
    float4* dst = (float4*)W2s;
    #pragma unroll
    for (int it = 0; it < 8; ++it) dst[it*256 + tid] = src[it*256 + tid];
    if (tid < 64) W3s[tid] = W3[tid];
  }
  const float4* Wc4 = (const float4*)Wcatp;
  float4* Bp4 = (float4*)Bp;

  for (long long blk = blockIdx.x; blk < BT/64; blk += gridDim.x) {
    const long long m0 = blk * 64;
    __syncthreads();
    #pragma unroll
    for (int it = 0; it < 16; ++it) {
      int idx = it*256 + tid;
      int r = idx >> 6, q = idx & 63;
      long long row = m0 + r;
      int b = (int)(row / T);
      if (q < 32) {
        float4 h = *(const float4*)(hs + row*128 + 4*q);
        float* dst = As + r*260 + 4*q;
        dst[0]=tf32r(h.x); dst[1]=tf32r(h.y); dst[2]=tf32r(h.z); dst[3]=tf32r(h.w);
      } else {
        int qq = q - 32;
        float4 h  = *(const float4*)(hs + row*128 + 4*qq);
        float4 nw = *(const float4*)(inputs + ((long long)b*(T+1) + T)*128 + 4*qq);
        float* dst = As + r*260 + 128 + 4*qq;
        dst[0]=tf32r(h.x*nw.x); dst[1]=tf32r(h.y*nw.y);
        dst[2]=tf32r(h.z*nw.z); dst[3]=tf32r(h.w*nw.w);
      }
    }
    float acc[2][4][4];
    #pragma unroll
    for (int mt=0;mt<2;mt++)
      #pragma unroll
      for (int nt=0;nt<4;nt++)
        #pragma unroll
        for (int q=0;q<4;q++) acc[mt][nt][q] = 0.f;
    for (int kc = 0; kc < 2; ++kc) {
      __syncthreads();
      #pragma unroll
      for (int it = 0; it < 16; ++it) {
        int f = it*256 + tid;
        int k8 = f >> 8, rem = f & 255;
        Bp4[f] = Wc4[((long long)(kc*16 + k8)*8)*32 + rem];
      }
      __syncthreads();
      #pragma unroll
      for (int k8 = 0; k8 < 16; ++k8) {
        uint32_t a[2][4];
        #pragma unroll
        for (int mt=0;mt<2;mt++) {
          const float* ap = As + (wm*32 + mt*16 + g)*260 + kc*128 + k8*8 + t4;
          a[mt][0] = __float_as_uint(ap[0]);
          a[mt][1] = __float_as_uint(ap[8*260]);
          a[mt][2] = __float_as_uint(ap[4]);
          a[mt][3] = __float_as_uint(ap[8*260+4]);
        }
        float4 b40 = Bp4[(k8*8 + wn*2    )*32 + lane];
        float4 b41 = Bp4[(k8*8 + wn*2 + 1)*32 + lane];
        uint32_t bb[4][2];
        bb[0][0]=__float_as_uint(b40.x); bb[0][1]=__float_as_uint(b40.y);
        bb[1][0]=__float_as_uint(b40.z); bb[1][1]=__float_as_uint(b40.w);
        bb[2][0]=__float_as_uint(b41.x); bb[2][1]=__float_as_uint(b41.y);
        bb[3][0]=__float_as_uint(b41.z); bb[3][1]=__float_as_uint(b41.w);
        #pragma unroll
        for (int mt=0;mt<2;mt++)
          #pragma unroll
          for (int nt=0;nt<4;nt++)
            mma8(acc[mt][nt], a[mt], bb[nt]);
      }
    }
    __syncthreads();
    float* a1s = Bp;
    #pragma unroll
    for (int mt=0;mt<2;mt++) {
      int row0 = wm*32 + mt*16 + g;
      #pragma unroll
      for (int nt=0;nt<4;nt++) {
        int col = wn*32 + nt*8 + 2*t4;
        #pragma unroll
        for (int h=0; h<2; ++h) {
          int row = row0 + 8*h;
          long long rowg = m0 + row;
          const float* np = nterm + (long long)(rowg / T)*128;
          a1s[row*132 + col]     = tf32r(fmaxf(acc[mt][nt][2*h+0] + np[col],   0.f));
          a1s[row*132 + col + 1] = tf32r(fmaxf(acc[mt][nt][2*h+1] + np[col+1], 0.f));
        }
      }
    }
    __syncthreads();
    {
      float acc2[4][4];
      #pragma unroll
      for (int nt=0;nt<4;nt++)
        #pragma unroll
        for (int q=0;q<4;q++) acc2[nt][q] = 0.f;
      const float4* W2p4 = (const float4*)W2s;
      #pragma unroll
      for (int k8 = 0; k8 < 16; ++k8) {
        uint32_t a[4];
        const float* ap = a1s + (wm3*16 + g)*132 + k8*8 + t4;
        a[0] = __float_as_uint(ap[0]);
        a[1] = __float_as_uint(ap[8*132]);
        a[2] = __float_as_uint(ap[4]);
        a[3] = __float_as_uint(ap[8*132+4]);
        float4 b40 = W2p4[(k8*4 + wn3*2    )*32 + lane];
        float4 b41 = W2p4[(k8*4 + wn3*2 + 1)*32 + lane];
        uint32_t bb[4][2];
        bb[0][0]=__float_as_uint(b40.x); bb[0][1]=__float_as_uint(b40.y);
        bb[1][0]=__float_as_uint(b40.z); bb[1][1]=__float_as_uint(b40.w);
        bb[2][0]=__float_as_uint(b41.x); bb[2][1]=__float_as_uint(b41.y);
        bb[3][0]=__float_as_uint(b41.z); bb[3][1]=__float_as_uint(b41.w);
        #pragma unroll
        for (int nt=0;nt<4;nt++)
          mma8(acc2[nt], a, bb[nt]);
      }
      #pragma unroll
      for (int nt=0;nt<4;nt++) {
        int col = wn3*32 + nt*8 + 2*t4;
        float bc0 = b2[col], bc1 = b2[col+1];
        #pragma unroll
        for (int h=0; h<2; ++h) {
          int row = wm3*16 + g + 8*h;
          a2s[row*68 + col]     = fmaxf(acc2[nt][2*h+0] + bc0, 0.f);
          a2s[row*68 + col + 1] = fmaxf(acc2[nt][2*h+1] + bc1, 0.f);
        }
      }
    }
    __syncthreads();
    if (tid < 64) {
      float accv = b3v;
      #pragma unroll 8
      for (int cc=0; cc<64; ++cc) accv = fmaf(a2s[tid*68 + cc], W3s[cc], accv);
      g_ats[m0 + tid] = sigf(accv);
    }
  }
}

// ------------------------------ head ------------------------------
__global__ void head_kernel(const float* __restrict__ inputs,
                            const float* __restrict__ gamma, const float* __restrict__ beta,
                            const float* __restrict__ mean,  const float* __restrict__ var,
                            const float* __restrict__ W1, const float* __restrict__ bb1,
                            const float* __restrict__ W2, const float* __restrict__ bb2,
                            const float* __restrict__ fW, const float* __restrict__ fb,
                            float* __restrict__ out) {
  extern __shared__ float sm[];
  float* xs  = sm;          // 32*256
  float* y1s = xs + 8192;   // 32*256
  float* y2s = y1s + 8192;  // 32*128
  const int tid = threadIdx.x;   // 256
  const int b0 = blockIdx.x * 32;
  for (int r = 0; r < 32; ++r) {
    int k = tid;
    int bb = b0 + r;
    float v = (k < 128) ? g_hfin[bb*128 + k]
                        : inputs[((long long)bb*(T+1) + T)*128 + (k - 128)];
    float nv = (v - mean[k]) * rsqrtf(var[k] + BN_EPS) * gamma[k] + beta[k];
    xs[r*256 + k] = nv;
  }
  __syncthreads();
  {
    float acc[32];
    #pragma unroll
    for (int r=0;r<32;r++) acc[r] = bb1[tid];
    for (int k=0;k<256;++k) {
      float w = W1[k*256 + tid];
      #pragma unroll
      for (int r=0;r<32;r++) acc[r] = fmaf(xs[r*256+k], w, acc[r]);
    }
    #pragma unroll
    for (int r=0;r<32;r++) {
      float v = acc[r];
      y1s[r*256 + tid] = v >= 0.f ? v : LEAKY*v;
    }
  }
  __syncthreads();
  if (tid < 128) {
    float acc[32];
    #pragma unroll
    for (int r=0;r<32;r++) acc[r] = bb2[tid];
    for (int k=0;k<256;++k) {
      float w = W2[k*128 + tid];
      #pragma unroll
      for (int r=0;r<32;r++) acc[r] = fmaf(y1s[r*256+k], w, acc[r]);
    }
    #pragma unroll
    for (int r=0;r<32;r++) {
      float v = acc[r];
      y2s[r*128 + tid] = v >= 0.f ? v : LEAKY*v;
    }
  }
  __syncthreads();
  if (tid < 32) {
    float acc = fb[0];
    for (int k=0;k<128;++k) acc = fmaf(y2s[tid*128+k], fW[k], acc);
    out[b0 + tid] = sigf(acc);
  }
}

// ------------------------------ launch ------------------------------
extern "C" void kernel_launch(void* const* d_in, const int* in_sizes, int n_in,
                              void* d_out, int out_size) {
  (void)in_sizes; (void)n_in; (void)out_size;
  const float* inputs  = (const float*)d_in[0];
  const float* gru_W   = (const float*)d_in[1];
  const float* gru_U   = (const float*)d_in[2];
  const float* gru_b   = (const float*)d_in[3];
  const float* att_W1  = (const float*)d_in[4];
  const float* att_b1  = (const float*)d_in[5];
  const float* att_W2  = (const float*)d_in[6];
  const float* att_b2  = (const float*)d_in[7];
  const float* att_W3  = (const float*)d_in[8];
  const float* att_b3  = (const float*)d_in[9];
  const float* au_Wu   = (const float*)d_in[10];
  const float* au_bu   = (const float*)d_in[11];
  const float* au_Uu   = (const float*)d_in[12];
  const float* au_Wr   = (const float*)d_in[13];
  const float* au_br   = (const float*)d_in[14];
  const float* au_Ur   = (const float*)d_in[15];
  const float* au_Wc   = (const float*)d_in[16];
  const float* au_bc   = (const float*)d_in[17];
  const float* au_Uc   = (const float*)d_in[18];
  const float* bn_gamma= (const float*)d_in[19];
  const float* bn_beta = (const float*)d_in[20];
  const float* bn_mean = (const float*)d_in[21];
  const float* bn_var  = (const float*)d_in[22];
  const float* d_W1    = (const float*)d_in[23];
  const float* d_b1    = (const float*)d_in[24];
  const float* d_W2    = (const float*)d_in[25];
  const float* d_b2    = (const float*)d_in[26];
  const float* f_W     = (const float*)d_in[27];
  const float* f_b     = (const float*)d_in[28];
  float* out = (float*)d_out;

  const size_t sm_gemm = (64*132 + 16384)*sizeof(float);      // 99328
  const size_t sm_scan = 98304 + 2*A_BUF16*sizeof(__nv_bfloat16); // 98304+8704 = 107008
  const size_t sm_attf = (16640 + 16384 + 8192 + 4352 + 64)*sizeof(float); // 182528
  const size_t sm_head = (8192*2 + 4096)*sizeof(float);
  cudaFuncSetAttribute(gemm_v2,        cudaFuncAttributeMaxDynamicSharedMemorySize, (int)sm_gemm);
  cudaFuncSetAttribute(gru_scan_mma,   cudaFuncAttributeMaxDynamicSharedMemorySize, (int)sm_scan);
  cudaFuncSetAttribute(augru_scan_mma, cudaFuncAttributeMaxDynamicSharedMemorySize, (int)sm_scan);
  cudaFuncSetAttribute(att_fused,      cudaFuncAttributeMaxDynamicSharedMemorySize, (int)sm_attf);
  cudaFuncSetAttribute(head_kernel,    cudaFuncAttributeMaxDynamicSharedMemorySize, (int)sm_head);

  float *p_Xp, *p_hs, *p_X3, *p_newsterm, *p_bau;
  float *p_WpgW, *p_Wpau, *p_Wp1bc, *p_Wpcat, *p_Wpatt2;
  uint32_t *p_Ubg, *p_Uba;
  cudaGetSymbolAddress((void**)&p_Xp,       g_Xp);
  cudaGetSymbolAddress((void**)&p_hs,       g_hs);
  cudaGetSymbolAddress((void**)&p_X3,       g_X3);
  cudaGetSymbolAddress((void**)&p_newsterm, g_newsterm);
  cudaGetSymbolAddress((void**)&p_bau,      g_bau);
  cudaGetSymbolAddress((void**)&p_Ubg,      g_Ubf_gru);
  cudaGetSymbolAddress((void**)&p_Uba,      g_Ubf_au);
  cudaGetSymbolAddress((void**)&p_WpgW,     g_Wp_gruW);
  cudaGetSymbolAddress((void**)&p_Wpau,     g_Wp_au);
  cudaGetSymbolAddress((void**)&p_Wp1bc,    g_Wp_1bc);
  cudaGetSymbolAddress((void**)&p_Wpcat,    g_Wp_cat);
  cudaGetSymbolAddress((void**)&p_Wpatt2,   g_Wp_att2);

  cudaStream_t s2;
  cudaStreamCreateWithFlags(&s2, cudaStreamNonBlocking);
  cudaEvent_t evPack, evNews, evFork, evJoin;
  cudaEventCreateWithFlags(&evPack, cudaEventDisableTiming);
  cudaEventCreateWithFlags(&evNews, cudaEventDisableTiming);
  cudaEventCreateWithFlags(&evFork, cudaEventDisableTiming);
  cudaEventCreateWithFlags(&evJoin, cudaEventDisableTiming);

  // 1) fold weights, then all fragment packs
  prep_kernel<<<192, 256>>>(au_Wu, au_bu, au_Wr, au_br, au_Wc, au_bc,
                            au_Uu, au_Ur, au_Uc, att_W1);
  pack_all<<<800, 256>>>(gru_U, gru_W, att_W2);
  cudaEventRecord(evPack, 0);
  cudaStreamWaitEvent(s2, evPack, 0);
  // 2) newsterm = news @ (W1B+W1C) + b1  (side stream, overlaps Xp gemm + scan)
  gemm_v2<<<dim3(B/64, 1), 256, sm_gemm, s2>>>(inputs + (long long)T*128, 1, (long long)(T+1)*128, 128,
                                               p_Wp1bc, 8, att_b1, p_newsterm, 128);
  cudaEventRecord(evNews, s2);
  // 3) Xp = hist @ gru_W + gru_b[0]
  gemm_v2<<<dim3(BT/64, 3), 256, sm_gemm>>>(inputs, T, (long long)(T+1)*128, 128,
                                            p_WpgW, 24, gru_b, p_Xp, 384);
  // 4) GRU recurrence -> hs (bf16 tensor-core scan, 2 CTAs/SM)
  gru_scan_mma<<<B/16, 256, sm_scan>>>(p_Xp, p_Ubg, gru_b + 384, p_hs);
  // fork: X3 gemm on s2, attention on main stream
  cudaEventRecord(evFork, 0);
  cudaStreamWaitEvent(s2, evFork, 0);
  // 5) X3 = hs @ [Wu|Wr|Wc] + [bu|br|bc]   (side stream)
  gemm_v2<<<dim3(BT/64, 3), 256, sm_gemm, s2>>>(p_hs, 1<<30, 0LL, 128,
                                                p_Wpau, 24, p_bau, p_X3, 384);
  cudaEventRecord(evJoin, s2);
  // 6) fused attention -> g_ats  (main stream; needs newsterm)
  cudaStreamWaitEvent(0, evNews, 0);
  att_fused<<<148, 256, sm_attf>>>(p_hs, inputs, p_Wpcat, p_Wpatt2,
                                   att_b2, att_W3, att_b3, p_newsterm);
  cudaStreamWaitEvent(0, evJoin, 0);
  // 7) AUGRU recurrence -> hfin (bf16 tensor-core scan, 2 CTAs/SM)
  augru_scan_mma<<<B/16, 256, sm_scan>>>(p_X3, p_Uba);
  // 8) BN + dense head -> out
  head_kernel<<<B/32, 256, sm_head>>>(inputs, bn_gamma, bn_beta, bn_mean, bn_var,
                                      d_W1, d_b1, d_W2, d_b2, f_W, f_b, out);
}

// round 9
// speedup vs baseline: 1.0357x; 1.0357x over previous
#include <cuda_runtime.h>
#include <cuda_bf16.h>
#include <math.h>
#include <stdint.h>

#define B  4096
#define T  50
#define U  128
#define N3 384
#define BT (B*T)
#define BN_EPS 1e-3f
#define LEAKY  3e-4f

// ------------ scratch (device globals; no allocation allowed) ------------
__device__ float g_Xp[BT*N3];        // GRU input projection (used as bf16, half occupancy)
__device__ float g_hs[BT*U];         // GRU hidden states
__device__ float g_X3[BT*N3];        // AUGRU input projections (bf16)
__device__ float g_ats[BT];          // attention scores
__device__ float g_hfin[B*U];        // AUGRU final state
__device__ float g_newsterm[B*U];    // news@(W1B+W1C)+b1
__device__ float g_Wau[U*N3];        // packed input  [Wu|Wr|Wc]
__device__ float g_Uau[U*N3];        // packed recur  [Uu|Ur|Uc]
__device__ float g_bau[N3];          // packed [bu|br|bc]
__device__ float g_Wcat[2*U*U];      // [W1A-W1B ; W1D]  (256 x 128)
__device__ float g_W1bc[U*U];        // W1B + W1C
__device__ uint32_t g_Ubf_gru[24576];// bf16 fragment-ordered gru_U   (96 KB)
__device__ uint32_t g_Ubf_au[24576]; // bf16 fragment-ordered [Uu|Ur|Uc]
__device__ float g_Wp_gruW[128*N3];  // tf32 fragment-ordered gru_W
__device__ float g_Wp_au[128*N3];    // tf32 fragment-ordered [Wu|Wr|Wc]
__device__ float g_Wp_1bc[128*128];  // tf32 fragment-ordered W1B+W1C
__device__ float g_Wp_cat[256*128];  // tf32 fragment-ordered Wcat (K=256)
__device__ float g_Wp_att2[128*64];  // tf32 fragment-ordered att_W2

__device__ __forceinline__ float sigf(float x){ return 1.f/(1.f+expf(-x)); }
__device__ __forceinline__ float tanha(float x){
  float y; asm("tanh.approx.f32 %0, %1;" : "=f"(y) : "f"(x)); return y;
}
__device__ __forceinline__ float sigt(float x){ return fmaf(tanha(0.5f*x), 0.5f, 0.5f); }
__device__ __forceinline__ float tf32r(float f){
  uint32_t r; asm("cvt.rna.tf32.f32 %0, %1;" : "=r"(r) : "f"(f));
  return __uint_as_float(r);
}
__device__ __forceinline__ uint32_t bf2(float lo, float hi){
  __nv_bfloat162 v;
  v.x = __float2bfloat16(lo); v.y = __float2bfloat16(hi);
  return *(uint32_t*)&v;
}
__device__ __forceinline__ float2 bf2f(uint32_t u){
  __nv_bfloat162 v = *(__nv_bfloat162*)&u;
  return __bfloat1622float2(v);
}
__device__ __forceinline__ void mma8(float* d, const uint32_t* a, const uint32_t* b){
  asm volatile("mma.sync.aligned.m16n8k8.row.col.f32.tf32.tf32.f32 "
               "{%0,%1,%2,%3}, {%4,%5,%6,%7}, {%8,%9}, {%0,%1,%2,%3};"
               : "+f"(d[0]), "+f"(d[1]), "+f"(d[2]), "+f"(d[3])
               : "r"(a[0]), "r"(a[1]), "r"(a[2]), "r"(a[3]), "r"(b[0]), "r"(b[1]));
}
__device__ __forceinline__ void mma16(float* d, const uint32_t* a, const uint32_t* b){
  asm volatile("mma.sync.aligned.m16n8k16.row.col.f32.bf16.bf16.f32 "
               "{%0,%1,%2,%3}, {%4,%5,%6,%7}, {%8,%9}, {%0,%1,%2,%3};"
               : "+f"(d[0]), "+f"(d[1]), "+f"(d[2]), "+f"(d[3])
               : "r"(a[0]), "r"(a[1]), "r"(a[2]), "r"(a[3]), "r"(b[0]), "r"(b[1]));
}

// ------------------------------- prep -------------------------------
__global__ void prep_kernel(const float* __restrict__ Wu, const float* __restrict__ bu,
                            const float* __restrict__ Wr, const float* __restrict__ br,
                            const float* __restrict__ Wc, const float* __restrict__ bc,
                            const float* __restrict__ Uu, const float* __restrict__ Ur,
                            const float* __restrict__ Uc,
                            const float* __restrict__ attW1) {
  int id = blockIdx.x*blockDim.x + threadIdx.x;
  if (id < U*N3) {
    int k = id / N3, c = id % N3;
    float w, u;
    if (c < 128)      { w = Wu[k*128 + c];       u = Uu[k*128 + c]; }
    else if (c < 256) { w = Wr[k*128 + (c-128)]; u = Ur[k*128 + (c-128)]; }
    else              { w = Wc[k*128 + (c-256)]; u = Uc[k*128 + (c-256)]; }
    g_Wau[id] = w;
    g_Uau[id] = u;
  }
  if (id < N3)
    g_bau[id] = (id < 128) ? bu[id] : (id < 256 ? br[id-128] : bc[id-256]);
  if (id < 2*U*U) {
    int k = id / 128, c = id % 128;
    float v;
    if (k < 128) v = attW1[k*128 + c] - attW1[U*U + k*128 + c];     // W1A - W1B
    else         v = attW1[3*U*U + (k-128)*128 + c];                // W1D
    g_Wcat[id] = v;
  }
  if (id < U*U)
    g_W1bc[id] = attW1[U*U + id] + attW1[2*U*U + id];
}

// --------------- pack weights fragment-ordered, one launch ---------------
__device__ __forceinline__ void pack_one(const float* __restrict__ Um, float* __restrict__ P,
                                         int N, int idx) {
  int q = idx & 3, lane = (idx >> 2) & 31;
  int Ntp = N >> 4;
  int tp = (idx >> 7) % Ntp, k8 = (idx >> 7) / Ntp;
  int tile = 2*tp + (q >> 1), r = q & 1;
  int k = k8*8 + (lane & 3) + 4*r;
  int n = tile*8 + (lane >> 2);
  P[idx] = tf32r(Um[k*N + n]);
}
__device__ __forceinline__ void pack_bf16_one(const float* __restrict__ Um,
                                              uint32_t* __restrict__ P, int idx) {
  int q = idx & 3, lane = (idx >> 2) & 31;
  int tp = (idx >> 7) % 24, k16 = (idx >> 7) / 24;
  int tile = 2*tp + (q >> 1), r = q & 1;
  int k = k16*16 + 2*(lane & 3) + 8*r;
  int n = tile*8 + (lane >> 2);
  P[idx] = bf2(Um[k*N3 + n], Um[(k+1)*N3 + n]);
}

__global__ void pack_all(const float* __restrict__ gruU, const float* __restrict__ gruW,
                         const float* __restrict__ attW2) {
  int idx = blockIdx.x*256 + threadIdx.x;   // 204800 total
  if (idx < 24576)        pack_bf16_one(gruU,  g_Ubf_gru, idx);
  else if (idx < 49152)   pack_bf16_one(g_Uau, g_Ubf_au,  idx - 24576);
  else if (idx < 98304)   pack_one(gruW,    g_Wp_gruW,   384, idx - 49152);
  else if (idx < 147456)  pack_one(g_Wau,   g_Wp_au,     384, idx - 98304);
  else if (idx < 163840)  pack_one(g_W1bc,  g_Wp_1bc,    128, idx - 147456);
  else if (idx < 196608)  pack_one(g_Wcat,  g_Wp_cat,    128, idx - 163840);
  else if (idx < 204800)  pack_one(attW2,   g_Wp_att2,   64,  idx - 196608);
}

// --------------------- tf32 GEMM, packed-B, K=128 ---------------------
// obf=0: C fp32 (ldc floats).  obf=1: C bf16 (ldc bf16 elements).
__global__ void gemm_v2(const float* __restrict__ A, int P, long long GS, int RS,
                        const float* __restrict__ Bpk, int Ntp,
                        const float* __restrict__ bias, void* __restrict__ C, int ldc,
                        int obf) {
  extern __shared__ float sm[];
  float* As = sm;               // 64 x 132
  float* Bp = sm + 64*132;      // 16384 floats
  const int m0 = blockIdx.x * 64;
  const int c0 = blockIdx.y * 128;
  const int tp0 = blockIdx.y * 8;
  const int tid = threadIdx.x;          // 256
  const int kq = tid >> 5, cq = tid & 31;
  const int lane = tid & 31, wid = tid >> 5;
  const int wm = wid & 1, wn = wid >> 1;
  const int g = lane >> 2, t4 = lane & 3;

  #pragma unroll
  for (int it = 0; it < 8; ++it) {
    int r = kq + 8*it;
    int m = m0 + r;
    const float* ap = A + (long long)(m/P)*GS + (long long)(m%P)*RS;
    float4 v = *(const float4*)(ap + 4*cq);
    float* dst = As + r*132 + 4*cq;
    dst[0]=tf32r(v.x); dst[1]=tf32r(v.y); dst[2]=tf32r(v.z); dst[3]=tf32r(v.w);
  }
  {
    const float4* src = (const float4*)Bpk;
    float4* dst = (float4*)Bp;
    #pragma unroll
    for (int it = 0; it < 16; ++it) {
      int f = it*256 + tid;
      int k8 = f >> 8, rem = f & 255;
      dst[f] = src[((long long)k8*Ntp + tp0)*32 + rem];
    }
  }
  __syncthreads();

  float acc[2][4][4];
  #pragma unroll
  for (int mt=0;mt<2;mt++)
    #pragma unroll
    for (int nt=0;nt<4;nt++)
      #pragma unroll
      for (int q=0;q<4;q++) acc[mt][nt][q] = 0.f;

  const float4* bp4 = (const float4*)Bp;
  #pragma unroll
  for (int k8 = 0; k8 < 16; ++k8) {
    uint32_t a[2][4];
    #pragma unroll
    for (int mt=0;mt<2;mt++) {
      const float* ap = As + (wm*32 + mt*16 + g)*132 + k8*8 + t4;
      a[mt][0] = __float_as_uint(ap[0]);
      a[mt][1] = __float_as_uint(ap[8*132]);
      a[mt][2] = __float_as_uint(ap[4]);
      a[mt][3] = __float_as_uint(ap[8*132+4]);
    }
    float4 b40 = bp4[(k8*8 + wn*2    )*32 + lane];
    float4 b41 = bp4[(k8*8 + wn*2 + 1)*32 + lane];
    uint32_t bb[4][2];
    bb[0][0]=__float_as_uint(b40.x); bb[0][1]=__float_as_uint(b40.y);
    bb[1][0]=__float_as_uint(b40.z); bb[1][1]=__float_as_uint(b40.w);
    bb[2][0]=__float_as_uint(b41.x); bb[2][1]=__float_as_uint(b41.y);
    bb[3][0]=__float_as_uint(b41.z); bb[3][1]=__float_as_uint(b41.w);
    #pragma unroll
    for (int mt=0;mt<2;mt++)
      #pragma unroll
      for (int nt=0;nt<4;nt++)
        mma8(acc[mt][nt], a[mt], bb[nt]);
  }
  #pragma unroll
  for (int mt=0;mt<2;mt++) {
    int row0 = m0 + wm*32 + mt*16 + g;
    #pragma unroll
    for (int nt=0;nt<4;nt++) {
      int col = c0 + wn*32 + nt*8 + 2*t4;
      float bc0 = bias[col], bc1 = bias[col+1];
      #pragma unroll
      for (int h=0; h<2; ++h) {
        int row = row0 + 8*h;
        float v0 = acc[mt][nt][2*h+0] + bc0;
        float v1 = acc[mt][nt][2*h+1] + bc1;
        if (obf) {
          *(uint32_t*)((__nv_bfloat16*)C + (long long)row*ldc + col) = bf2(v0, v1);
        } else {
          float2 o = {v0, v1};
          *(float2*)((float*)C + (long long)row*ldc + col) = o;
        }
      }
    }
  }
}

// -------------------- GRU scan, bf16 tensor-core (32 rows/CTA) --------------------
#define A_STRIDE 136
#define A_BUF    (32*A_STRIDE)   // bf16 elements per buffer
__global__ __launch_bounds__(256, 1)
void gru_scan_mma(const __nv_bfloat16* __restrict__ Xp, const uint32_t* __restrict__ Bpack,
                  const float* __restrict__ brec, float* __restrict__ hs) {
  extern __shared__ char smc[];
  uint32_t* Bp = (uint32_t*)smc;                       // 24576 u32
  __nv_bfloat16* Ab = (__nv_bfloat16*)(smc + 98304);   // 2 * A_BUF
  const int tid = threadIdx.x;    // 256
  const int w = tid >> 5, lane = tid & 31;
  const int g = lane >> 2, t4 = lane & 3;
  const int b0 = blockIdx.x * 32;
  #pragma unroll
  for (int it = 0; it < 24; ++it)
    ((float4*)Bp)[it*256 + tid] = ((const float4*)Bpack)[it*256 + tid];
  for (int i = tid; i < A_BUF; i += 256) ((uint32_t*)Ab)[i] = 0u;
  float2 bz[2], brr[2], bh[2];
  #pragma unroll
  for (int nt=0; nt<2; ++nt) {
    int c = (2*w+nt)*8 + 2*t4;
    bz[nt]  = *(const float2*)(brec + c);
    brr[nt] = *(const float2*)(brec + 128 + c);
    bh[nt]  = *(const float2*)(brec + 256 + c);
  }
  float h[2][2][2][2];
  #pragma unroll
  for (int a1=0;a1<2;a1++)
    #pragma unroll
    for (int a2=0;a2<2;a2++)
      #pragma unroll
      for (int a3=0;a3<2;a3++) { h[a1][a2][a3][0]=0.f; h[a1][a2][a3][1]=0.f; }
  __syncthreads();

  for (int t = 0; t < T; ++t) {
    const __nv_bfloat16* Ar = Ab + (t & 1) * A_BUF;
    __nv_bfloat16* Aw = Ab + ((t & 1) ^ 1) * A_BUF;
    float2 xz[2][2][2], xr[2][2][2], xh[2][2][2];
    #pragma unroll
    for (int mt=0;mt<2;mt++)
      #pragma unroll
      for (int rh=0;rh<2;rh++) {
        long long base = ((long long)(b0 + mt*16 + rh*8 + g)*T + t)*N3 + 2*t4;
        #pragma unroll
        for (int nt=0;nt<2;nt++) {
          int c = (2*w+nt)*8;
          xz[mt][rh][nt] = bf2f(*(const uint32_t*)(Xp + base + c));
          xr[mt][rh][nt] = bf2f(*(const uint32_t*)(Xp + base + 128 + c));
          xh[mt][rh][nt] = bf2f(*(const uint32_t*)(Xp + base + 256 + c));
        }
      }
    float acc[2][6][4];
    #pragma unroll
    for (int mt=0;mt<2;mt++)
      #pragma unroll
      for (int j=0;j<6;j++)
        #pragma unroll
        for (int q=0;q<4;q++) acc[mt][j][q] = 0.f;
    #pragma unroll
    for (int k16=0;k16<8;++k16) {
      uint32_t a[2][4];
      #pragma unroll
      for (int mt=0;mt<2;mt++) {
        const __nv_bfloat16* ap = Ar + (mt*16 + g)*A_STRIDE + k16*16 + 2*t4;
        a[mt][0] = *(const uint32_t*)(ap);
        a[mt][1] = *(const uint32_t*)(ap + 8*A_STRIDE);
        a[mt][2] = *(const uint32_t*)(ap + 8);
        a[mt][3] = *(const uint32_t*)(ap + 8*A_STRIDE + 8);
      }
      uint4 bv0 = ((const uint4*)Bp)[(k16*24 +      w)*32 + lane];
      uint4 bv1 = ((const uint4*)Bp)[(k16*24 +  8 + w)*32 + lane];
      uint4 bv2 = ((const uint4*)Bp)[(k16*24 + 16 + w)*32 + lane];
      uint32_t bb[6][2];
      bb[0][0]=bv0.x; bb[0][1]=bv0.y; bb[1][0]=bv0.z; bb[1][1]=bv0.w;
      bb[2][0]=bv1.x; bb[2][1]=bv1.y; bb[3][0]=bv1.z; bb[3][1]=bv1.w;
      bb[4][0]=bv2.x; bb[4][1]=bv2.y; bb[5][0]=bv2.z; bb[5][1]=bv2.w;
      #pragma unroll
      for (int mt=0;mt<2;mt++)
        #pragma unroll
        for (int j=0;j<6;j++)
          mma16(acc[mt][j], a[mt], bb[j]);
    }
    #pragma unroll
    for (int mt=0;mt<2;mt++)
      #pragma unroll
      for (int rh=0;rh<2;rh++) {
        int row = mt*16 + rh*8 + g;
        long long grow = ((long long)(b0+row)*T + t)*128;
        #pragma unroll
        for (int nt=0;nt<2;nt++) {
          int c = (2*w+nt)*8 + 2*t4;
          float hn0, hn1;
          {
            float z  = sigt(xz[mt][rh][nt].x + acc[mt][nt][rh*2]     + bz[nt].x);
            float r  = sigt(xr[mt][rh][nt].x + acc[mt][2+nt][rh*2]   + brr[nt].x);
            float hc = tanha(xh[mt][rh][nt].x + r*(acc[mt][4+nt][rh*2] + bh[nt].x));
            float ho = h[mt][rh][nt][0];
            hn0 = z*ho + (1.f - z)*hc;
            h[mt][rh][nt][0] = hn0;
          }
          {
            float z  = sigt(xz[mt][rh][nt].y + acc[mt][nt][rh*2+1]     + bz[nt].y);
            float r  = sigt(xr[mt][rh][nt].y + acc[mt][2+nt][rh*2+1]   + brr[nt].y);
            float hc = tanha(xh[mt][rh][nt].y + r*(acc[mt][4+nt][rh*2+1] + bh[nt].y));
            float ho = h[mt][rh][nt][1];
            hn1 = z*ho + (1.f - z)*hc;
            h[mt][rh][nt][1] = hn1;
          }
          float2 o = {hn0, hn1};
          *(float2*)(hs + grow + c) = o;
          *(uint32_t*)(Aw + row*A_STRIDE + c) = bf2(hn0, hn1);
        }
      }
    __syncthreads();
  }
}

// -------------------- AUGRU scan, bf16 tensor-core (32 rows/CTA) --------------------
__global__ __launch_bounds__(256, 1)
void augru_scan_mma(const __nv_bfloat16* __restrict__ X3, const uint32_t* __restrict__ Bpack) {
  extern __shared__ char smc[];
  uint32_t* Bp = (uint32_t*)smc;
  __nv_bfloat16* Ab = (__nv_bfloat16*)(smc + 98304);
  const int tid = threadIdx.x;
  const int w = tid >> 5, lane = tid & 31;
  const int g = lane >> 2, t4 = lane & 3;
  const int b0 = blockIdx.x * 32;
  #pragma unroll
  for (int it = 0; it < 24; ++it)
    ((float4*)Bp)[it*256 + tid] = ((const float4*)Bpack)[it*256 + tid];
  for (int i = tid; i < A_BUF; i += 256) ((uint32_t*)Ab)[i] = 0u;
  float h[2][2][2][2];
  #pragma unroll
  for (int a1=0;a1<2;a1++)
    #pragma unroll
    for (int a2=0;a2<2;a2++)
      #pragma unroll
      for (int a3=0;a3<2;a3++) { h[a1][a2][a3][0]=0.f; h[a1][a2][a3][1]=0.f; }
  __syncthreads();

  for (int t = 0; t < T; ++t) {
    const __nv_bfloat16* Ar = Ab + (t & 1) * A_BUF;
    __nv_bfloat16* Aw = Ab + ((t & 1) ^ 1) * A_BUF;
    float2 xu[2][2][2], xr[2][2][2], xc[2][2][2];
    float at[2][2];
    #pragma unroll
    for (int mt=0;mt<2;mt++)
      #pragma unroll
      for (int rh=0;rh<2;rh++) {
        long long rowg = (long long)(b0 + mt*16 + rh*8 + g)*T + t;
        at[mt][rh] = g_ats[rowg];
        long long base = rowg*N3 + 2*t4;
        #pragma unroll
        for (int nt=0;nt<2;nt++) {
          int c = (2*w+nt)*8;
          xu[mt][rh][nt] = bf2f(*(const uint32_t*)(X3 + base + c));
          xr[mt][rh][nt] = bf2f(*(const uint32_t*)(X3 + base + 128 + c));
          xc[mt][rh][nt] = bf2f(*(const uint32_t*)(X3 + base + 256 + c));
        }
      }
    float acc[2][6][4];
    #pragma unroll
    for (int mt=0;mt<2;mt++)
      #pragma unroll
      for (int j=0;j<6;j++)
        #pragma unroll
        for (int q=0;q<4;q++) acc[mt][j][q] = 0.f;
    #pragma unroll
    for (int k16=0;k16<8;++k16) {
      uint32_t a[2][4];
      #pragma unroll
      for (int mt=0;mt<2;mt++) {
        const __nv_bfloat16* ap = Ar + (mt*16 + g)*A_STRIDE + k16*16 + 2*t4;
        a[mt][0] = *(const uint32_t*)(ap);
        a[mt][1] = *(const uint32_t*)(ap + 8*A_STRIDE);
        a[mt][2] = *(const uint32_t*)(ap + 8);
        a[mt][3] = *(const uint32_t*)(ap + 8*A_STRIDE + 8);
      }
      uint4 bv0 = ((const uint4*)Bp)[(k16*24 +      w)*32 + lane];
      uint4 bv1 = ((const uint4*)Bp)[(k16*24 +  8 + w)*32 + lane];
      uint4 bv2 = ((const uint4*)Bp)[(k16*24 + 16 + w)*32 + lane];
      uint32_t bb[6][2];
      bb[0][0]=bv0.x; bb[0][1]=bv0.y; bb[1][0]=bv0.z; bb[1][1]=bv0.w;
      bb[2][0]=bv1.x; bb[2][1]=bv1.y; bb[3][0]=bv1.z; bb[3][1]=bv1.w;
      bb[4][0]=bv2.x; bb[4][1]=bv2.y; bb[5][0]=bv2.z; bb[5][1]=bv2.w;
      #pragma unroll
      for (int mt=0;mt<2;mt++)
        #pragma unroll
        for (int j=0;j<6;j++)
          mma16(acc[mt][j], a[mt], bb[j]);
    }
    #pragma unroll
    for (int mt=0;mt<2;mt++)
      #pragma unroll
      for (int rh=0;rh<2;rh++) {
        int row = mt*16 + rh*8 + g;
        float atv = at[mt][rh];
        #pragma unroll
        for (int nt=0;nt<2;nt++) {
          int c = (2*w+nt)*8 + 2*t4;
          float hn0, hn1;
          {
            float u  = sigt(xu[mt][rh][nt].x + acc[mt][nt][rh*2]);
            float r  = sigt(xr[mt][rh][nt].x + acc[mt][2+nt][rh*2]);
            float cc = tanha(xc[mt][rh][nt].x + r*acc[mt][4+nt][rh*2]);
            float uu = atv*u;
            float ho = h[mt][rh][nt][0];
            hn0 = (1.f - uu)*ho + uu*cc;
            h[mt][rh][nt][0] = hn0;
          }
          {
            float u  = sigt(xu[mt][rh][nt].y + acc[mt][nt][rh*2+1]);
            float r  = sigt(xr[mt][rh][nt].y + acc[mt][2+nt][rh*2+1]);
            float cc = tanha(xc[mt][rh][nt].y + r*acc[mt][4+nt][rh*2+1]);
            float uu = atv*u;
            float ho = h[mt][rh][nt][1];
            hn1 = (1.f - uu)*ho + uu*cc;
            h[mt][rh][nt][1] = hn1;
          }
          *(uint32_t*)(Aw + row*A_STRIDE + c) = bf2(hn0, hn1);
        }
      }
    __syncthreads();
  }
  #pragma unroll
  for (int mt=0;mt<2;mt++)
    #pragma unroll
    for (int rh=0;rh<2;rh++) {
      int row = mt*16 + rh*8 + g;
      #pragma unroll
      for (int nt=0;nt<2;nt++) {
        int c = (2*w+nt)*8 + 2*t4;
        float2 o = {h[mt][rh][nt][0], h[mt][rh][nt][1]};
        *(float2*)(g_hfin + (long long)(b0+row)*128 + c) = o;
      }
    }
}

// ------------- fused attention: hs,news -> a1 -> a2 -> ats -------------
__global__ __launch_bounds__(256, 1)
void att_fused(const float* __restrict__ hs, const float* __restrict__ inputs,
               const float* __restrict__ Wcatp, const float* __restrict__ W2p,
               const float* __restrict__ b2, const float* __restrict__ W3,
               const float* __restrict__ b3, const float* __restrict__ nterm) {
  extern __shared__ float sm[];
  float* As  = sm;                 // 64*260 = 16640
  float* Bp  = sm + 16640;         // 16384 (reused as a1s, stride 132)
  float* W2s = Bp + 16384;         // 8192 (packed W2 fragments)
  float* a2s = W2s + 8192;         // 64*68 = 4352
  float* W3s = a2s + 4352;         // 64
  const int tid = threadIdx.x;     // 256
  const int lane = tid & 31, wid = tid >> 5;
  const int wm = wid & 1, wn = wid >> 1;
  const int wm3 = wid & 3, wn3 = wid >> 2;
  const int g = lane >> 2, t4 = lane & 3;
  const float b3v = b3[0];

  {
    const float4* src = (const float4*)W2p;
    float4* dst = (float4*)W2s;
    #pragma unroll
    for (int it = 0; it < 8; ++it) dst[it*256 + tid] = src[it*256 + tid];
    if (tid < 64) W3s[tid] = W3[tid];
  }
  const float4* Wc4 = (const float4*)Wcatp;
  float4* Bp4 = (float4*)Bp;

  for (long long blk = blockIdx.x; blk < BT/64; blk += gridDim.x) {
    const long long m0 = blk * 64;
    __syncthreads();
    #pragma unroll
    for (int it = 0; it < 16; ++it) {
      int idx = it*256 + tid;
      int r = idx >> 6, q = idx & 63;
      long long row = m0 + r;
      int b = (int)(row / T);
      if (q < 32) {
        float4 h = *(const float4*)(hs + row*128 + 4*q);
        float* dst = As + r*260 + 4*q;
        dst[0]=tf32r(h.x); dst[1]=tf32r(h.y); dst[2]=tf32r(h.z); dst[3]=tf32r(h.w);
      } else {
        int qq = q - 32;
        float4 h  = *(const float4*)(hs + row*128 + 4*qq);
        float4 nw = *(const float4*)(inputs + ((long long)b*(T+1) + T)*128 + 4*qq);
        float* dst = As + r*260 + 128 + 4*qq;
        dst[0]=tf32r(h.x*nw.x); dst[1]=tf32r(h.y*nw.y);
        dst[2]=tf32r(h.z*nw.z); dst[3]=tf32r(h.w*nw.w);
      }
    }
    float acc[2][4][4];
    #pragma unroll
    for (int mt=0;mt<2;mt++)
      #pragma unroll
      for (int nt=0;nt<4;nt++)
        #pragma unroll
        for (int q=0;q<4;q++) acc[mt][nt][q] = 0.f;
    for (int kc = 0; kc < 2; ++kc) {
      __syncthreads();
      #pragma unroll
      for (int it = 0; it < 16; ++it) {
        int f = it*256 + tid;
        int k8 = f >> 8, rem = f & 255;
        Bp4[f] = Wc4[((long long)(kc*16 + k8)*8)*32 + rem];
      }
      __syncthreads();
      #pragma unroll
      for (int k8 = 0; k8 < 16; ++k8) {
        uint32_t a[2][4];
        #pragma unroll
        for (int mt=0;mt<2;mt++) {
          const float* ap = As + (wm*32 + mt*16 + g)*260 + kc*128 + k8*8 + t4;
          a[mt][0] = __float_as_uint(ap[0]);
          a[mt][1] = __float_as_uint(ap[8*260]);
          a[mt][2] = __float_as_uint(ap[4]);
          a[mt][3] = __float_as_uint(ap[8*260+4]);
        }
        float4 b40 = Bp4[(k8*8 + wn*2    )*32 + lane];
        float4 b41 = Bp4[(k8*8 + wn*2 + 1)*32 + lane];
        uint32_t bb[4][2];
        bb[0][0]=__float_as_uint(b40.x); bb[0][1]=__float_as_uint(b40.y);
        bb[1][0]=__float_as_uint(b40.z); bb[1][1]=__float_as_uint(b40.w);
        bb[2][0]=__float_as_uint(b41.x); bb[2][1]=__float_as_uint(b41.y);
        bb[3][0]=__float_as_uint(b41.z); bb[3][1]=__float_as_uint(b41.w);
        #pragma unroll
        for (int mt=0;mt<2;mt++)
          #pragma unroll
          for (int nt=0;nt<4;nt++)
            mma8(acc[mt][nt], a[mt], bb[nt]);
      }
    }
    __syncthreads();
    float* a1s = Bp;
    #pragma unroll
    for (int mt=0;mt<2;mt++) {
      int row0 = wm*32 + mt*16 + g;
      #pragma unroll
      for (int nt=0;nt<4;nt++) {
        int col = wn*32 + nt*8 + 2*t4;
        #pragma unroll
        for (int h=0; h<2; ++h) {
          int row = row0 + 8*h;
          long long rowg = m0 + row;
          const float* np = nterm + (long long)(rowg / T)*128;
          a1s[row*132 + col]     = tf32r(fmaxf(acc[mt][nt][2*h+0] + np[col],   0.f));
          a1s[row*132 + col + 1] = tf32r(fmaxf(acc[mt][nt][2*h+1] + np[col+1], 0.f));
        }
      }
    }
    __syncthreads();
    {
      float acc2[4][4];
      #pragma unroll
      for (int nt=0;nt<4;nt++)
        #pragma unroll
        for (int q=0;q<4;q++) acc2[nt][q] = 0.f;
      const float4* W2p4 = (const float4*)W2s;
      #pragma unroll
      for (int k8 = 0; k8 < 16; ++k8) {
        uint32_t a[4];
        const float* ap = a1s + (wm3*16 + g)*132 + k8*8 + t4;
        a[0] = __float_as_uint(ap[0]);
        a[1] = __float_as_uint(ap[8*132]);
        a[2] = __float_as_uint(ap[4]);
        a[3] = __float_as_uint(ap[8*132+4]);
        float4 b40 = W2p4[(k8*4 + wn3*2    )*32 + lane];
        float4 b41 = W2p4[(k8*4 + wn3*2 + 1)*32 + lane];
        uint32_t bb[4][2];
        bb[0][0]=__float_as_uint(b40.x); bb[0][1]=__float_as_uint(b40.y);
        bb[1][0]=__float_as_uint(b40.z); bb[1][1]=__float_as_uint(b40.w);
        bb[2][0]=__float_as_uint(b41.x); bb[2][1]=__float_as_uint(b41.y);
        bb[3][0]=__float_as_uint(b41.z); bb[3][1]=__float_as_uint(b41.w);
        #pragma unroll
        for (int nt=0;nt<4;nt++)
          mma8(acc2[nt], a, bb[nt]);
      }
      #pragma unroll
      for (int nt=0;nt<4;nt++) {
        int col = wn3*32 + nt*8 + 2*t4;
        float bc0 = b2[col], bc1 = b2[col+1];
        #pragma unroll
        for (int h=0; h<2; ++h) {
          int row = wm3*16 + g + 8*h;
          a2s[row*68 + col]     = fmaxf(acc2[nt][2*h+0] + bc0, 0.f);
          a2s[row*68 + col + 1] = fmaxf(acc2[nt][2*h+1] + bc1, 0.f);
        }
      }
    }
    __syncthreads();
    if (tid < 64) {
      float accv = b3v;
      #pragma unroll 8
      for (int cc=0; cc<64; ++cc) accv = fmaf(a2s[tid*68 + cc], W3s[cc], accv);
      g_ats[m0 + tid] = sigf(accv);
    }
  }
}

// ------------------------------ head ------------------------------
__global__ void head_kernel(const float* __restrict__ inputs,
                            const float* __restrict__ gamma, const float* __restrict__ beta,
                            const float* __restrict__ mean,  const float* __restrict__ var,
                            const float* __restrict__ W1, const float* __restrict__ bb1,
                            const float* __restrict__ W2, const float* __restrict__ bb2,
                            const float* __restrict__ fW, const float* __restrict__ fb,
                            float* __restrict__ out) {
  extern __shared__ float sm[];
  float* xs  = sm;          // 32*256
  float* y1s = xs + 8192;   // 32*256
  float* y2s = y1s + 8192;  // 32*128
  const int tid = threadIdx.x;   // 256
  const int b0 = blockIdx.x * 32;
  for (int r = 0; r < 32; ++r) {
    int k = tid;
    int bb = b0 + r;
    float v = (k < 128) ? g_hfin[bb*128 + k]
                        : inputs[((long long)bb*(T+1) + T)*128 + (k - 128)];
    float nv = (v - mean[k]) * rsqrtf(var[k] + BN_EPS) * gamma[k] + beta[k];
    xs[r*256 + k] = nv;
  }
  __syncthreads();
  {
    float acc[32];
    #pragma unroll
    for (int r=0;r<32;r++) acc[r] = bb1[tid];
    for (int k=0;k<256;++k) {
      float w = W1[k*256 + tid];
      #pragma unroll
      for (int r=0;r<32;r++) acc[r] = fmaf(xs[r*256+k], w, acc[r]);
    }
    #pragma unroll
    for (int r=0;r<32;r++) {
      float v = acc[r];
      y1s[r*256 + tid] = v >= 0.f ? v : LEAKY*v;
    }
  }
  __syncthreads();
  if (tid < 128) {
    float acc[32];
    #pragma unroll
    for (int r=0;r<32;r++) acc[r] = bb2[tid];
    for (int k=0;k<256;++k) {
      float w = W2[k*128 + tid];
      #pragma unroll
      for (int r=0;r<32;r++) acc[r] = fmaf(y1s[r*256+k], w, acc[r]);
    }
    #pragma unroll
    for (int r=0;r<32;r++) {
      float v = acc[r];
      y2s[r*128 + tid] = v >= 0.f ? v : LEAKY*v;
    }
  }
  __syncthreads();
  if (tid < 32) {
    float acc = fb[0];
    for (int k=0;k<128;++k) acc = fmaf(y2s[tid*128+k], fW[k], acc);
    out[b0 + tid] = sigf(acc);
  }
}

// ------------------------------ launch ------------------------------
extern "C" void kernel_launch(void* const* d_in, const int* in_sizes, int n_in,
                              void* d_out, int out_size) {
  (void)in_sizes; (void)n_in; (void)out_size;
  const float* inputs  = (const float*)d_in[0];
  const float* gru_W   = (const float*)d_in[1];
  const float* gru_U   = (const float*)d_in[2];
  const float* gru_b   = (const float*)d_in[3];
  const float* att_W1  = (const float*)d_in[4];
  const float* att_b1  = (const float*)d_in[5];
  const float* att_W2  = (const float*)d_in[6];
  const float* att_b2  = (const float*)d_in[7];
  const float* att_W3  = (const float*)d_in[8];
  const float* att_b3  = (const float*)d_in[9];
  const float* au_Wu   = (const float*)d_in[10];
  const float* au_bu   = (const float*)d_in[11];
  const float* au_Uu   = (const float*)d_in[12];
  const float* au_Wr   = (const float*)d_in[13];
  const float* au_br   = (const float*)d_in[14];
  const float* au_Ur   = (const float*)d_in[15];
  const float* au_Wc   = (const float*)d_in[16];
  const float* au_bc   = (const float*)d_in[17];
  const float* au_Uc   = (const float*)d_in[18];
  const float* bn_gamma= (const float*)d_in[19];
  const float* bn_beta = (const float*)d_in[20];
  const float* bn_mean = (const float*)d_in[21];
  const float* bn_var  = (const float*)d_in[22];
  const float* d_W1    = (const float*)d_in[23];
  const float* d_b1    = (const float*)d_in[24];
  const float* d_W2    = (const float*)d_in[25];
  const float* d_b2    = (const float*)d_in[26];
  const float* f_W     = (const float*)d_in[27];
  const float* f_b     = (const float*)d_in[28];
  float* out = (float*)d_out;

  const size_t sm_gemm = (64*132 + 16384)*sizeof(float);      // 99328
  const size_t sm_scan = 98304 + 2*A_BUF*sizeof(__nv_bfloat16); // 98304+17408 = 115712
  const size_t sm_attf = (16640 + 16384 + 8192 + 4352 + 64)*sizeof(float); // 182528
  const size_t sm_head = (8192*2 + 4096)*sizeof(float);
  cudaFuncSetAttribute(gemm_v2,        cudaFuncAttributeMaxDynamicSharedMemorySize, (int)sm_gemm);
  cudaFuncSetAttribute(gru_scan_mma,   cudaFuncAttributeMaxDynamicSharedMemorySize, (int)sm_scan);
  cudaFuncSetAttribute(augru_scan_mma, cudaFuncAttributeMaxDynamicSharedMemorySize, (int)sm_scan);
  cudaFuncSetAttribute(att_fused,      cudaFuncAttributeMaxDynamicSharedMemorySize, (int)sm_attf);
  cudaFuncSetAttribute(head_kernel,    cudaFuncAttributeMaxDynamicSharedMemorySize, (int)sm_head);

  float *p_Xp, *p_hs, *p_X3, *p_newsterm, *p_bau;
  float *p_WpgW, *p_Wpau, *p_Wp1bc, *p_Wpcat, *p_Wpatt2;
  uint32_t *p_Ubg, *p_Uba;
  cudaGetSymbolAddress((void**)&p_Xp,       g_Xp);
  cudaGetSymbolAddress((void**)&p_hs,       g_hs);
  cudaGetSymbolAddress((void**)&p_X3,       g_X3);
  cudaGetSymbolAddress((void**)&p_newsterm, g_newsterm);
  cudaGetSymbolAddress((void**)&p_bau,      g_bau);
  cudaGetSymbolAddress((void**)&p_Ubg,      g_Ubf_gru);
  cudaGetSymbolAddress((void**)&p_Uba,      g_Ubf_au);
  cudaGetSymbolAddress((void**)&p_WpgW,     g_Wp_gruW);
  cudaGetSymbolAddress((void**)&p_Wpau,     g_Wp_au);
  cudaGetSymbolAddress((void**)&p_Wp1bc,    g_Wp_1bc);
  cudaGetSymbolAddress((void**)&p_Wpcat,    g_Wp_cat);
  cudaGetSymbolAddress((void**)&p_Wpatt2,   g_Wp_att2);

  cudaStream_t s2;
  cudaStreamCreateWithFlags(&s2, cudaStreamNonBlocking);
  cudaEvent_t evPack, evNews, evFork, evJoin;
  cudaEventCreateWithFlags(&evPack, cudaEventDisableTiming);
  cudaEventCreateWithFlags(&evNews, cudaEventDisableTiming);
  cudaEventCreateWithFlags(&evFork, cudaEventDisableTiming);
  cudaEventCreateWithFlags(&evJoin, cudaEventDisableTiming);

  // 1) fold weights, then all fragment packs
  prep_kernel<<<192, 256>>>(au_Wu, au_bu, au_Wr, au_br, au_Wc, au_bc,
                            au_Uu, au_Ur, au_Uc, att_W1);
  pack_all<<<800, 256>>>(gru_U, gru_W, att_W2);
  cudaEventRecord(evPack, 0);
  cudaStreamWaitEvent(s2, evPack, 0);
  // 2) newsterm = news @ (W1B+W1C) + b1  (side stream; fp32 out)
  gemm_v2<<<dim3(B/64, 1), 256, sm_gemm, s2>>>(inputs + (long long)T*128, 1, (long long)(T+1)*128, 128,
                                               p_Wp1bc, 8, att_b1, p_newsterm, 128, 0);
  cudaEventRecord(evNews, s2);
  // 3) Xp = hist @ gru_W + gru_b[0]   (bf16 out)
  gemm_v2<<<dim3(BT/64, 3), 256, sm_gemm>>>(inputs, T, (long long)(T+1)*128, 128,
                                            p_WpgW, 24, gru_b, p_Xp, 384, 1);
  // 4) GRU recurrence -> hs (bf16 scan, 32 rows/CTA)
  gru_scan_mma<<<B/32, 256, sm_scan>>>((const __nv_bfloat16*)p_Xp, p_Ubg, gru_b + 384, p_hs);
  // fork: X3 gemm on s2, attention on main stream
  cudaEventRecord(evFork, 0);
  cudaStreamWaitEvent(s2, evFork, 0);
  // 5) X3 = hs @ [Wu|Wr|Wc] + [bu|br|bc]   (side stream; bf16 out)
  gemm_v2<<<dim3(BT/64, 3), 256, sm_gemm, s2>>>(p_hs, 1<<30, 0LL, 128,
                                                p_Wpau, 24, p_bau, p_X3, 384, 1);
  cudaEventRecord(evJoin, s2);
  // 6) fused attention -> g_ats  (main stream; needs newsterm)
  cudaStreamWaitEvent(0, evNews, 0);
  att_fused<<<148, 256, sm_attf>>>(p_hs, inputs, p_Wpcat, p_Wpatt2,
                                   att_b2, att_W3, att_b3, p_newsterm);
  cudaStreamWaitEvent(0, evJoin, 0);
  // 7) AUGRU recurrence -> hfin (bf16 scan, 32 rows/CTA)
  augru_scan_mma<<<B/32, 256, sm_scan>>>((const __nv_bfloat16*)p_X3, p_Uba);
  // 8) BN + dense head -> out
  head_kernel<<<B/32, 256, sm_head>>>(inputs, bn_gamma, bn_beta, bn_mean, bn_var,
                                      d_W1, d_b1, d_W2, d_b2, f_W, f_b, out);
}

// round 10
// speedup vs baseline: 1.2470x; 1.2040x over previous
#include <cuda_runtime.h>
#include <cuda_bf16.h>
#include <math.h>
#include <stdint.h>

#define B  4096
#define T  50
#define U  128
#define N3 384
#define BT (B*T)
#define BN_EPS 1e-3f
#define LEAKY  3e-4f

// ------------ scratch (device globals; no allocation allowed) ------------
__device__ float g_Xp[BT*N3];        // GRU input projection (bf16 payload)
__device__ float g_hs[BT*U];         // GRU hidden states
__device__ float g_X3[BT*N3];        // AUGRU input projections (bf16 payload)
__device__ float g_ats[BT];          // attention scores
__device__ float g_hfin[B*U];        // AUGRU final state
__device__ float g_newsterm[B*U];    // news@(W1B+W1C)+b1
__device__ float g_Wau[U*N3];        // packed input  [Wu|Wr|Wc]
__device__ float g_Uau[U*N3];        // packed recur  [Uu|Ur|Uc]
__device__ float g_bau[N3];          // packed [bu|br|bc]
__device__ float g_Wcat[2*U*U];      // [W1A-W1B ; W1D]  (256 x 128)
__device__ float g_W1bc[U*U];        // W1B + W1C
__device__ uint32_t g_Ubf_gru[24576];// bf16 frag gru_U
__device__ uint32_t g_Ubf_au[24576]; // bf16 frag [Uu|Ur|Uc]
__device__ uint32_t g_Wb_gruW[24576];// bf16 frag gru_W     (K=128,N=384)
__device__ uint32_t g_Wb_au[24576];  // bf16 frag [Wu|Wr|Wc]
__device__ uint32_t g_Wb_1bc[8192];  // bf16 frag W1B+W1C   (K=128,N=128)
__device__ uint32_t g_Wb_cat[16384]; // bf16 frag Wcat      (K=256,N=128)
__device__ uint32_t g_Wb_att2[4096]; // bf16 frag att_W2    (K=128,N=64)

__device__ __forceinline__ float sigf(float x){ return 1.f/(1.f+expf(-x)); }
__device__ __forceinline__ float tanha(float x){
  float y; asm("tanh.approx.f32 %0, %1;" : "=f"(y) : "f"(x)); return y;
}
__device__ __forceinline__ float sigt(float x){ return fmaf(tanha(0.5f*x), 0.5f, 0.5f); }
__device__ __forceinline__ uint32_t bf2(float lo, float hi){
  __nv_bfloat162 v;
  v.x = __float2bfloat16(lo); v.y = __float2bfloat16(hi);
  return *(uint32_t*)&v;
}
__device__ __forceinline__ float2 bf2f(uint32_t u){
  __nv_bfloat162 v = *(__nv_bfloat162*)&u;
  return __bfloat1622float2(v);
}
__device__ __forceinline__ uint32_t cvta_s(const void* p){
  return (uint32_t)__cvta_generic_to_shared(p);
}
__device__ __forceinline__ void ldsm4(uint32_t* r, uint32_t addr){
  asm volatile("ldmatrix.sync.aligned.m8n8.x4.shared.b16 {%0,%1,%2,%3}, [%4];"
               : "=r"(r[0]), "=r"(r[1]), "=r"(r[2]), "=r"(r[3]) : "r"(addr));
}
__device__ __forceinline__ void mma16(float* d, const uint32_t* a, const uint32_t* b){
  asm volatile("mma.sync.aligned.m16n8k16.row.col.f32.bf16.bf16.f32 "
               "{%0,%1,%2,%3}, {%4,%5,%6,%7}, {%8,%9}, {%0,%1,%2,%3};"
               : "+f"(d[0]), "+f"(d[1]), "+f"(d[2]), "+f"(d[3])
               : "r"(a[0]), "r"(a[1]), "r"(a[2]), "r"(a[3]), "r"(b[0]), "r"(b[1]));
}

// ------------------------------- prep -------------------------------
__global__ void prep_kernel(const float* __restrict__ Wu, const float* __restrict__ bu,
                            const float* __restrict__ Wr, const float* __restrict__ br,
                            const float* __restrict__ Wc, const float* __restrict__ bc,
                            const float* __restrict__ Uu, const float* __restrict__ Ur,
                            const float* __restrict__ Uc,
                            const float* __restrict__ attW1) {
  int id = blockIdx.x*blockDim.x + threadIdx.x;
  if (id < U*N3) {
    int k = id / N3, c = id % N3;
    float w, u;
    if (c < 128)      { w = Wu[k*128 + c];       u = Uu[k*128 + c]; }
    else if (c < 256) { w = Wr[k*128 + (c-128)]; u = Ur[k*128 + (c-128)]; }
    else              { w = Wc[k*128 + (c-256)]; u = Uc[k*128 + (c-256)]; }
    g_Wau[id] = w;
    g_Uau[id] = u;
  }
  if (id < N3)
    g_bau[id] = (id < 128) ? bu[id] : (id < 256 ? br[id-128] : bc[id-256]);
  if (id < 2*U*U) {
    int k = id / 128, c = id % 128;
    float v;
    if (k < 128) v = attW1[k*128 + c] - attW1[U*U + k*128 + c];     // W1A - W1B
    else         v = attW1[3*U*U + (k-128)*128 + c];                // W1D
    g_Wcat[id] = v;
  }
  if (id < U*U)
    g_W1bc[id] = attW1[U*U + id] + attW1[2*U*U + id];
}

// --------------- pack all weights bf16 fragment-ordered, one launch ---------------
// P[((k16*Ntp + tp)*32 + lane)*4 + q]: tile=2*tp+(q>>1), reg=q&1,
//   k = k16*16 + 2*(lane&3) + 8*reg (lo; hi=k+1),  n = tile*8 + (lane>>2)
__device__ __forceinline__ void pack_bf16_n(const float* __restrict__ Um,
                                            uint32_t* __restrict__ P, int N, int idx) {
  int q = idx & 3, lane = (idx >> 2) & 31;
  int Ntp = N >> 4;
  int tp = (idx >> 7) % Ntp, k16 = (idx >> 7) / Ntp;
  int tile = 2*tp + (q >> 1), r = q & 1;
  int k = k16*16 + 2*(lane & 3) + 8*r;
  int n = tile*8 + (lane >> 2);
  P[idx] = bf2(Um[k*N + n], Um[(k+1)*N + n]);
}

__global__ void pack_all(const float* __restrict__ gruU, const float* __restrict__ gruW,
                         const float* __restrict__ attW2) {
  int idx = blockIdx.x*256 + threadIdx.x;   // 126976 total
  if (idx < 24576)        pack_bf16_n(gruU,   g_Ubf_gru, 384, idx);
  else if (idx < 49152)   pack_bf16_n(g_Uau,  g_Ubf_au,  384, idx - 24576);
  else if (idx < 73728)   pack_bf16_n(gruW,   g_Wb_gruW, 384, idx - 49152);
  else if (idx < 98304)   pack_bf16_n(g_Wau,  g_Wb_au,   384, idx - 73728);
  else if (idx < 106496)  pack_bf16_n(g_W1bc, g_Wb_1bc,  128, idx - 98304);
  else if (idx < 122880)  pack_bf16_n(g_Wcat, g_Wb_cat,  128, idx - 106496);
  else if (idx < 126976)  pack_bf16_n(attW2,  g_Wb_att2, 64,  idx - 122880);
}

// --------------------- bf16 GEMM, packed-B + ldmatrix-A, K=128 ---------------------
// obf=0: C fp32.  obf=1: C bf16.
#define GAS 136   // As stride (bf16)
__global__ void gemm_bf16(const float* __restrict__ A, int P, long long GS, int RS,
                          const uint32_t* __restrict__ Bpk, int Ntp,
                          const float* __restrict__ bias, void* __restrict__ C, int ldc,
                          int obf) {
  extern __shared__ char smc[];
  __nv_bfloat16* As = (__nv_bfloat16*)smc;          // 64 x GAS  (17408 B)
  uint32_t* Bp = (uint32_t*)(smc + 64*GAS*2);       // 8192 u32  (32768 B)
  const int m0 = blockIdx.x * 64;
  const int c0 = blockIdx.y * 128;
  const int tp0 = blockIdx.y * 8;
  const int tid = threadIdx.x;          // 256
  const int kq = tid >> 5, cq = tid & 31;
  const int lane = tid & 31, wid = tid >> 5;
  const int wm = wid & 1, wn = wid >> 1;
  const int g = lane >> 2, t4 = lane & 3;

  #pragma unroll
  for (int it = 0; it < 8; ++it) {
    int r = kq + 8*it;
    int m = m0 + r;
    const float* ap = A + (long long)(m/P)*GS + (long long)(m%P)*RS;
    float4 v = *(const float4*)(ap + 4*cq);
    uint32_t* dst = (uint32_t*)(As + r*GAS + 4*cq);
    dst[0] = bf2(v.x, v.y);
    dst[1] = bf2(v.z, v.w);
  }
  {
    const uint4* src = (const uint4*)Bpk;
    uint4* dst = (uint4*)Bp;
    #pragma unroll
    for (int it = 0; it < 8; ++it) {
      int f = it*256 + tid;               // 2048 uint4
      int k16 = f >> 8, rem = f & 255;
      dst[f] = src[((long long)k16*Ntp + tp0)*32 + rem];
    }
  }
  __syncthreads();

  float acc[2][4][4];
  #pragma unroll
  for (int mt=0;mt<2;mt++)
    #pragma unroll
    for (int nt=0;nt<4;nt++)
      #pragma unroll
      for (int q=0;q<4;q++) acc[mt][nt][q] = 0.f;

  const uint32_t asb = cvta_s(As);
  const uint4* bp4 = (const uint4*)Bp;
  #pragma unroll
  for (int k16 = 0; k16 < 8; ++k16) {
    uint32_t a[2][4];
    #pragma unroll
    for (int mt=0;mt<2;mt++)
      ldsm4(a[mt], asb + ((wm*32 + mt*16 + (lane & 15))*GAS + k16*16 + ((lane >> 4) << 3))*2);
    uint4 b40 = bp4[(k16*8 + wn*2    )*32 + lane];
    uint4 b41 = bp4[(k16*8 + wn*2 + 1)*32 + lane];
    uint32_t bb[4][2];
    bb[0][0]=b40.x; bb[0][1]=b40.y; bb[1][0]=b40.z; bb[1][1]=b40.w;
    bb[2][0]=b41.x; bb[2][1]=b41.y; bb[3][0]=b41.z; bb[3][1]=b41.w;
    #pragma unroll
    for (int mt=0;mt<2;mt++)
      #pragma unroll
      for (int nt=0;nt<4;nt++)
        mma16(acc[mt][nt], a[mt], bb[nt]);
  }
  #pragma unroll
  for (int mt=0;mt<2;mt++) {
    int row0 = m0 + wm*32 + mt*16 + g;
    #pragma unroll
    for (int nt=0;nt<4;nt++) {
      int col = c0 + wn*32 + nt*8 + 2*t4;
      float bc0 = bias[col], bc1 = bias[col+1];
      #pragma unroll
      for (int h=0; h<2; ++h) {
        int row = row0 + 8*h;
        float v0 = acc[mt][nt][2*h+0] + bc0;
        float v1 = acc[mt][nt][2*h+1] + bc1;
        if (obf) {
          *(uint32_t*)((__nv_bfloat16*)C + (long long)row*ldc + col) = bf2(v0, v1);
        } else {
          float2 o = {v0, v1};
          *(float2*)((float*)C + (long long)row*ldc + col) = o;
        }
      }
    }
  }
}

// -------------------- GRU scan, bf16 tensor-core (32 rows/CTA) --------------------
#define A_STRIDE 136
#define A_BUF    (32*A_STRIDE)   // bf16 elements per buffer
__global__ __launch_bounds__(256, 1)
void gru_scan_mma(const __nv_bfloat16* __restrict__ Xp, const uint32_t* __restrict__ Bpack,
                  const float* __restrict__ brec, float* __restrict__ hs) {
  extern __shared__ char smc[];
  uint32_t* Bp = (uint32_t*)smc;                       // 24576 u32
  __nv_bfloat16* Ab = (__nv_bfloat16*)(smc + 98304);   // 2 * A_BUF
  const int tid = threadIdx.x;    // 256
  const int w = tid >> 5, lane = tid & 31;
  const int g = lane >> 2, t4 = lane & 3;
  const int b0 = blockIdx.x * 32;
  #pragma unroll
  for (int it = 0; it < 24; ++it)
    ((float4*)Bp)[it*256 + tid] = ((const float4*)Bpack)[it*256 + tid];
  for (int i = tid; i < A_BUF; i += 256) ((uint32_t*)Ab)[i] = 0u;
  float2 bz[2], brr[2], bh[2];
  #pragma unroll
  for (int nt=0; nt<2; ++nt) {
    int c = (2*w+nt)*8 + 2*t4;
    bz[nt]  = *(const float2*)(brec + c);
    brr[nt] = *(const float2*)(brec + 128 + c);
    bh[nt]  = *(const float2*)(brec + 256 + c);
  }
  float h[2][2][2][2];
  #pragma unroll
  for (int a1=0;a1<2;a1++)
    #pragma unroll
    for (int a2=0;a2<2;a2++)
      #pragma unroll
      for (int a3=0;a3<2;a3++) { h[a1][a2][a3][0]=0.f; h[a1][a2][a3][1]=0.f; }
  const uint32_t abb = cvta_s(Ab);
  __syncthreads();

  for (int t = 0; t < T; ++t) {
    const uint32_t arb = abb + (uint32_t)((t & 1) * A_BUF * 2);
    __nv_bfloat16* Aw = Ab + ((t & 1) ^ 1) * A_BUF;
    float2 xz[2][2][2], xr[2][2][2], xh[2][2][2];
    #pragma unroll
    for (int mt=0;mt<2;mt++)
      #pragma unroll
      for (int rh=0;rh<2;rh++) {
        long long base = ((long long)(b0 + mt*16 + rh*8 + g)*T + t)*N3 + 2*t4;
        #pragma unroll
        for (int nt=0;nt<2;nt++) {
          int c = (2*w+nt)*8;
          xz[mt][rh][nt] = bf2f(*(const uint32_t*)(Xp + base + c));
          xr[mt][rh][nt] = bf2f(*(const uint32_t*)(Xp + base + 128 + c));
          xh[mt][rh][nt] = bf2f(*(const uint32_t*)(Xp + base + 256 + c));
        }
      }
    float acc[2][6][4];
    #pragma unroll
    for (int mt=0;mt<2;mt++)
      #pragma unroll
      for (int j=0;j<6;j++)
        #pragma unroll
        for (int q=0;q<4;q++) acc[mt][j][q] = 0.f;
    #pragma unroll
    for (int k16=0;k16<8;++k16) {
      uint32_t a[2][4];
      #pragma unroll
      for (int mt=0;mt<2;mt++)
        ldsm4(a[mt], arb + ((mt*16 + (lane & 15))*A_STRIDE + k16*16 + ((lane >> 4) << 3))*2);
      uint4 bv0 = ((const uint4*)Bp)[(k16*24 +      w)*32 + lane];
      uint4 bv1 = ((const uint4*)Bp)[(k16*24 +  8 + w)*32 + lane];
      uint4 bv2 = ((const uint4*)Bp)[(k16*24 + 16 + w)*32 + lane];
      uint32_t bb[6][2];
      bb[0][0]=bv0.x; bb[0][1]=bv0.y; bb[1][0]=bv0.z; bb[1][1]=bv0.w;
      bb[2][0]=bv1.x; bb[2][1]=bv1.y; bb[3][0]=bv1.z; bb[3][1]=bv1.w;
      bb[4][0]=bv2.x; bb[4][1]=bv2.y; bb[5][0]=bv2.z; bb[5][1]=bv2.w;
      #pragma unroll
      for (int mt=0;mt<2;mt++)
        #pragma unroll
        for (int j=0;j<6;j++)
          mma16(acc[mt][j], a[mt], bb[j]);
    }
    #pragma unroll
    for (int mt=0;mt<2;mt++)
      #pragma unroll
      for (int rh=0;rh<2;rh++) {
        int row = mt*16 + rh*8 + g;
        long long grow = ((long long)(b0+row)*T + t)*128;
        #pragma unroll
        for (int nt=0;nt<2;nt++) {
          int c = (2*w+nt)*8 + 2*t4;
          float hn0, hn1;
          {
            float z  = sigt(xz[mt][rh][nt].x + acc[mt][nt][rh*2]     + bz[nt].x);
            float r  = sigt(xr[mt][rh][nt].x + acc[mt][2+nt][rh*2]   + brr[nt].x);
            float hc = tanha(xh[mt][rh][nt].x + r*(acc[mt][4+nt][rh*2] + bh[nt].x));
            float ho = h[mt][rh][nt][0];
            hn0 = z*ho + (1.f - z)*hc;
            h[mt][rh][nt][0] = hn0;
          }
          {
            float z  = sigt(xz[mt][rh][nt].y + acc[mt][nt][rh*2+1]     + bz[nt].y);
            float r  = sigt(xr[mt][rh][nt].y + acc[mt][2+nt][rh*2+1]   + brr[nt].y);
            float hc = tanha(xh[mt][rh][nt].y + r*(acc[mt][4+nt][rh*2+1] + bh[nt].y));
            float ho = h[mt][rh][nt][1];
            hn1 = z*ho + (1.f - z)*hc;
            h[mt][rh][nt][1] = hn1;
          }
          float2 o = {hn0, hn1};
          *(float2*)(hs + grow + c) = o;
          *(uint32_t*)(Aw + row*A_STRIDE + c) = bf2(hn0, hn1);
        }
      }
    __syncthreads();
  }
}

// -------------------- AUGRU scan, bf16 tensor-core (32 rows/CTA) --------------------
__global__ __launch_bounds__(256, 1)
void augru_scan_mma(const __nv_bfloat16* __restrict__ X3, const uint32_t* __restrict__ Bpack) {
  extern __shared__ char smc[];
  uint32_t* Bp = (uint32_t*)smc;
  __nv_bfloat16* Ab = (__nv_bfloat16*)(smc + 98304);
  const int tid = threadIdx.x;
  const int w = tid >> 5, lane = tid & 31;
  const int g = lane >> 2, t4 = lane & 3;
  const int b0 = blockIdx.x * 32;
  #pragma unroll
  for (int it = 0; it < 24; ++it)
    ((float4*)Bp)[it*256 + tid] = ((const float4*)Bpack)[it*256 + tid];
  for (int i = tid; i < A_BUF; i += 256) ((uint32_t*)Ab)[i] = 0u;
  float h[2][2][2][2];
  #pragma unroll
  for (int a1=0;a1<2;a1++)
    #pragma unroll
    for (int a2=0;a2<2;a2++)
      #pragma unroll
      for (int a3=0;a3<2;a3++) { h[a1][a2][a3][0]=0.f; h[a1][a2][a3][1]=0.f; }
  const uint32_t abb = cvta_s(Ab);
  __syncthreads();

  for (int t = 0; t < T; ++t) {
    const uint32_t arb = abb + (uint32_t)((t & 1) * A_BUF * 2);
    __nv_bfloat16* Aw = Ab + ((t & 1) ^ 1) * A_BUF;
    float2 xu[2][2][2], xr[2][2][2], xc[2][2][2];
    float at[2][2];
    #pragma unroll
    for (int mt=0;mt<2;mt++)
      #pragma unroll
      for (int rh=0;rh<2;rh++) {
        long long rowg = (long long)(b0 + mt*16 + rh*8 + g)*T + t;
        at[mt][rh] = g_ats[rowg];
        long long base = rowg*N3 + 2*t4;
        #pragma unroll
        for (int nt=0;nt<2;nt++) {
          int c = (2*w+nt)*8;
          xu[mt][rh][nt] = bf2f(*(const uint32_t*)(X3 + base + c));
          xr[mt][rh][nt] = bf2f(*(const uint32_t*)(X3 + base + 128 + c));
          xc[mt][rh][nt] = bf2f(*(const uint32_t*)(X3 + base + 256 + c));
        }
      }
    float acc[2][6][4];
    #pragma unroll
    for (int mt=0;mt<2;mt++)
      #pragma unroll
      for (int j=0;j<6;j++)
        #pragma unroll
        for (int q=0;q<4;q++) acc[mt][j][q] = 0.f;
    #pragma unroll
    for (int k16=0;k16<8;++k16) {
      uint32_t a[2][4];
      #pragma unroll
      for (int mt=0;mt<2;mt++)
        ldsm4(a[mt], arb + ((mt*16 + (lane & 15))*A_STRIDE + k16*16 + ((lane >> 4) << 3))*2);
      uint4 bv0 = ((const uint4*)Bp)[(k16*24 +      w)*32 + lane];
      uint4 bv1 = ((const uint4*)Bp)[(k16*24 +  8 + w)*32 + lane];
      uint4 bv2 = ((const uint4*)Bp)[(k16*24 + 16 + w)*32 + lane];
      uint32_t bb[6][2];
      bb[0][0]=bv0.x; bb[0][1]=bv0.y; bb[1][0]=bv0.z; bb[1][1]=bv0.w;
      bb[2][0]=bv1.x; bb[2][1]=bv1.y; bb[3][0]=bv1.z; bb[3][1]=bv1.w;
      bb[4][0]=bv2.x; bb[4][1]=bv2.y; bb[5][0]=bv2.z; bb[5][1]=bv2.w;
      #pragma unroll
      for (int mt=0;mt<2;mt++)
        #pragma unroll
        for (int j=0;j<6;j++)
          mma16(acc[mt][j], a[mt], bb[j]);
    }
    #pragma unroll
    for (int mt=0;mt<2;mt++)
      #pragma unroll
      for (int rh=0;rh<2;rh++) {
        int row = mt*16 + rh*8 + g;
        float atv = at[mt][rh];
        #pragma unroll
        for (int nt=0;nt<2;nt++) {
          int c = (2*w+nt)*8 + 2*t4;
          float hn0, hn1;
          {
            float u  = sigt(xu[mt][rh][nt].x + acc[mt][nt][rh*2]);
            float r  = sigt(xr[mt][rh][nt].x + acc[mt][2+nt][rh*2]);
            float cc = tanha(xc[mt][rh][nt].x + r*acc[mt][4+nt][rh*2]);
            float uu = atv*u;
            float ho = h[mt][rh][nt][0];
            hn0 = (1.f - uu)*ho + uu*cc;
            h[mt][rh][nt][0] = hn0;
          }
          {
            float u  = sigt(xu[mt][rh][nt].y + acc[mt][nt][rh*2+1]);
            float r  = sigt(xr[mt][rh][nt].y + acc[mt][2+nt][rh*2+1]);
            float cc = tanha(xc[mt][rh][nt].y + r*acc[mt][4+nt][rh*2+1]);
            float uu = atv*u;
            float ho = h[mt][rh][nt][1];
            hn1 = (1.f - uu)*ho + uu*cc;
            h[mt][rh][nt][1] = hn1;
          }
          *(uint32_t*)(Aw + row*A_STRIDE + c) = bf2(hn0, hn1);
        }
      }
    __syncthreads();
  }
  #pragma unroll
  for (int mt=0;mt<2;mt++)
    #pragma unroll
    for (int rh=0;rh<2;rh++) {
      int row = mt*16 + rh*8 + g;
      #pragma unroll
      for (int nt=0;nt<2;nt++) {
        int c = (2*w+nt)*8 + 2*t4;
        float2 o = {h[mt][rh][nt][0], h[mt][rh][nt][1]};
        *(float2*)(g_hfin + (long long)(b0+row)*128 + c) = o;
      }
    }
}

// ------------- fused attention (bf16): hs,news -> a1 -> a2 -> ats -------------
#define ATT_AS 264   // As stride (bf16)
__global__ __launch_bounds__(256, 1)
void att_fused(const float* __restrict__ hs, const float* __restrict__ inputs,
               const uint32_t* __restrict__ Wcatp, const uint32_t* __restrict__ W2p,
               const float* __restrict__ b2, const float* __restrict__ W3,
               const float* __restrict__ b3, const float* __restrict__ nterm) {
  extern __shared__ char smc[];
  __nv_bfloat16* As  = (__nv_bfloat16*)smc;            // 64 x 264        (33792 B)
  uint32_t* Wc  = (uint32_t*)(smc + 33792);            // 16384 u32       (65536 B)
  __nv_bfloat16* a1s = (__nv_bfloat16*)(smc + 99328);  // 64 x 136        (17408 B)
  uint32_t* W2s = (uint32_t*)(smc + 116736);           // 4096 u32        (16384 B)
  float* a2s = (float*)(smc + 133120);                 // 64 x 68         (17408 B)
  float* W3s = (float*)(smc + 150528);                 // 64
  const int tid = threadIdx.x;     // 256
  const int lane = tid & 31, wid = tid >> 5;
  const int wm = wid & 1, wn = wid >> 1;
  const int wm3 = wid & 3, wn3 = wid >> 2;
  const int g = lane >> 2, t4 = lane & 3;
  const float b3v = b3[0];

  {
    const uint4* src = (const uint4*)Wcatp;
    uint4* dst = (uint4*)Wc;
    #pragma unroll
    for (int it = 0; it < 16; ++it) dst[it*256 + tid] = src[it*256 + tid];
    const uint4* src2 = (const uint4*)W2p;
    uint4* dst2 = (uint4*)W2s;
    #pragma unroll
    for (int it = 0; it < 4; ++it) dst2[it*256 + tid] = src2[it*256 + tid];
    if (tid < 64) W3s[tid] = W3[tid];
  }
  const uint32_t asb = cvta_s(As);
  const uint32_t a1b = cvta_s(a1s);
  const uint4* Wc4 = (const uint4*)Wc;
  const uint4* W2p4 = (const uint4*)W2s;

  for (long long blk = blockIdx.x; blk < BT/64; blk += gridDim.x) {
    const long long m0 = blk * 64;
    __syncthreads();   // protect As / a2s from previous iteration readers
    // build A = [hs | hs*news] (bf16), 64 x 256
    #pragma unroll
    for (int it = 0; it < 16; ++it) {
      int idx = it*256 + tid;
      int r = idx >> 6, q = idx & 63;
      long long row = m0 + r;
      int b = (int)(row / T);
      if (q < 32) {
        float4 hv = *(const float4*)(hs + row*128 + 4*q);
        uint32_t* dst = (uint32_t*)(As + r*ATT_AS + 4*q);
        dst[0] = bf2(hv.x, hv.y);
        dst[1] = bf2(hv.z, hv.w);
      } else {
        int qq = q - 32;
        float4 hv = *(const float4*)(hs + row*128 + 4*qq);
        float4 nw = *(const float4*)(inputs + ((long long)b*(T+1) + T)*128 + 4*qq);
        uint32_t* dst = (uint32_t*)(As + r*ATT_AS + 128 + 4*qq);
        dst[0] = bf2(hv.x*nw.x, hv.y*nw.y);
        dst[1] = bf2(hv.z*nw.z, hv.w*nw.w);
      }
    }
    __syncthreads();
    // layer 1: K=256, 16 k16 iters
    float acc[2][4][4];
    #pragma unroll
    for (int mt=0;mt<2;mt++)
      #pragma unroll
      for (int nt=0;nt<4;nt++)
        #pragma unroll
        for (int q=0;q<4;q++) acc[mt][nt][q] = 0.f;
    #pragma unroll
    for (int k16 = 0; k16 < 16; ++k16) {
      uint32_t a[2][4];
      #pragma unroll
      for (int mt=0;mt<2;mt++)
        ldsm4(a[mt], asb + ((wm*32 + mt*16 + (lane & 15))*ATT_AS + k16*16 + ((lane >> 4) << 3))*2);
      uint4 b40 = Wc4[(k16*8 + wn*2    )*32 + lane];
      uint4 b41 = Wc4[(k16*8 + wn*2 + 1)*32 + lane];
      uint32_t bb[4][2];
      bb[0][0]=b40.x; bb[0][1]=b40.y; bb[1][0]=b40.z; bb[1][1]=b40.w;
      bb[2][0]=b41.x; bb[2][1]=b41.y; bb[3][0]=b41.z; bb[3][1]=b41.w;
      #pragma unroll
      for (int mt=0;mt<2;mt++)
        #pragma unroll
        for (int nt=0;nt<4;nt++)
          mma16(acc[mt][nt], a[mt], bb[nt]);
    }
    // epilogue -> a1s (bf16, +nterm, relu)
    #pragma unroll
    for (int mt=0;mt<2;mt++) {
      int row0 = wm*32 + mt*16 + g;
      #pragma unroll
      for (int nt=0;nt<4;nt++) {
        int col = wn*32 + nt*8 + 2*t4;
        #pragma unroll
        for (int h=0; h<2; ++h) {
          int row = row0 + 8*h;
          long long rowg = m0 + row;
          const float* np = nterm + (long long)(rowg / T)*128;
          float v0 = fmaxf(acc[mt][nt][2*h+0] + np[col],   0.f);
          float v1 = fmaxf(acc[mt][nt][2*h+1] + np[col+1], 0.f);
          *(uint32_t*)(a1s + row*A_STRIDE + col) = bf2(v0, v1);
        }
      }
    }
    __syncthreads();
    // layer 2: a2 = relu(a1 @ W2 + b2), 64x64, K=128 (8 k16 iters)
    {
      float acc2[4][4];
      #pragma unroll
      for (int nt=0;nt<4;nt++)
        #pragma unroll
        for (int q=0;q<4;q++) acc2[nt][q] = 0.f;
      #pragma unroll
      for (int k16 = 0; k16 < 8; ++k16) {
        uint32_t a[4];
        ldsm4(a, a1b + ((wm3*16 + (lane & 15))*A_STRIDE + k16*16 + ((lane >> 4) << 3))*2);
        uint4 b40 = W2p4[(k16*4 + wn3*2    )*32 + lane];
        uint4 b41 = W2p4[(k16*4 + wn3*2 + 1)*32 + lane];
        uint32_t bb[4][2];
        bb[0][0]=b40.x; bb[0][1]=b40.y; bb[1][0]=b40.z; bb[1][1]=b40.w;
        bb[2][0]=b41.x; bb[2][1]=b41.y; bb[3][0]=b41.z; bb[3][1]=b41.w;
        #pragma unroll
        for (int nt=0;nt<4;nt++)
          mma16(acc2[nt], a, bb[nt]);
      }
      #pragma unroll
      for (int nt=0;nt<4;nt++) {
        int col = wn3*32 + nt*8 + 2*t4;
        float bc0 = b2[col], bc1 = b2[col+1];
        #pragma unroll
        for (int h=0; h<2; ++h) {
          int row = wm3*16 + g + 8*h;
          a2s[row*68 + col]     = fmaxf(acc2[nt][2*h+0] + bc0, 0.f);
          a2s[row*68 + col + 1] = fmaxf(acc2[nt][2*h+1] + bc1, 0.f);
        }
      }
    }
    __syncthreads();
    if (tid < 64) {
      float accv = b3v;
      #pragma unroll 8
      for (int cc=0; cc<64; ++cc) accv = fmaf(a2s[tid*68 + cc], W3s[cc], accv);
      g_ats[m0 + tid] = sigf(accv);
    }
  }
}

// ------------------------------ head ------------------------------
__global__ void head_kernel(const float* __restrict__ inputs,
                            const float* __restrict__ gamma, const float* __restrict__ beta,
                            const float* __restrict__ mean,  const float* __restrict__ var,
                            const float* __restrict__ W1, const float* __restrict__ bb1,
                            const float* __restrict__ W2, const float* __restrict__ bb2,
                            const float* __restrict__ fW, const float* __restrict__ fb,
                            float* __restrict__ out) {
  extern __shared__ float sm[];
  float* xs  = sm;          // 32*256
  float* y1s = xs + 8192;   // 32*256
  float* y2s = y1s + 8192;  // 32*128
  const int tid = threadIdx.x;   // 256
  const int b0 = blockIdx.x * 32;
  for (int r = 0; r < 32; ++r) {
    int k = tid;
    int bb = b0 + r;
    float v = (k < 128) ? g_hfin[bb*128 + k]
                        : inputs[((long long)bb*(T+1) + T)*128 + (k - 128)];
    float nv = (v - mean[k]) * rsqrtf(var[k] + BN_EPS) * gamma[k] + beta[k];
    xs[r*256 + k] = nv;
  }
  __syncthreads();
  {
    float acc[32];
    #pragma unroll
    for (int r=0;r<32;r++) acc[r] = bb1[tid];
    for (int k=0;k<256;++k) {
      float w = W1[k*256 + tid];
      #pragma unroll
      for (int r=0;r<32;r++) acc[r] = fmaf(xs[r*256+k], w, acc[r]);
    }
    #pragma unroll
    for (int r=0;r<32;r++) {
      float v = acc[r];
      y1s[r*256 + tid] = v >= 0.f ? v : LEAKY*v;
    }
  }
  __syncthreads();
  if (tid < 128) {
    float acc[32];
    #pragma unroll
    for (int r=0;r<32;r++) acc[r] = bb2[tid];
    for (int k=0;k<256;++k) {
      float w = W2[k*128 + tid];
      #pragma unroll
      for (int r=0;r<32;r++) acc[r] = fmaf(y1s[r*256+k], w, acc[r]);
    }
    #pragma unroll
    for (int r=0;r<32;r++) {
      float v = acc[r];
      y2s[r*128 + tid] = v >= 0.f ? v : LEAKY*v;
    }
  }
  __syncthreads();
  if (tid < 32) {
    float acc = fb[0];
    for (int k=0;k<128;++k) acc = fmaf(y2s[tid*128+k], fW[k], acc);
    out[b0 + tid] = sigf(acc);
  }
}

// ------------------------------ launch ------------------------------
extern "C" void kernel_launch(void* const* d_in, const int* in_sizes, int n_in,
                              void* d_out, int out_size) {
  (void)in_sizes; (void)n_in; (void)out_size;
  const float* inputs  = (const float*)d_in[0];
  const float* gru_W   = (const float*)d_in[1];
  const float* gru_U   = (const float*)d_in[2];
  const float* gru_b   = (const float*)d_in[3];
  const float* att_W1  = (const float*)d_in[4];
  const float* att_b1  = (const float*)d_in[5];
  const float* att_W2  = (const float*)d_in[6];
  const float* att_b2  = (const float*)d_in[7];
  const float* att_W3  = (const float*)d_in[8];
  const float* att_b3  = (const float*)d_in[9];
  const float* au_Wu   = (const float*)d_in[10];
  const float* au_bu   = (const float*)d_in[11];
  const float* au_Uu   = (const float*)d_in[12];
  const float* au_Wr   = (const float*)d_in[13];
  const float* au_br   = (const float*)d_in[14];
  const float* au_Ur   = (const float*)d_in[15];
  const float* au_Wc   = (const float*)d_in[16];
  const float* au_bc   = (const float*)d_in[17];
  const float* au_Uc   = (const float*)d_in[18];
  const float* bn_gamma= (const float*)d_in[19];
  const float* bn_beta = (const float*)d_in[20];
  const float* bn_mean = (const float*)d_in[21];
  const float* bn_var  = (const float*)d_in[22];
  const float* d_W1    = (const float*)d_in[23];
  const float* d_b1    = (const float*)d_in[24];
  const float* d_W2    = (const float*)d_in[25];
  const float* d_b2    = (const float*)d_in[26];
  const float* f_W     = (const float*)d_in[27];
  const float* f_b     = (const float*)d_in[28];
  float* out = (float*)d_out;

  const size_t sm_gemm = 64*GAS*2 + 8192*4;                     // 50176
  const size_t sm_scan = 98304 + 2*A_BUF*sizeof(__nv_bfloat16); // 115712
  const size_t sm_attf = 150784;
  const size_t sm_head = (8192*2 + 4096)*sizeof(float);
  cudaFuncSetAttribute(gemm_bf16,      cudaFuncAttributeMaxDynamicSharedMemorySize, (int)sm_gemm);
  cudaFuncSetAttribute(gru_scan_mma,   cudaFuncAttributeMaxDynamicSharedMemorySize, (int)sm_scan);
  cudaFuncSetAttribute(augru_scan_mma, cudaFuncAttributeMaxDynamicSharedMemorySize, (int)sm_scan);
  cudaFuncSetAttribute(att_fused,      cudaFuncAttributeMaxDynamicSharedMemorySize, (int)sm_attf);
  cudaFuncSetAttribute(head_kernel,    cudaFuncAttributeMaxDynamicSharedMemorySize, (int)sm_head);

  float *p_Xp, *p_hs, *p_X3, *p_newsterm, *p_bau;
  uint32_t *p_Ubg, *p_Uba, *p_WbgW, *p_Wbau, *p_Wb1bc, *p_Wbcat, *p_Wbatt2;
  cudaGetSymbolAddress((void**)&p_Xp,       g_Xp);
  cudaGetSymbolAddress((void**)&p_hs,       g_hs);
  cudaGetSymbolAddress((void**)&p_X3,       g_X3);
  cudaGetSymbolAddress((void**)&p_newsterm, g_newsterm);
  cudaGetSymbolAddress((void**)&p_bau,      g_bau);
  cudaGetSymbolAddress((void**)&p_Ubg,      g_Ubf_gru);
  cudaGetSymbolAddress((void**)&p_Uba,      g_Ubf_au);
  cudaGetSymbolAddress((void**)&p_WbgW,     g_Wb_gruW);
  cudaGetSymbolAddress((void**)&p_Wbau,     g_Wb_au);
  cudaGetSymbolAddress((void**)&p_Wb1bc,    g_Wb_1bc);
  cudaGetSymbolAddress((void**)&p_Wbcat,    g_Wb_cat);
  cudaGetSymbolAddress((void**)&p_Wbatt2,   g_Wb_att2);

  cudaStream_t s2;
  cudaStreamCreateWithFlags(&s2, cudaStreamNonBlocking);
  cudaEvent_t evPack, evNews, evFork, evJoin;
  cudaEventCreateWithFlags(&evPack, cudaEventDisableTiming);
  cudaEventCreateWithFlags(&evNews, cudaEventDisableTiming);
  cudaEventCreateWithFlags(&evFork, cudaEventDisableTiming);
  cudaEventCreateWithFlags(&evJoin, cudaEventDisableTiming);

  // 1) fold weights, then all bf16 fragment packs
  prep_kernel<<<192, 256>>>(au_Wu, au_bu, au_Wr, au_br, au_Wc, au_bc,
                            au_Uu, au_Ur, au_Uc, att_W1);
  pack_all<<<496, 256>>>(gru_U, gru_W, att_W2);
  cudaEventRecord(evPack, 0);
  cudaStreamWaitEvent(s2, evPack, 0);
  // 2) newsterm = news @ (W1B+W1C) + b1  (side stream; fp32 out)
  gemm_bf16<<<dim3(B/64, 1), 256, sm_gemm, s2>>>(inputs + (long long)T*128, 1, (long long)(T+1)*128, 128,
                                                 p_Wb1bc, 8, att_b1, p_newsterm, 128, 0);
  cudaEventRecord(evNews, s2);
  // 3) Xp = hist @ gru_W + gru_b[0]   (bf16 out)
  gemm_bf16<<<dim3(BT/64, 3), 256, sm_gemm>>>(inputs, T, (long long)(T+1)*128, 128,
                                              p_WbgW, 24, gru_b, p_Xp, 384, 1);
  // 4) GRU recurrence -> hs
  gru_scan_mma<<<B/32, 256, sm_scan>>>((const __nv_bfloat16*)p_Xp, p_Ubg, gru_b + 384, p_hs);
  // fork: X3 gemm on s2, attention on main stream
  cudaEventRecord(evFork, 0);
  cudaStreamWaitEvent(s2, evFork, 0);
  // 5) X3 = hs @ [Wu|Wr|Wc] + [bu|br|bc]   (side stream; bf16 out)
  gemm_bf16<<<dim3(BT/64, 3), 256, sm_gemm, s2>>>(p_hs, 1<<30, 0LL, 128,
                                                  p_Wbau, 24, p_bau, p_X3, 384, 1);
  cudaEventRecord(evJoin, s2);
  // 6) fused attention -> g_ats  (main stream; needs newsterm)
  cudaStreamWaitEvent(0, evNews, 0);
  att_fused<<<148, 256, sm_attf>>>(p_hs, inputs, p_Wbcat, p_Wbatt2,
                                   att_b2, att_W3, att_b3, p_newsterm);
  cudaStreamWaitEvent(0, evJoin, 0);
  // 7) AUGRU recurrence -> hfin
  augru_scan_mma<<<B/32, 256, sm_scan>>>((const __nv_bfloat16*)p_X3, p_Uba);
  // 8) BN + dense head -> out
  head_kernel<<<B/32, 256, sm_head>>>(inputs, bn_gamma, bn_beta, bn_mean, bn_var,
                                      d_W1, d_b1, d_W2, d_b2, f_W, f_b, out);
}

// round 11
// speedup vs baseline: 1.2868x; 1.0319x over previous
#include <cuda_runtime.h>
#include <cuda_bf16.h>
#include <math.h>
#include <stdint.h>

#define B  4096
#define T  50
#define U  128
#define N3 384
#define BT (B*T)
#define BN_EPS 1e-3f
#define LEAKY  3e-4f

// ------------ scratch (device globals; no allocation allowed) ------------
__device__ float g_Xp[BT*N3];        // GRU input projection (bf16 payload)
__device__ float g_hs[BT*U];         // GRU hidden states
__device__ float g_X3[BT*N3];        // AUGRU input projections (bf16 payload)
__device__ float g_ats[BT];          // attention scores
__device__ float g_hfin[B*U];        // AUGRU final state
__device__ float g_newsterm[B*U];    // news@(W1B+W1C)+b1
__device__ float g_Wau[U*N3];        // packed input  [Wu|Wr|Wc]
__device__ float g_Uau[U*N3];        // packed recur  [Uu|Ur|Uc]
__device__ float g_bau[N3];          // packed [bu|br|bc]
__device__ float g_Wcat[2*U*U];      // [W1A-W1B ; W1D]  (256 x 128)
__device__ float g_W1bc[U*U];        // W1B + W1C
__device__ uint32_t g_Ubf_gru[24576];// bf16 frag gru_U
__device__ uint32_t g_Ubf_au[24576]; // bf16 frag [Uu|Ur|Uc]
__device__ uint32_t g_Wb_gruW[24576];// bf16 frag gru_W     (K=128,N=384)
__device__ uint32_t g_Wb_au[24576];  // bf16 frag [Wu|Wr|Wc]
__device__ uint32_t g_Wb_1bc[8192];  // bf16 frag W1B+W1C   (K=128,N=128)
__device__ uint32_t g_Wb_cat[16384]; // bf16 frag Wcat      (K=256,N=128)
__device__ uint32_t g_Wb_att2[4096]; // bf16 frag att_W2    (K=128,N=64)

__device__ __forceinline__ float sigf(float x){ return 1.f/(1.f+expf(-x)); }
__device__ __forceinline__ float tanha(float x){
  float y; asm("tanh.approx.f32 %0, %1;" : "=f"(y) : "f"(x)); return y;
}
__device__ __forceinline__ float sigt(float x){ return fmaf(tanha(0.5f*x), 0.5f, 0.5f); }
__device__ __forceinline__ uint32_t bf2(float lo, float hi){
  __nv_bfloat162 v;
  v.x = __float2bfloat16(lo); v.y = __float2bfloat16(hi);
  return *(uint32_t*)&v;
}
__device__ __forceinline__ float2 bf2f(uint32_t u){
  __nv_bfloat162 v = *(__nv_bfloat162*)&u;
  return __bfloat1622float2(v);
}
__device__ __forceinline__ uint32_t cvta_s(const void* p){
  return (uint32_t)__cvta_generic_to_shared(p);
}
__device__ __forceinline__ void ldsm4(uint32_t* r, uint32_t addr){
  asm volatile("ldmatrix.sync.aligned.m8n8.x4.shared.b16 {%0,%1,%2,%3}, [%4];"
               : "=r"(r[0]), "=r"(r[1]), "=r"(r[2]), "=r"(r[3]) : "r"(addr));
}
__device__ __forceinline__ void mma16(float* d, const uint32_t* a, const uint32_t* b){
  asm volatile("mma.sync.aligned.m16n8k16.row.col.f32.bf16.bf16.f32 "
               "{%0,%1,%2,%3}, {%4,%5,%6,%7}, {%8,%9}, {%0,%1,%2,%3};"
               : "+f"(d[0]), "+f"(d[1]), "+f"(d[2]), "+f"(d[3])
               : "r"(a[0]), "r"(a[1]), "r"(a[2]), "r"(a[3]), "r"(b[0]), "r"(b[1]));
}

// ------------------------------- prep -------------------------------
__global__ void prep_kernel(const float* __restrict__ Wu, const float* __restrict__ bu,
                            const float* __restrict__ Wr, const float* __restrict__ br,
                            const float* __restrict__ Wc, const float* __restrict__ bc,
                            const float* __restrict__ Uu, const float* __restrict__ Ur,
                            const float* __restrict__ Uc,
                            const float* __restrict__ attW1) {
  int id = blockIdx.x*blockDim.x + threadIdx.x;
  if (id < U*N3) {
    int k = id / N3, c = id % N3;
    float w, u;
    if (c < 128)      { w = Wu[k*128 + c];       u = Uu[k*128 + c]; }
    else if (c < 256) { w = Wr[k*128 + (c-128)]; u = Ur[k*128 + (c-128)]; }
    else              { w = Wc[k*128 + (c-256)]; u = Uc[k*128 + (c-256)]; }
    g_Wau[id] = w;
    g_Uau[id] = u;
  }
  if (id < N3)
    g_bau[id] = (id < 128) ? bu[id] : (id < 256 ? br[id-128] : bc[id-256]);
  if (id < 2*U*U) {
    int k = id / 128, c = id % 128;
    float v;
    if (k < 128) v = attW1[k*128 + c] - attW1[U*U + k*128 + c];     // W1A - W1B
    else         v = attW1[3*U*U + (k-128)*128 + c];                // W1D
    g_Wcat[id] = v;
  }
  if (id < U*U)
    g_W1bc[id] = attW1[U*U + id] + attW1[2*U*U + id];
}

// --------------- pack all weights bf16 fragment-ordered ---------------
__device__ __forceinline__ void pack_bf16_n(const float* __restrict__ Um,
                                            uint32_t* __restrict__ P, int N, int idx) {
  int q = idx & 3, lane = (idx >> 2) & 31;
  int Ntp = N >> 4;
  int tp = (idx >> 7) % Ntp, k16 = (idx >> 7) / Ntp;
  int tile = 2*tp + (q >> 1), r = q & 1;
  int k = k16*16 + 2*(lane & 3) + 8*r;
  int n = tile*8 + (lane >> 2);
  P[idx] = bf2(Um[k*N + n], Um[(k+1)*N + n]);
}

__global__ void pack_all(const float* __restrict__ gruU, const float* __restrict__ gruW,
                         const float* __restrict__ attW2) {
  int idx = blockIdx.x*256 + threadIdx.x;   // 126976 total
  if (idx < 24576)        pack_bf16_n(gruU,   g_Ubf_gru, 384, idx);
  else if (idx < 49152)   pack_bf16_n(g_Uau,  g_Ubf_au,  384, idx - 24576);
  else if (idx < 73728)   pack_bf16_n(gruW,   g_Wb_gruW, 384, idx - 49152);
  else if (idx < 98304)   pack_bf16_n(g_Wau,  g_Wb_au,   384, idx - 73728);
  else if (idx < 106496)  pack_bf16_n(g_W1bc, g_Wb_1bc,  128, idx - 98304);
  else if (idx < 122880)  pack_bf16_n(g_Wcat, g_Wb_cat,  128, idx - 106496);
  else if (idx < 126976)  pack_bf16_n(attW2,  g_Wb_att2, 64,  idx - 122880);
}

// --------------------- bf16 GEMM, packed-B + ldmatrix-A, K=128 ---------------------
// obf=0: C fp32 direct.  obf=1: C bf16, SMEM-staged coalesced stores.
#define GAS 136   // As stride (bf16)
__global__ void gemm_bf16(const float* __restrict__ A, int P, long long GS, int RS,
                          const uint32_t* __restrict__ Bpk, int Ntp,
                          const float* __restrict__ bias, void* __restrict__ C, int ldc,
                          int obf) {
  extern __shared__ char smc[];
  __nv_bfloat16* As = (__nv_bfloat16*)smc;          // 64 x GAS  (17408 B)
  uint32_t* Bp = (uint32_t*)(smc + 64*GAS*2);       // 8192 u32  (32768 B)
  const int m0 = blockIdx.x * 64;
  const int c0 = blockIdx.y * 128;
  const int tp0 = blockIdx.y * 8;
  const int tid = threadIdx.x;          // 256
  const int kq = tid >> 5, cq = tid & 31;
  const int lane = tid & 31, wid = tid >> 5;
  const int wm = wid & 1, wn = wid >> 1;
  const int g = lane >> 2, t4 = lane & 3;

  #pragma unroll
  for (int it = 0; it < 8; ++it) {
    int r = kq + 8*it;
    int m = m0 + r;
    const float* ap = A + (long long)(m/P)*GS + (long long)(m%P)*RS;
    float4 v = *(const float4*)(ap + 4*cq);
    uint32_t* dst = (uint32_t*)(As + r*GAS + 4*cq);
    dst[0] = bf2(v.x, v.y);
    dst[1] = bf2(v.z, v.w);
  }
  {
    const uint4* src = (const uint4*)Bpk;
    uint4* dst = (uint4*)Bp;
    #pragma unroll
    for (int it = 0; it < 8; ++it) {
      int f = it*256 + tid;               // 2048 uint4
      int k16 = f >> 8, rem = f & 255;
      dst[f] = src[((long long)k16*Ntp + tp0)*32 + rem];
    }
  }
  __syncthreads();

  float acc[2][4][4];
  #pragma unroll
  for (int mt=0;mt<2;mt++)
    #pragma unroll
    for (int nt=0;nt<4;nt++)
      #pragma unroll
      for (int q=0;q<4;q++) acc[mt][nt][q] = 0.f;

  const uint32_t asb = cvta_s(As);
  const uint4* bp4 = (const uint4*)Bp;
  #pragma unroll
  for (int k16 = 0; k16 < 8; ++k16) {
    uint32_t a[2][4];
    #pragma unroll
    for (int mt=0;mt<2;mt++)
      ldsm4(a[mt], asb + ((wm*32 + mt*16 + (lane & 15))*GAS + k16*16 + ((lane >> 4) << 3))*2);
    uint4 b40 = bp4[(k16*8 + wn*2    )*32 + lane];
    uint4 b41 = bp4[(k16*8 + wn*2 + 1)*32 + lane];
    uint32_t bb[4][2];
    bb[0][0]=b40.x; bb[0][1]=b40.y; bb[1][0]=b40.z; bb[1][1]=b40.w;
    bb[2][0]=b41.x; bb[2][1]=b41.y; bb[3][0]=b41.z; bb[3][1]=b41.w;
    #pragma unroll
    for (int mt=0;mt<2;mt++)
      #pragma unroll
      for (int nt=0;nt<4;nt++)
        mma16(acc[mt][nt], a[mt], bb[nt]);
  }
  if (obf) {
    // stage C tile (bf16) in SMEM, then coalesced stores
    __syncthreads();                       // done reading As
    uint32_t* Cs = (uint32_t*)smc;         // 64 x 65 u32 (16640 B, fits in As area)
    #pragma unroll
    for (int mt=0;mt<2;mt++) {
      int row0 = wm*32 + mt*16 + g;
      #pragma unroll
      for (int nt=0;nt<4;nt++) {
        int col = wn*32 + nt*8 + 2*t4;
        float bc0 = bias[c0+col], bc1 = bias[c0+col+1];
        #pragma unroll
        for (int h=0; h<2; ++h) {
          int row = row0 + 8*h;
          Cs[row*65 + (col >> 1)] = bf2(acc[mt][nt][2*h+0] + bc0, acc[mt][nt][2*h+1] + bc1);
        }
      }
    }
    __syncthreads();
    #pragma unroll
    for (int it = 0; it < 16; ++it) {
      int f = it*256 + tid;                // 4096 u32, 64 per row
      int r = f >> 6, q = f & 63;
      *(uint32_t*)((__nv_bfloat16*)C + (long long)(m0+r)*ldc + c0 + 2*q) = Cs[r*65 + q];
    }
  } else {
    #pragma unroll
    for (int mt=0;mt<2;mt++) {
      int row0 = m0 + wm*32 + mt*16 + g;
      #pragma unroll
      for (int nt=0;nt<4;nt++) {
        int col = c0 + wn*32 + nt*8 + 2*t4;
        float bc0 = bias[col], bc1 = bias[col+1];
        #pragma unroll
        for (int h=0; h<2; ++h) {
          int row = row0 + 8*h;
          float2 o = {acc[mt][nt][2*h+0] + bc0, acc[mt][nt][2*h+1] + bc1};
          *(float2*)((float*)C + (long long)row*ldc + col) = o;
        }
      }
    }
  }
}

// -------------------- GRU scan, bf16 TC, staged I/O (32 rows/CTA) --------------------
#define A_STRIDE 136
#define A_BUF    (32*A_STRIDE)      // bf16 per Ab buffer
#define XS_STRIDE 392               // bf16
#define XS_BUF   (32*XS_STRIDE)     // bf16 per Xs buffer
#define HS_BUF   (32*132)           // fp32 per Hs buffer
// smem: Bp[98304] Ab[34816] Xs[50176] Hs[33792]  = 217088 B
__global__ __launch_bounds__(256, 1)
void gru_scan_mma(const __nv_bfloat16* __restrict__ Xp, const uint32_t* __restrict__ Bpack,
                  const float* __restrict__ brec, float* __restrict__ hs) {
  extern __shared__ char smc[];
  uint32_t* Bp = (uint32_t*)smc;
  __nv_bfloat16* Ab = (__nv_bfloat16*)(smc + 98304);
  __nv_bfloat16* Xs = (__nv_bfloat16*)(smc + 98304 + 34816);
  float* Hs = (float*)(smc + 98304 + 34816 + 50176);
  const int tid = threadIdx.x;    // 256
  const int w = tid >> 5, lane = tid & 31;
  const int g = lane >> 2, t4 = lane & 3;
  const int b0 = blockIdx.x * 32;
  #pragma unroll
  for (int it = 0; it < 24; ++it)
    ((float4*)Bp)[it*256 + tid] = ((const float4*)Bpack)[it*256 + tid];
  for (int i = tid; i < A_BUF; i += 256) ((uint32_t*)Ab)[i] = 0u;
  // stage x(0) into Xs buf 0
  #pragma unroll
  for (int it = 0; it < 6; ++it) {
    int f = it*256 + tid;
    int r = f / 48, q = f % 48;
    uint4 v = *(const uint4*)(Xp + ((long long)(b0+r)*T + 0)*N3 + q*8);
    *(uint4*)(Xs + r*XS_STRIDE + q*8) = v;
  }
  float2 bz[2], brr[2], bh[2];
  #pragma unroll
  for (int nt=0; nt<2; ++nt) {
    int c = (2*w+nt)*8 + 2*t4;
    bz[nt]  = *(const float2*)(brec + c);
    brr[nt] = *(const float2*)(brec + 128 + c);
    bh[nt]  = *(const float2*)(brec + 256 + c);
  }
  float h[2][2][2][2];
  #pragma unroll
  for (int a1=0;a1<2;a1++)
    #pragma unroll
    for (int a2=0;a2<2;a2++)
      #pragma unroll
      for (int a3=0;a3<2;a3++) { h[a1][a2][a3][0]=0.f; h[a1][a2][a3][1]=0.f; }
  const uint32_t abb = cvta_s(Ab);
  __syncthreads();

  for (int t = 0; t < T; ++t) {
    // prefetch-stage x(t+1) into other buffer (lands by next barrier)
    if (t + 1 < T) {
      __nv_bfloat16* Xw = Xs + ((t+1) & 1) * XS_BUF;
      #pragma unroll
      for (int it = 0; it < 6; ++it) {
        int f = it*256 + tid;
        int r = f / 48, q = f % 48;
        uint4 v = *(const uint4*)(Xp + ((long long)(b0+r)*T + t+1)*N3 + q*8);
        *(uint4*)(Xw + r*XS_STRIDE + q*8) = v;
      }
    }
    // coalesced store of hs(t-1)
    if (t >= 1) {
      const float* Hr = Hs + ((t-1) & 1) * HS_BUF;
      #pragma unroll
      for (int it = 0; it < 4; ++it) {
        int f = it*256 + tid;
        int r = f >> 5, q = f & 31;
        float4 v = *(const float4*)(Hr + r*132 + q*4);
        *(float4*)(hs + ((long long)(b0+r)*T + (t-1))*128 + q*4) = v;
      }
    }
    const __nv_bfloat16* Xc = Xs + (t & 1) * XS_BUF;
    const uint32_t arb = abb + (uint32_t)((t & 1) * A_BUF * 2);
    __nv_bfloat16* Aw = Ab + ((t & 1) ^ 1) * A_BUF;
    float* Hw = Hs + (t & 1) * HS_BUF;
    float2 xz[2][2][2], xr[2][2][2], xh[2][2][2];
    #pragma unroll
    for (int mt=0;mt<2;mt++)
      #pragma unroll
      for (int rh=0;rh<2;rh++) {
        const __nv_bfloat16* xp = Xc + (mt*16 + rh*8 + g)*XS_STRIDE + 2*t4;
        #pragma unroll
        for (int nt=0;nt<2;nt++) {
          int c = (2*w+nt)*8;
          xz[mt][rh][nt] = bf2f(*(const uint32_t*)(xp + c));
          xr[mt][rh][nt] = bf2f(*(const uint32_t*)(xp + 128 + c));
          xh[mt][rh][nt] = bf2f(*(const uint32_t*)(xp + 256 + c));
        }
      }
    float acc[2][6][4];
    #pragma unroll
    for (int mt=0;mt<2;mt++)
      #pragma unroll
      for (int j=0;j<6;j++)
        #pragma unroll
        for (int q=0;q<4;q++) acc[mt][j][q] = 0.f;
    #pragma unroll
    for (int k16=0;k16<8;++k16) {
      uint32_t a[2][4];
      #pragma unroll
      for (int mt=0;mt<2;mt++)
        ldsm4(a[mt], arb + ((mt*16 + (lane & 15))*A_STRIDE + k16*16 + ((lane >> 4) << 3))*2);
      uint4 bv0 = ((const uint4*)Bp)[(k16*24 +      w)*32 + lane];
      uint4 bv1 = ((const uint4*)Bp)[(k16*24 +  8 + w)*32 + lane];
      uint4 bv2 = ((const uint4*)Bp)[(k16*24 + 16 + w)*32 + lane];
      uint32_t bb[6][2];
      bb[0][0]=bv0.x; bb[0][1]=bv0.y; bb[1][0]=bv0.z; bb[1][1]=bv0.w;
      bb[2][0]=bv1.x; bb[2][1]=bv1.y; bb[3][0]=bv1.z; bb[3][1]=bv1.w;
      bb[4][0]=bv2.x; bb[4][1]=bv2.y; bb[5][0]=bv2.z; bb[5][1]=bv2.w;
      #pragma unroll
      for (int mt=0;mt<2;mt++)
        #pragma unroll
        for (int j=0;j<6;j++)
          mma16(acc[mt][j], a[mt], bb[j]);
    }
    #pragma unroll
    for (int mt=0;mt<2;mt++)
      #pragma unroll
      for (int rh=0;rh<2;rh++) {
        int row = mt*16 + rh*8 + g;
        #pragma unroll
        for (int nt=0;nt<2;nt++) {
          int c = (2*w+nt)*8 + 2*t4;
          float hn0, hn1;
          {
            float z  = sigt(xz[mt][rh][nt].x + acc[mt][nt][rh*2]     + bz[nt].x);
            float r  = sigt(xr[mt][rh][nt].x + acc[mt][2+nt][rh*2]   + brr[nt].x);
            float hc = tanha(xh[mt][rh][nt].x + r*(acc[mt][4+nt][rh*2] + bh[nt].x));
            float ho = h[mt][rh][nt][0];
            hn0 = z*ho + (1.f - z)*hc;
            h[mt][rh][nt][0] = hn0;
          }
          {
            float z  = sigt(xz[mt][rh][nt].y + acc[mt][nt][rh*2+1]     + bz[nt].y);
            float r  = sigt(xr[mt][rh][nt].y + acc[mt][2+nt][rh*2+1]   + brr[nt].y);
            float hc = tanha(xh[mt][rh][nt].y + r*(acc[mt][4+nt][rh*2+1] + bh[nt].y));
            float ho = h[mt][rh][nt][1];
            hn1 = z*ho + (1.f - z)*hc;
            h[mt][rh][nt][1] = hn1;
          }
          float2 o = {hn0, hn1};
          *(float2*)(Hw + row*132 + c) = o;
          *(uint32_t*)(Aw + row*A_STRIDE + c) = bf2(hn0, hn1);
        }
      }
    __syncthreads();
  }
  { // final hs(T-1) store
    const float* Hr = Hs + ((T-1) & 1) * HS_BUF;
    #pragma unroll
    for (int it = 0; it < 4; ++it) {
      int f = it*256 + tid;
      int r = f >> 5, q = f & 31;
      float4 v = *(const float4*)(Hr + r*132 + q*4);
      *(float4*)(hs + ((long long)(b0+r)*T + (T-1))*128 + q*4) = v;
    }
  }
}

// -------------------- AUGRU scan, bf16 TC, staged x (32 rows/CTA) --------------------
// smem: Bp[98304] Ab[34816] Xs[50176] ats[256] = 183552 B
__global__ __launch_bounds__(256, 1)
void augru_scan_mma(const __nv_bfloat16* __restrict__ X3, const uint32_t* __restrict__ Bpack) {
  extern __shared__ char smc[];
  uint32_t* Bp = (uint32_t*)smc;
  __nv_bfloat16* Ab = (__nv_bfloat16*)(smc + 98304);
  __nv_bfloat16* Xs = (__nv_bfloat16*)(smc + 98304 + 34816);
  float* ats_s = (float*)(smc + 98304 + 34816 + 50176);   // 2 x 32
  const int tid = threadIdx.x;
  const int w = tid >> 5, lane = tid & 31;
  const int g = lane >> 2, t4 = lane & 3;
  const int b0 = blockIdx.x * 32;
  #pragma unroll
  for (int it = 0; it < 24; ++it)
    ((float4*)Bp)[it*256 + tid] = ((const float4*)Bpack)[it*256 + tid];
  for (int i = tid; i < A_BUF; i += 256) ((uint32_t*)Ab)[i] = 0u;
  #pragma unroll
  for (int it = 0; it < 6; ++it) {
    int f = it*256 + tid;
    int r = f / 48, q = f % 48;
    uint4 v = *(const uint4*)(X3 + ((long long)(b0+r)*T + 0)*N3 + q*8);
    *(uint4*)(Xs + r*XS_STRIDE + q*8) = v;
  }
  if (tid < 32) ats_s[tid] = g_ats[(long long)(b0+tid)*T + 0];
  float h[2][2][2][2];
  #pragma unroll
  for (int a1=0;a1<2;a1++)
    #pragma unroll
    for (int a2=0;a2<2;a2++)
      #pragma unroll
      for (int a3=0;a3<2;a3++) { h[a1][a2][a3][0]=0.f; h[a1][a2][a3][1]=0.f; }
  const uint32_t abb = cvta_s(Ab);
  __syncthreads();

  for (int t = 0; t < T; ++t) {
    if (t + 1 < T) {
      __nv_bfloat16* Xw = Xs + ((t+1) & 1) * XS_BUF;
      #pragma unroll
      for (int it = 0; it < 6; ++it) {
        int f = it*256 + tid;
        int r = f / 48, q = f % 48;
        uint4 v = *(const uint4*)(X3 + ((long long)(b0+r)*T + t+1)*N3 + q*8);
        *(uint4*)(Xw + r*XS_STRIDE + q*8) = v;
      }
      if (tid < 32) ats_s[((t+1)&1)*32 + tid] = g_ats[(long long)(b0+tid)*T + t+1];
    }
    const __nv_bfloat16* Xc = Xs + (t & 1) * XS_BUF;
    const float* atc = ats_s + (t & 1) * 32;
    const uint32_t arb = abb + (uint32_t)((t & 1) * A_BUF * 2);
    __nv_bfloat16* Aw = Ab + ((t & 1) ^ 1) * A_BUF;
    float2 xu[2][2][2], xr[2][2][2], xc[2][2][2];
    float at[2][2];
    #pragma unroll
    for (int mt=0;mt<2;mt++)
      #pragma unroll
      for (int rh=0;rh<2;rh++) {
        at[mt][rh] = atc[mt*16 + rh*8 + g];
        const __nv_bfloat16* xp = Xc + (mt*16 + rh*8 + g)*XS_STRIDE + 2*t4;
        #pragma unroll
        for (int nt=0;nt<2;nt++) {
          int c = (2*w+nt)*8;
          xu[mt][rh][nt] = bf2f(*(const uint32_t*)(xp + c));
          xr[mt][rh][nt] = bf2f(*(const uint32_t*)(xp + 128 + c));
          xc[mt][rh][nt] = bf2f(*(const uint32_t*)(xp + 256 + c));
        }
      }
    float acc[2][6][4];
    #pragma unroll
    for (int mt=0;mt<2;mt++)
      #pragma unroll
      for (int j=0;j<6;j++)
        #pragma unroll
        for (int q=0;q<4;q++) acc[mt][j][q] = 0.f;
    #pragma unroll
    for (int k16=0;k16<8;++k16) {
      uint32_t a[2][4];
      #pragma unroll
      for (int mt=0;mt<2;mt++)
        ldsm4(a[mt], arb + ((mt*16 + (lane & 15))*A_STRIDE + k16*16 + ((lane >> 4) << 3))*2);
      uint4 bv0 = ((const uint4*)Bp)[(k16*24 +      w)*32 + lane];
      uint4 bv1 = ((const uint4*)Bp)[(k16*24 +  8 + w)*32 + lane];
      uint4 bv2 = ((const uint4*)Bp)[(k16*24 + 16 + w)*32 + lane];
      uint32_t bb[6][2];
      bb[0][0]=bv0.x; bb[0][1]=bv0.y; bb[1][0]=bv0.z; bb[1][1]=bv0.w;
      bb[2][0]=bv1.x; bb[2][1]=bv1.y; bb[3][0]=bv1.z; bb[3][1]=bv1.w;
      bb[4][0]=bv2.x; bb[4][1]=bv2.y; bb[5][0]=bv2.z; bb[5][1]=bv2.w;
      #pragma unroll
      for (int mt=0;mt<2;mt++)
        #pragma unroll
        for (int j=0;j<6;j++)
          mma16(acc[mt][j], a[mt], bb[j]);
    }
    #pragma unroll
    for (int mt=0;mt<2;mt++)
      #pragma unroll
      for (int rh=0;rh<2;rh++) {
        int row = mt*16 + rh*8 + g;
        float atv = at[mt][rh];
        #pragma unroll
        for (int nt=0;nt<2;nt++) {
          int c = (2*w+nt)*8 + 2*t4;
          float hn0, hn1;
          {
            float u  = sigt(xu[mt][rh][nt].x + acc[mt][nt][rh*2]);
            float r  = sigt(xr[mt][rh][nt].x + acc[mt][2+nt][rh*2]);
            float cc = tanha(xc[mt][rh][nt].x + r*acc[mt][4+nt][rh*2]);
            float uu = atv*u;
            float ho = h[mt][rh][nt][0];
            hn0 = (1.f - uu)*ho + uu*cc;
            h[mt][rh][nt][0] = hn0;
          }
          {
            float u  = sigt(xu[mt][rh][nt].y + acc[mt][nt][rh*2+1]);
            float r  = sigt(xr[mt][rh][nt].y + acc[mt][2+nt][rh*2+1]);
            float cc = tanha(xc[mt][rh][nt].y + r*acc[mt][4+nt][rh*2+1]);
            float uu = atv*u;
            float ho = h[mt][rh][nt][1];
            hn1 = (1.f - uu)*ho + uu*cc;
            h[mt][rh][nt][1] = hn1;
          }
          *(uint32_t*)(Aw + row*A_STRIDE + c) = bf2(hn0, hn1);
        }
      }
    __syncthreads();
  }
  #pragma unroll
  for (int mt=0;mt<2;mt++)
    #pragma unroll
    for (int rh=0;rh<2;rh++) {
      int row = mt*16 + rh*8 + g;
      #pragma unroll
      for (int nt=0;nt<2;nt++) {
        int c = (2*w+nt)*8 + 2*t4;
        float2 o = {h[mt][rh][nt][0], h[mt][rh][nt][1]};
        *(float2*)(g_hfin + (long long)(b0+row)*128 + c) = o;
      }
    }
}

// ------------- fused attention (bf16): hs,news -> a1 -> a2 -> ats -------------
#define ATT_AS 264   // As stride (bf16)
__global__ __launch_bounds__(256, 1)
void att_fused(const float* __restrict__ hs, const float* __restrict__ inputs,
               const uint32_t* __restrict__ Wcatp, const uint32_t* __restrict__ W2p,
               const float* __restrict__ b2, const float* __restrict__ W3,
               const float* __restrict__ b3, const float* __restrict__ nterm) {
  extern __shared__ char smc[];
  __nv_bfloat16* As  = (__nv_bfloat16*)smc;            // 64 x 264        (33792 B)
  uint32_t* Wc  = (uint32_t*)(smc + 33792);            // 16384 u32       (65536 B)
  __nv_bfloat16* a1s = (__nv_bfloat16*)(smc + 99328);  // 64 x 136        (17408 B)
  uint32_t* W2s = (uint32_t*)(smc + 116736);           // 4096 u32        (16384 B)
  float* a2s = (float*)(smc + 133120);                 // 64 x 68         (17408 B)
  float* W3s = (float*)(smc + 150528);                 // 64
  const int tid = threadIdx.x;     // 256
  const int lane = tid & 31, wid = tid >> 5;
  const int wm = wid & 1, wn = wid >> 1;
  const int wm3 = wid & 3, wn3 = wid >> 2;
  const int g = lane >> 2, t4 = lane & 3;
  const float b3v = b3[0];

  {
    const uint4* src = (const uint4*)Wcatp;
    uint4* dst = (uint4*)Wc;
    #pragma unroll
    for (int it = 0; it < 16; ++it) dst[it*256 + tid] = src[it*256 + tid];
    const uint4* src2 = (const uint4*)W2p;
    uint4* dst2 = (uint4*)W2s;
    #pragma unroll
    for (int it = 0; it < 4; ++it) dst2[it*256 + tid] = src2[it*256 + tid];
    if (tid < 64) W3s[tid] = W3[tid];
  }
  const uint32_t asb = cvta_s(As);
  const uint32_t a1b = cvta_s(a1s);
  const uint4* Wc4 = (const uint4*)Wc;
  const uint4* W2p4 = (const uint4*)W2s;

  for (long long blk = blockIdx.x; blk < BT/64; blk += gridDim.x) {
    const long long m0 = blk * 64;
    __syncthreads();
    #pragma unroll
    for (int it = 0; it < 16; ++it) {
      int idx = it*256 + tid;
      int r = idx >> 6, q = idx & 63;
      long long row = m0 + r;
      int b = (int)(row / T);
      if (q < 32) {
        float4 hv = *(const float4*)(hs + row*128 + 4*q);
        uint32_t* dst = (uint32_t*)(As + r*ATT_AS + 4*q);
        dst[0] = bf2(hv.x, hv.y);
        dst[1] = bf2(hv.z, hv.w);
      } else {
        int qq = q - 32;
        float4 hv = *(const float4*)(hs + row*128 + 4*qq);
        float4 nw = *(const float4*)(inputs + ((long long)b*(T+1) + T)*128 + 4*qq);
        uint32_t* dst = (uint32_t*)(As + r*ATT_AS + 128 + 4*qq);
        dst[0] = bf2(hv.x*nw.x, hv.y*nw.y);
        dst[1] = bf2(hv.z*nw.z, hv.w*nw.w);
      }
    }
    __syncthreads();
    float acc[2][4][4];
    #pragma unroll
    for (int mt=0;mt<2;mt++)
      #pragma unroll
      for (int nt=0;nt<4;nt++)
        #pragma unroll
        for (int q=0;q<4;q++) acc[mt][nt][q] = 0.f;
    #pragma unroll
    for (int k16 = 0; k16 < 16; ++k16) {
      uint32_t a[2][4];
      #pragma unroll
      for (int mt=0;mt<2;mt++)
        ldsm4(a[mt], asb + ((wm*32 + mt*16 + (lane & 15))*ATT_AS + k16*16 + ((lane >> 4) << 3))*2);
      uint4 b40 = Wc4[(k16*8 + wn*2    )*32 + lane];
      uint4 b41 = Wc4[(k16*8 + wn*2 + 1)*32 + lane];
      uint32_t bb[4][2];
      bb[0][0]=b40.x; bb[0][1]=b40.y; bb[1][0]=b40.z; bb[1][1]=b40.w;
      bb[2][0]=b41.x; bb[2][1]=b41.y; bb[3][0]=b41.z; bb[3][1]=b41.w;
      #pragma unroll
      for (int mt=0;mt<2;mt++)
        #pragma unroll
        for (int nt=0;nt<4;nt++)
          mma16(acc[mt][nt], a[mt], bb[nt]);
    }
    #pragma unroll
    for (int mt=0;mt<2;mt++) {
      int row0 = wm*32 + mt*16 + g;
      #pragma unroll
      for (int nt=0;nt<4;nt++) {
        int col = wn*32 + nt*8 + 2*t4;
        #pragma unroll
        for (int h=0; h<2; ++h) {
          int row = row0 + 8*h;
          long long rowg = m0 + row;
          const float* np = nterm + (long long)(rowg / T)*128;
          float v0 = fmaxf(acc[mt][nt][2*h+0] + np[col],   0.f);
          float v1 = fmaxf(acc[mt][nt][2*h+1] + np[col+1], 0.f);
          *(uint32_t*)(a1s + row*A_STRIDE + col) = bf2(v0, v1);
        }
      }
    }
    __syncthreads();
    {
      float acc2[4][4];
      #pragma unroll
      for (int nt=0;nt<4;nt++)
        #pragma unroll
        for (int q=0;q<4;q++) acc2[nt][q] = 0.f;
      #pragma unroll
      for (int k16 = 0; k16 < 8; ++k16) {
        uint32_t a[4];
        ldsm4(a, a1b + ((wm3*16 + (lane & 15))*A_STRIDE + k16*16 + ((lane >> 4) << 3))*2);
        uint4 b40 = W2p4[(k16*4 + wn3*2    )*32 + lane];
        uint4 b41 = W2p4[(k16*4 + wn3*2 + 1)*32 + lane];
        uint32_t bb[4][2];
        bb[0][0]=b40.x; bb[0][1]=b40.y; bb[1][0]=b40.z; bb[1][1]=b40.w;
        bb[2][0]=b41.x; bb[2][1]=b41.y; bb[3][0]=b41.z; bb[3][1]=b41.w;
        #pragma unroll
        for (int nt=0;nt<4;nt++)
          mma16(acc2[nt], a, bb[nt]);
      }
      #pragma unroll
      for (int nt=0;nt<4;nt++) {
        int col = wn3*32 + nt*8 + 2*t4;
        float bc0 = b2[col], bc1 = b2[col+1];
        #pragma unroll
        for (int h=0; h<2; ++h) {
          int row = wm3*16 + g + 8*h;
          a2s[row*68 + col]     = fmaxf(acc2[nt][2*h+0] + bc0, 0.f);
          a2s[row*68 + col + 1] = fmaxf(acc2[nt][2*h+1] + bc1, 0.f);
        }
      }
    }
    __syncthreads();
    if (tid < 64) {
      float accv = b3v;
      #pragma unroll 8
      for (int cc=0; cc<64; ++cc) accv = fmaf(a2s[tid*68 + cc], W3s[cc], accv);
      g_ats[m0 + tid] = sigf(accv);
    }
  }
}

// ------------------------------ head ------------------------------
__global__ void head_kernel(const float* __restrict__ inputs,
                            const float* __restrict__ gamma, const float* __restrict__ beta,
                            const float* __restrict__ mean,  const float* __restrict__ var,
                            const float* __restrict__ W1, const float* __restrict__ bb1,
                            const float* __restrict__ W2, const float* __restrict__ bb2,
                            const float* __restrict__ fW, const float* __restrict__ fb,
                            float* __restrict__ out) {
  extern __shared__ float sm[];
  float* xs  = sm;          // 32*256
  float* y1s = xs + 8192;   // 32*256
  float* y2s = y1s + 8192;  // 32*128
  const int tid = threadIdx.x;   // 256
  const int b0 = blockIdx.x * 32;
  for (int r = 0; r < 32; ++r) {
    int k = tid;
    int bb = b0 + r;
    float v = (k < 128) ? g_hfin[bb*128 + k]
                        : inputs[((long long)bb*(T+1) + T)*128 + (k - 128)];
    float nv = (v - mean[k]) * rsqrtf(var[k] + BN_EPS) * gamma[k] + beta[k];
    xs[r*256 + k] = nv;
  }
  __syncthreads();
  {
    float acc[32];
    #pragma unroll
    for (int r=0;r<32;r++) acc[r] = bb1[tid];
    for (int k=0;k<256;++k) {
      float w = W1[k*256 + tid];
      #pragma unroll
      for (int r=0;r<32;r++) acc[r] = fmaf(xs[r*256+k], w, acc[r]);
    }
    #pragma unroll
    for (int r=0;r<32;r++) {
      float v = acc[r];
      y1s[r*256 + tid] = v >= 0.f ? v : LEAKY*v;
    }
  }
  __syncthreads();
  if (tid < 128) {
    float acc[32];
    #pragma unroll
    for (int r=0;r<32;r++) acc[r] = bb2[tid];
    for (int k=0;k<256;++k) {
      float w = W2[k*128 + tid];
      #pragma unroll
      for (int r=0;r<32;r++) acc[r] = fmaf(y1s[r*256+k], w, acc[r]);
    }
    #pragma unroll
    for (int r=0;r<32;r++) {
      float v = acc[r];
      y2s[r*128 + tid] = v >= 0.f ? v : LEAKY*v;
    }
  }
  __syncthreads();
  if (tid < 32) {
    float acc = fb[0];
    for (int k=0;k<128;++k) acc = fmaf(y2s[tid*128+k], fW[k], acc);
    out[b0 + tid] = sigf(acc);
  }
}

// ------------------------------ launch ------------------------------
extern "C" void kernel_launch(void* const* d_in, const int* in_sizes, int n_in,
                              void* d_out, int out_size) {
  (void)in_sizes; (void)n_in; (void)out_size;
  const float* inputs  = (const float*)d_in[0];
  const float* gru_W   = (const float*)d_in[1];
  const float* gru_U   = (const float*)d_in[2];
  const float* gru_b   = (const float*)d_in[3];
  const float* att_W1  = (const float*)d_in[4];
  const float* att_b1  = (const float*)d_in[5];
  const float* att_W2  = (const float*)d_in[6];
  const float* att_b2  = (const float*)d_in[7];
  const float* att_W3  = (const float*)d_in[8];
  const float* att_b3  = (const float*)d_in[9];
  const float* au_Wu   = (const float*)d_in[10];
  const float* au_bu   = (const float*)d_in[11];
  const float* au_Uu   = (const float*)d_in[12];
  const float* au_Wr   = (const float*)d_in[13];
  const float* au_br   = (const float*)d_in[14];
  const float* au_Ur   = (const float*)d_in[15];
  const float* au_Wc   = (const float*)d_in[16];
  const float* au_bc   = (const float*)d_in[17];
  const float* au_Uc   = (const float*)d_in[18];
  const float* bn_gamma= (const float*)d_in[19];
  const float* bn_beta = (const float*)d_in[20];
  const float* bn_mean = (const float*)d_in[21];
  const float* bn_var  = (const float*)d_in[22];
  const float* d_W1    = (const float*)d_in[23];
  const float* d_b1    = (const float*)d_in[24];
  const float* d_W2    = (const float*)d_in[25];
  const float* d_b2    = (const float*)d_in[26];
  const float* f_W     = (const float*)d_in[27];
  const float* f_b     = (const float*)d_in[28];
  float* out = (float*)d_out;

  const size_t sm_gemm  = 64*GAS*2 + 8192*4;                 // 50176
  const size_t sm_gru   = 98304 + 34816 + 50176 + 33792;     // 217088
  const size_t sm_au    = 98304 + 34816 + 50176 + 256;       // 183552
  const size_t sm_attf  = 150784;
  const size_t sm_head  = (8192*2 + 4096)*sizeof(float);
  cudaFuncSetAttribute(gemm_bf16,      cudaFuncAttributeMaxDynamicSharedMemorySize, (int)sm_gemm);
  cudaFuncSetAttribute(gru_scan_mma,   cudaFuncAttributeMaxDynamicSharedMemorySize, (int)sm_gru);
  cudaFuncSetAttribute(augru_scan_mma, cudaFuncAttributeMaxDynamicSharedMemorySize, (int)sm_au);
  cudaFuncSetAttribute(att_fused,      cudaFuncAttributeMaxDynamicSharedMemorySize, (int)sm_attf);
  cudaFuncSetAttribute(head_kernel,    cudaFuncAttributeMaxDynamicSharedMemorySize, (int)sm_head);

  float *p_Xp, *p_hs, *p_X3, *p_newsterm, *p_bau;
  uint32_t *p_Ubg, *p_Uba, *p_WbgW, *p_Wbau, *p_Wb1bc, *p_Wbcat, *p_Wbatt2;
  cudaGetSymbolAddress((void**)&p_Xp,       g_Xp);
  cudaGetSymbolAddress((void**)&p_hs,       g_hs);
  cudaGetSymbolAddress((void**)&p_X3,       g_X3);
  cudaGetSymbolAddress((void**)&p_newsterm, g_newsterm);
  cudaGetSymbolAddress((void**)&p_bau,      g_bau);
  cudaGetSymbolAddress((void**)&p_Ubg,      g_Ubf_gru);
  cudaGetSymbolAddress((void**)&p_Uba,      g_Ubf_au);
  cudaGetSymbolAddress((void**)&p_WbgW,     g_Wb_gruW);
  cudaGetSymbolAddress((void**)&p_Wbau,     g_Wb_au);
  cudaGetSymbolAddress((void**)&p_Wb1bc,    g_Wb_1bc);
  cudaGetSymbolAddress((void**)&p_Wbcat,    g_Wb_cat);
  cudaGetSymbolAddress((void**)&p_Wbatt2,   g_Wb_att2);

  cudaStream_t s2;
  cudaStreamCreateWithFlags(&s2, cudaStreamNonBlocking);
  cudaEvent_t evPack, evNews, evFork, evJoin;
  cudaEventCreateWithFlags(&evPack, cudaEventDisableTiming);
  cudaEventCreateWithFlags(&evNews, cudaEventDisableTiming);
  cudaEventCreateWithFlags(&evFork, cudaEventDisableTiming);
  cudaEventCreateWithFlags(&evJoin, cudaEventDisableTiming);

  // 1) fold weights, then all bf16 fragment packs
  prep_kernel<<<192, 256>>>(au_Wu, au_bu, au_Wr, au_br, au_Wc, au_bc,
                            au_Uu, au_Ur, au_Uc, att_W1);
  pack_all<<<496, 256>>>(gru_U, gru_W, att_W2);
  cudaEventRecord(evPack, 0);
  cudaStreamWaitEvent(s2, evPack, 0);
  // 2) newsterm = news @ (W1B+W1C) + b1  (side stream; fp32 out)
  gemm_bf16<<<dim3(B/64, 1), 256, sm_gemm, s2>>>(inputs + (long long)T*128, 1, (long long)(T+1)*128, 128,
                                                 p_Wb1bc, 8, att_b1, p_newsterm, 128, 0);
  cudaEventRecord(evNews, s2);
  // 3) Xp = hist @ gru_W + gru_b[0]   (bf16 out, staged stores)
  gemm_bf16<<<dim3(BT/64, 3), 256, sm_gemm>>>(inputs, T, (long long)(T+1)*128, 128,
                                              p_WbgW, 24, gru_b, p_Xp, 384, 1);
  // 4) GRU recurrence -> hs
  gru_scan_mma<<<B/32, 256, sm_gru>>>((const __nv_bfloat16*)p_Xp, p_Ubg, gru_b + 384, p_hs);
  // fork: X3 gemm on s2, attention on main stream
  cudaEventRecord(evFork, 0);
  cudaStreamWaitEvent(s2, evFork, 0);
  // 5) X3 = hs @ [Wu|Wr|Wc] + [bu|br|bc]   (side stream; bf16 out)
  gemm_bf16<<<dim3(BT/64, 3), 256, sm_gemm, s2>>>(p_hs, 1<<30, 0LL, 128,
                                                  p_Wbau, 24, p_bau, p_X3, 384, 1);
  cudaEventRecord(evJoin, s2);
  // 6) fused attention -> g_ats  (main stream; needs newsterm)
  cudaStreamWaitEvent(0, evNews, 0);
  att_fused<<<148, 256, sm_attf>>>(p_hs, inputs, p_Wbcat, p_Wbatt2,
                                   att_b2, att_W3, att_b3, p_newsterm);
  cudaStreamWaitEvent(0, evJoin, 0);
  // 7) AUGRU recurrence -> hfin
  augru_scan_mma<<<B/32, 256, sm_au>>>((const __nv_bfloat16*)p_X3, p_Uba);
  // 8) BN + dense head -> out
  head_kernel<<<B/32, 256, sm_head>>>(inputs, bn_gamma, bn_beta, bn_mean, bn_var,
                                      d_W1, d_b1, d_W2, d_b2, f_W, f_b, out);
}

// round 12
// speedup vs baseline: 1.4862x; 1.1549x over previous
#include <cuda_runtime.h>
#include <cuda_bf16.h>
#include <math.h>
#include <stdint.h>

#define B  4096
#define T  50
#define U  128
#define N3 384
#define BT (B*T)
#define BN_EPS 1e-3f
#define LEAKY  3e-4f

// ------------ scratch (device globals; no allocation allowed) ------------
__device__ float g_Xp[BT*N3];            // GRU input projection (bf16 payload)
__device__ __nv_bfloat16 g_hsb[BT*U];    // GRU hidden states (bf16)
__device__ float g_X3[BT*N3];            // AUGRU input projections (bf16 payload)
__device__ float g_ats[BT];              // attention scores
__device__ float g_hfin[B*U];            // AUGRU final state
__device__ float g_newsterm[B*U];        // news@(W1B+W1C)+b1
__device__ float g_Wau[U*N3];            // packed input  [Wu|Wr|Wc]
__device__ float g_Uau[U*N3];            // packed recur  [Uu|Ur|Uc]
__device__ float g_bau[N3];              // packed [bu|br|bc]
__device__ float g_Wcat[2*U*U];          // [W1A-W1B ; W1D]  (256 x 128)
__device__ float g_W1bc[U*U];            // W1B + W1C
__device__ uint32_t g_Ubf_gru[24576];    // bf16 frag gru_U
__device__ uint32_t g_Ubf_au[24576];     // bf16 frag [Uu|Ur|Uc]
__device__ uint32_t g_Wb_gruW[24576];    // bf16 frag gru_W     (K=128,N=384)
__device__ uint32_t g_Wb_au[24576];      // bf16 frag [Wu|Wr|Wc]
__device__ uint32_t g_Wb_1bc[8192];      // bf16 frag W1B+W1C   (K=128,N=128)
__device__ uint32_t g_Wb_cat[16384];     // bf16 frag Wcat      (K=256,N=128)
__device__ uint32_t g_Wb_att2[4096];     // bf16 frag att_W2    (K=128,N=64)

__device__ __forceinline__ float sigf(float x){ return 1.f/(1.f+expf(-x)); }
__device__ __forceinline__ float tanha(float x){
  float y; asm("tanh.approx.f32 %0, %1;" : "=f"(y) : "f"(x)); return y;
}
__device__ __forceinline__ float sigt(float x){ return fmaf(tanha(0.5f*x), 0.5f, 0.5f); }
__device__ __forceinline__ uint32_t bf2(float lo, float hi){
  __nv_bfloat162 v;
  v.x = __float2bfloat16(lo); v.y = __float2bfloat16(hi);
  return *(uint32_t*)&v;
}
__device__ __forceinline__ float2 bf2f(uint32_t u){
  __nv_bfloat162 v = *(__nv_bfloat162*)&u;
  return __bfloat1622float2(v);
}
__device__ __forceinline__ uint32_t cvta_s(const void* p){
  return (uint32_t)__cvta_generic_to_shared(p);
}
__device__ __forceinline__ void ldsm4(uint32_t* r, uint32_t addr){
  asm volatile("ldmatrix.sync.aligned.m8n8.x4.shared.b16 {%0,%1,%2,%3}, [%4];"
               : "=r"(r[0]), "=r"(r[1]), "=r"(r[2]), "=r"(r[3]) : "r"(addr));
}
__device__ __forceinline__ void mma16(float* d, const uint32_t* a, const uint32_t* b){
  asm volatile("mma.sync.aligned.m16n8k16.row.col.f32.bf16.bf16.f32 "
               "{%0,%1,%2,%3}, {%4,%5,%6,%7}, {%8,%9}, {%0,%1,%2,%3};"
               : "+f"(d[0]), "+f"(d[1]), "+f"(d[2]), "+f"(d[3])
               : "r"(a[0]), "r"(a[1]), "r"(a[2]), "r"(a[3]), "r"(b[0]), "r"(b[1]));
}

// ------------------------------- prep -------------------------------
__global__ void prep_kernel(const float* __restrict__ Wu, const float* __restrict__ bu,
                            const float* __restrict__ Wr, const float* __restrict__ br,
                            const float* __restrict__ Wc, const float* __restrict__ bc,
                            const float* __restrict__ Uu, const float* __restrict__ Ur,
                            const float* __restrict__ Uc,
                            const float* __restrict__ attW1) {
  int id = blockIdx.x*blockDim.x + threadIdx.x;
  if (id < U*N3) {
    int k = id / N3, c = id % N3;
    float w, u;
    if (c < 128)      { w = Wu[k*128 + c];       u = Uu[k*128 + c]; }
    else if (c < 256) { w = Wr[k*128 + (c-128)]; u = Ur[k*128 + (c-128)]; }
    else              { w = Wc[k*128 + (c-256)]; u = Uc[k*128 + (c-256)]; }
    g_Wau[id] = w;
    g_Uau[id] = u;
  }
  if (id < N3)
    g_bau[id] = (id < 128) ? bu[id] : (id < 256 ? br[id-128] : bc[id-256]);
  if (id < 2*U*U) {
    int k = id / 128, c = id % 128;
    float v;
    if (k < 128) v = attW1[k*128 + c] - attW1[U*U + k*128 + c];     // W1A - W1B
    else         v = attW1[3*U*U + (k-128)*128 + c];                // W1D
    g_Wcat[id] = v;
  }
  if (id < U*U)
    g_W1bc[id] = attW1[U*U + id] + attW1[2*U*U + id];
}

// --------------- pack all weights bf16 fragment-ordered ---------------
__device__ __forceinline__ void pack_bf16_n(const float* __restrict__ Um,
                                            uint32_t* __restrict__ P, int N, int idx) {
  int q = idx & 3, lane = (idx >> 2) & 31;
  int Ntp = N >> 4;
  int tp = (idx >> 7) % Ntp, k16 = (idx >> 7) / Ntp;
  int tile = 2*tp + (q >> 1), r = q & 1;
  int k = k16*16 + 2*(lane & 3) + 8*r;
  int n = tile*8 + (lane >> 2);
  P[idx] = bf2(Um[k*N + n], Um[(k+1)*N + n]);
}

__global__ void pack_all(const float* __restrict__ gruU, const float* __restrict__ gruW,
                         const float* __restrict__ attW2) {
  int idx = blockIdx.x*256 + threadIdx.x;   // 126976 total
  if (idx < 24576)        pack_bf16_n(gruU,   g_Ubf_gru, 384, idx);
  else if (idx < 49152)   pack_bf16_n(g_Uau,  g_Ubf_au,  384, idx - 24576);
  else if (idx < 73728)   pack_bf16_n(gruW,   g_Wb_gruW, 384, idx - 49152);
  else if (idx < 98304)   pack_bf16_n(g_Wau,  g_Wb_au,   384, idx - 73728);
  else if (idx < 106496)  pack_bf16_n(g_W1bc, g_Wb_1bc,  128, idx - 98304);
  else if (idx < 122880)  pack_bf16_n(g_Wcat, g_Wb_cat,  128, idx - 106496);
  else if (idx < 126976)  pack_bf16_n(attW2,  g_Wb_att2, 64,  idx - 122880);
}

// --------------------- bf16 GEMM, packed-B + ldmatrix-A, K=128 ---------------------
// obf=0: C fp32 direct.  obf=1: C bf16, SMEM-staged coalesced stores.
// abf=1: A is bf16 (row stride RS elements).
#define GAS 136   // As stride (bf16)
__global__ void gemm_bf16(const void* __restrict__ A, int P, long long GS, int RS,
                          const uint32_t* __restrict__ Bpk, int Ntp,
                          const float* __restrict__ bias, void* __restrict__ C, int ldc,
                          int obf, int abf) {
  extern __shared__ char smc[];
  __nv_bfloat16* As = (__nv_bfloat16*)smc;          // 64 x GAS  (17408 B)
  uint32_t* Bp = (uint32_t*)(smc + 64*GAS*2);       // 8192 u32  (32768 B)
  const int m0 = blockIdx.x * 64;
  const int c0 = blockIdx.y * 128;
  const int tp0 = blockIdx.y * 8;
  const int tid = threadIdx.x;          // 256
  const int kq = tid >> 5, cq = tid & 31;
  const int lane = tid & 31, wid = tid >> 5;
  const int wm = wid & 1, wn = wid >> 1;
  const int g = lane >> 2, t4 = lane & 3;

  if (abf) {
    #pragma unroll
    for (int it = 0; it < 4; ++it) {
      int f = it*256 + tid;               // 1024 = 64 rows x 16 uint4
      int r = f >> 4, q = f & 15;
      int m = m0 + r;
      const __nv_bfloat16* ap = (const __nv_bfloat16*)A + (long long)(m/P)*GS + (long long)(m%P)*RS;
      uint4 v = *(const uint4*)(ap + q*8);
      *(uint4*)(As + r*GAS + q*8) = v;
    }
  } else {
    #pragma unroll
    for (int it = 0; it < 8; ++it) {
      int r = kq + 8*it;
      int m = m0 + r;
      const float* ap = (const float*)A + (long long)(m/P)*GS + (long long)(m%P)*RS;
      float4 v = *(const float4*)(ap + 4*cq);
      uint32_t* dst = (uint32_t*)(As + r*GAS + 4*cq);
      dst[0] = bf2(v.x, v.y);
      dst[1] = bf2(v.z, v.w);
    }
  }
  {
    const uint4* src = (const uint4*)Bpk;
    uint4* dst = (uint4*)Bp;
    #pragma unroll
    for (int it = 0; it < 8; ++it) {
      int f = it*256 + tid;               // 2048 uint4
      int k16 = f >> 8, rem = f & 255;
      dst[f] = src[((long long)k16*Ntp + tp0)*32 + rem];
    }
  }
  __syncthreads();

  float acc[2][4][4];
  #pragma unroll
  for (int mt=0;mt<2;mt++)
    #pragma unroll
    for (int nt=0;nt<4;nt++)
      #pragma unroll
      for (int q=0;q<4;q++) acc[mt][nt][q] = 0.f;

  const uint32_t asb = cvta_s(As);
  const uint4* bp4 = (const uint4*)Bp;
  #pragma unroll
  for (int k16 = 0; k16 < 8; ++k16) {
    uint32_t a[2][4];
    #pragma unroll
    for (int mt=0;mt<2;mt++)
      ldsm4(a[mt], asb + ((wm*32 + mt*16 + (lane & 15))*GAS + k16*16 + ((lane >> 4) << 3))*2);
    uint4 b40 = bp4[(k16*8 + wn*2    )*32 + lane];
    uint4 b41 = bp4[(k16*8 + wn*2 + 1)*32 + lane];
    uint32_t bb[4][2];
    bb[0][0]=b40.x; bb[0][1]=b40.y; bb[1][0]=b40.z; bb[1][1]=b40.w;
    bb[2][0]=b41.x; bb[2][1]=b41.y; bb[3][0]=b41.z; bb[3][1]=b41.w;
    #pragma unroll
    for (int mt=0;mt<2;mt++)
      #pragma unroll
      for (int nt=0;nt<4;nt++)
        mma16(acc[mt][nt], a[mt], bb[nt]);
  }
  if (obf) {
    __syncthreads();                       // done reading As
    uint32_t* Cs = (uint32_t*)smc;         // 64 x 65 u32 (16640 B)
    #pragma unroll
    for (int mt=0;mt<2;mt++) {
      int row0 = wm*32 + mt*16 + g;
      #pragma unroll
      for (int nt=0;nt<4;nt++) {
        int col = wn*32 + nt*8 + 2*t4;
        float bc0 = bias[c0+col], bc1 = bias[c0+col+1];
        #pragma unroll
        for (int h=0; h<2; ++h) {
          int row = row0 + 8*h;
          Cs[row*65 + (col >> 1)] = bf2(acc[mt][nt][2*h+0] + bc0, acc[mt][nt][2*h+1] + bc1);
        }
      }
    }
    __syncthreads();
    #pragma unroll
    for (int it = 0; it < 16; ++it) {
      int f = it*256 + tid;
      int r = f >> 6, q = f & 63;
      *(uint32_t*)((__nv_bfloat16*)C + (long long)(m0+r)*ldc + c0 + 2*q) = Cs[r*65 + q];
    }
  } else {
    #pragma unroll
    for (int mt=0;mt<2;mt++) {
      int row0 = m0 + wm*32 + mt*16 + g;
      #pragma unroll
      for (int nt=0;nt<4;nt++) {
        int col = c0 + wn*32 + nt*8 + 2*t4;
        float bc0 = bias[col], bc1 = bias[col+1];
        #pragma unroll
        for (int h=0; h<2; ++h) {
          int row = row0 + 8*h;
          float2 o = {acc[mt][nt][2*h+0] + bc0, acc[mt][nt][2*h+1] + bc1};
          *(float2*)((float*)C + (long long)row*ldc + col) = o;
        }
      }
    }
  }
}

// -------------------- GRU scan, bf16 TC, B-in-regs (32 rows/CTA) --------------------
#define A_STRIDE 136
#define A_BUF    (32*A_STRIDE)      // bf16 per Ab buffer
#define XS_STRIDE 392               // bf16
#define XS_BUF   (32*XS_STRIDE)     // bf16 per Xs buffer
// smem: Ab[34816] Xs[50176] = 84992 B
__global__ __launch_bounds__(256, 1)
void gru_scan_mma(const __nv_bfloat16* __restrict__ Xp, const uint32_t* __restrict__ Bpack,
                  const float* __restrict__ brec, __nv_bfloat16* __restrict__ hsb) {
  extern __shared__ char smc[];
  __nv_bfloat16* Ab = (__nv_bfloat16*)smc;
  __nv_bfloat16* Xs = (__nv_bfloat16*)(smc + 34816);
  const int tid = threadIdx.x;    // 256
  const int w = tid >> 5, lane = tid & 31;
  const int g = lane >> 2, t4 = lane & 3;
  const int b0 = blockIdx.x * 32;
  // B weights -> registers (24 uint4)
  uint4 breg[24];
  #pragma unroll
  for (int k16=0;k16<8;++k16)
    #pragma unroll
    for (int j=0;j<3;++j)
      breg[k16*3+j] = ((const uint4*)Bpack)[((k16*24) + j*8 + w)*32 + lane];
  for (int i = tid; i < A_BUF; i += 256) ((uint32_t*)Ab)[i] = 0u;
  // stage x(0)
  #pragma unroll
  for (int it = 0; it < 6; ++it) {
    int f = it*256 + tid;
    int r = f / 48, q = f % 48;
    uint4 v = *(const uint4*)(Xp + ((long long)(b0+r)*T + 0)*N3 + q*8);
    *(uint4*)(Xs + r*XS_STRIDE + q*8) = v;
  }
  float2 bz[2], brr[2], bh[2];
  #pragma unroll
  for (int nt=0; nt<2; ++nt) {
    int c = (2*w+nt)*8 + 2*t4;
    bz[nt]  = *(const float2*)(brec + c);
    brr[nt] = *(const float2*)(brec + 128 + c);
    bh[nt]  = *(const float2*)(brec + 256 + c);
  }
  float h[2][2][2][2];
  #pragma unroll
  for (int a1=0;a1<2;a1++)
    #pragma unroll
    for (int a2=0;a2<2;a2++)
      #pragma unroll
      for (int a3=0;a3<2;a3++) { h[a1][a2][a3][0]=0.f; h[a1][a2][a3][1]=0.f; }
  const uint32_t abb = cvta_s(Ab);
  __syncthreads();

  for (int t = 0; t < T; ++t) {
    // prefetch x(t+1)
    if (t + 1 < T) {
      __nv_bfloat16* Xw = Xs + ((t+1) & 1) * XS_BUF;
      #pragma unroll
      for (int it = 0; it < 6; ++it) {
        int f = it*256 + tid;
        int r = f / 48, q = f % 48;
        uint4 v = *(const uint4*)(Xp + ((long long)(b0+r)*T + t+1)*N3 + q*8);
        *(uint4*)(Xw + r*XS_STRIDE + q*8) = v;
      }
    }
    // coalesced store of h(t-1) straight from the Ar buffer (bf16)
    if (t >= 1) {
      const uint4* Au = (const uint4*)(Ab + (t & 1) * A_BUF);
      #pragma unroll
      for (int it = 0; it < 2; ++it) {
        int f = it*256 + tid;            // 512 = 32 rows x 16 uint4
        int r = f >> 4, q = f & 15;
        *((uint4*)(hsb + ((long long)(b0+r)*T + (t-1))*128) + q) = Au[r*17 + q];
      }
    }
    const __nv_bfloat16* Xc = Xs + (t & 1) * XS_BUF;
    const uint32_t arb = abb + (uint32_t)((t & 1) * A_BUF * 2);
    __nv_bfloat16* Aw = Ab + ((t & 1) ^ 1) * A_BUF;
    float2 xz[2][2][2], xr[2][2][2], xh[2][2][2];
    #pragma unroll
    for (int mt=0;mt<2;mt++)
      #pragma unroll
      for (int rh=0;rh<2;rh++) {
        const __nv_bfloat16* xp = Xc + (mt*16 + rh*8 + g)*XS_STRIDE + 2*t4;
        #pragma unroll
        for (int nt=0;nt<2;nt++) {
          int c = (2*w+nt)*8;
          xz[mt][rh][nt] = bf2f(*(const uint32_t*)(xp + c));
          xr[mt][rh][nt] = bf2f(*(const uint32_t*)(xp + 128 + c));
          xh[mt][rh][nt] = bf2f(*(const uint32_t*)(xp + 256 + c));
        }
      }
    float acc[2][6][4];
    #pragma unroll
    for (int mt=0;mt<2;mt++)
      #pragma unroll
      for (int j=0;j<6;j++)
        #pragma unroll
        for (int q=0;q<4;q++) acc[mt][j][q] = 0.f;
    #pragma unroll
    for (int k16=0;k16<8;++k16) {
      uint32_t a[2][4];
      #pragma unroll
      for (int mt=0;mt<2;mt++)
        ldsm4(a[mt], arb + ((mt*16 + (lane & 15))*A_STRIDE + k16*16 + ((lane >> 4) << 3))*2);
      uint32_t bb[6][2];
      bb[0][0]=breg[k16*3+0].x; bb[0][1]=breg[k16*3+0].y;
      bb[1][0]=breg[k16*3+0].z; bb[1][1]=breg[k16*3+0].w;
      bb[2][0]=breg[k16*3+1].x; bb[2][1]=breg[k16*3+1].y;
      bb[3][0]=breg[k16*3+1].z; bb[3][1]=breg[k16*3+1].w;
      bb[4][0]=breg[k16*3+2].x; bb[4][1]=breg[k16*3+2].y;
      bb[5][0]=breg[k16*3+2].z; bb[5][1]=breg[k16*3+2].w;
      #pragma unroll
      for (int mt=0;mt<2;mt++)
        #pragma unroll
        for (int j=0;j<6;j++)
          mma16(acc[mt][j], a[mt], bb[j]);
    }
    #pragma unroll
    for (int mt=0;mt<2;mt++)
      #pragma unroll
      for (int rh=0;rh<2;rh++) {
        int row = mt*16 + rh*8 + g;
        #pragma unroll
        for (int nt=0;nt<2;nt++) {
          int c = (2*w+nt)*8 + 2*t4;
          float hn0, hn1;
          {
            float z  = sigt(xz[mt][rh][nt].x + acc[mt][nt][rh*2]     + bz[nt].x);
            float r  = sigt(xr[mt][rh][nt].x + acc[mt][2+nt][rh*2]   + brr[nt].x);
            float hc = tanha(xh[mt][rh][nt].x + r*(acc[mt][4+nt][rh*2] + bh[nt].x));
            float ho = h[mt][rh][nt][0];
            hn0 = z*ho + (1.f - z)*hc;
            h[mt][rh][nt][0] = hn0;
          }
          {
            float z  = sigt(xz[mt][rh][nt].y + acc[mt][nt][rh*2+1]     + bz[nt].y);
            float r  = sigt(xr[mt][rh][nt].y + acc[mt][2+nt][rh*2+1]   + brr[nt].y);
            float hc = tanha(xh[mt][rh][nt].y + r*(acc[mt][4+nt][rh*2+1] + bh[nt].y));
            float ho = h[mt][rh][nt][1];
            hn1 = z*ho + (1.f - z)*hc;
            h[mt][rh][nt][1] = hn1;
          }
          *(uint32_t*)(Aw + row*A_STRIDE + c) = bf2(hn0, hn1);
        }
      }
    __syncthreads();
  }
  { // final h(T-1) store from buffer ((T-1)&1)^1 = 0
    const uint4* Au = (const uint4*)(Ab);
    #pragma unroll
    for (int it = 0; it < 2; ++it) {
      int f = it*256 + tid;
      int r = f >> 4, q = f & 15;
      *((uint4*)(hsb + ((long long)(b0+r)*T + (T-1))*128) + q) = Au[r*17 + q];
    }
  }
}

// -------------------- AUGRU scan, bf16 TC, B-in-regs (32 rows/CTA) --------------------
// smem: Ab[34816] Xs[50176] ats[256] = 85248 B
__global__ __launch_bounds__(256, 1)
void augru_scan_mma(const __nv_bfloat16* __restrict__ X3, const uint32_t* __restrict__ Bpack) {
  extern __shared__ char smc[];
  __nv_bfloat16* Ab = (__nv_bfloat16*)smc;
  __nv_bfloat16* Xs = (__nv_bfloat16*)(smc + 34816);
  float* ats_s = (float*)(smc + 34816 + 50176);   // 2 x 32
  const int tid = threadIdx.x;
  const int w = tid >> 5, lane = tid & 31;
  const int g = lane >> 2, t4 = lane & 3;
  const int b0 = blockIdx.x * 32;
  uint4 breg[24];
  #pragma unroll
  for (int k16=0;k16<8;++k16)
    #pragma unroll
    for (int j=0;j<3;++j)
      breg[k16*3+j] = ((const uint4*)Bpack)[((k16*24) + j*8 + w)*32 + lane];
  for (int i = tid; i < A_BUF; i += 256) ((uint32_t*)Ab)[i] = 0u;
  #pragma unroll
  for (int it = 0; it < 6; ++it) {
    int f = it*256 + tid;
    int r = f / 48, q = f % 48;
    uint4 v = *(const uint4*)(X3 + ((long long)(b0+r)*T + 0)*N3 + q*8);
    *(uint4*)(Xs + r*XS_STRIDE + q*8) = v;
  }
  if (tid < 32) ats_s[tid] = g_ats[(long long)(b0+tid)*T + 0];
  float h[2][2][2][2];
  #pragma unroll
  for (int a1=0;a1<2;a1++)
    #pragma unroll
    for (int a2=0;a2<2;a2++)
      #pragma unroll
      for (int a3=0;a3<2;a3++) { h[a1][a2][a3][0]=0.f; h[a1][a2][a3][1]=0.f; }
  const uint32_t abb = cvta_s(Ab);
  __syncthreads();

  for (int t = 0; t < T; ++t) {
    if (t + 1 < T) {
      __nv_bfloat16* Xw = Xs + ((t+1) & 1) * XS_BUF;
      #pragma unroll
      for (int it = 0; it < 6; ++it) {
        int f = it*256 + tid;
        int r = f / 48, q = f % 48;
        uint4 v = *(const uint4*)(X3 + ((long long)(b0+r)*T + t+1)*N3 + q*8);
        *(uint4*)(Xw + r*XS_STRIDE + q*8) = v;
      }
      if (tid < 32) ats_s[((t+1)&1)*32 + tid] = g_ats[(long long)(b0+tid)*T + t+1];
    }
    const __nv_bfloat16* Xc = Xs + (t & 1) * XS_BUF;
    const float* atc = ats_s + (t & 1) * 32;
    const uint32_t arb = abb + (uint32_t)((t & 1) * A_BUF * 2);
    __nv_bfloat16* Aw = Ab + ((t & 1) ^ 1) * A_BUF;
    float2 xu[2][2][2], xr[2][2][2], xc[2][2][2];
    float at[2][2];
    #pragma unroll
    for (int mt=0;mt<2;mt++)
      #pragma unroll
      for (int rh=0;rh<2;rh++) {
        at[mt][rh] = atc[mt*16 + rh*8 + g];
        const __nv_bfloat16* xp = Xc + (mt*16 + rh*8 + g)*XS_STRIDE + 2*t4;
        #pragma unroll
        for (int nt=0;nt<2;nt++) {
          int c = (2*w+nt)*8;
          xu[mt][rh][nt] = bf2f(*(const uint32_t*)(xp + c));
          xr[mt][rh][nt] = bf2f(*(const uint32_t*)(xp + 128 + c));
          xc[mt][rh][nt] = bf2f(*(const uint32_t*)(xp + 256 + c));
        }
      }
    float acc[2][6][4];
    #pragma unroll
    for (int mt=0;mt<2;mt++)
      #pragma unroll
      for (int j=0;j<6;j++)
        #pragma unroll
        for (int q=0;q<4;q++) acc[mt][j][q] = 0.f;
    #pragma unroll
    for (int k16=0;k16<8;++k16) {
      uint32_t a[2][4];
      #pragma unroll
      for (int mt=0;mt<2;mt++)
        ldsm4(a[mt], arb + ((mt*16 + (lane & 15))*A_STRIDE + k16*16 + ((lane >> 4) << 3))*2);
      uint32_t bb[6][2];
      bb[0][0]=breg[k16*3+0].x; bb[0][1]=breg[k16*3+0].y;
      bb[1][0]=breg[k16*3+0].z; bb[1][1]=breg[k16*3+0].w;
      bb[2][0]=breg[k16*3+1].x; bb[2][1]=breg[k16*3+1].y;
      bb[3][0]=breg[k16*3+1].z; bb[3][1]=breg[k16*3+1].w;
      bb[4][0]=breg[k16*3+2].x; bb[4][1]=breg[k16*3+2].y;
      bb[5][0]=breg[k16*3+2].z; bb[5][1]=breg[k16*3+2].w;
      #pragma unroll
      for (int mt=0;mt<2;mt++)
        #pragma unroll
        for (int j=0;j<6;j++)
          mma16(acc[mt][j], a[mt], bb[j]);
    }
    #pragma unroll
    for (int mt=0;mt<2;mt++)
      #pragma unroll
      for (int rh=0;rh<2;rh++) {
        int row = mt*16 + rh*8 + g;
        float atv = at[mt][rh];
        #pragma unroll
        for (int nt=0;nt<2;nt++) {
          int c = (2*w+nt)*8 + 2*t4;
          float hn0, hn1;
          {
            float u  = sigt(xu[mt][rh][nt].x + acc[mt][nt][rh*2]);
            float r  = sigt(xr[mt][rh][nt].x + acc[mt][2+nt][rh*2]);
            float cc = tanha(xc[mt][rh][nt].x + r*acc[mt][4+nt][rh*2]);
            float uu = atv*u;
            float ho = h[mt][rh][nt][0];
            hn0 = (1.f - uu)*ho + uu*cc;
            h[mt][rh][nt][0] = hn0;
          }
          {
            float u  = sigt(xu[mt][rh][nt].y + acc[mt][nt][rh*2+1]);
            float r  = sigt(xr[mt][rh][nt].y + acc[mt][2+nt][rh*2+1]);
            float cc = tanha(xc[mt][rh][nt].y + r*acc[mt][4+nt][rh*2+1]);
            float uu = atv*u;
            float ho = h[mt][rh][nt][1];
            hn1 = (1.f - uu)*ho + uu*cc;
            h[mt][rh][nt][1] = hn1;
          }
          *(uint32_t*)(Aw + row*A_STRIDE + c) = bf2(hn0, hn1);
        }
      }
    __syncthreads();
  }
  #pragma unroll
  for (int mt=0;mt<2;mt++)
    #pragma unroll
    for (int rh=0;rh<2;rh++) {
      int row = mt*16 + rh*8 + g;
      #pragma unroll
      for (int nt=0;nt<2;nt++) {
        int c = (2*w+nt)*8 + 2*t4;
        float2 o = {h[mt][rh][nt][0], h[mt][rh][nt][1]};
        *(float2*)(g_hfin + (long long)(b0+row)*128 + c) = o;
      }
    }
}

// ------------- fused attention (bf16): hs,news -> a1 -> a2 -> ats -------------
#define ATT_AS 264   // As stride (bf16)
__global__ __launch_bounds__(256, 1)
void att_fused(const __nv_bfloat16* __restrict__ hsb, const float* __restrict__ inputs,
               const uint32_t* __restrict__ Wcatp, const uint32_t* __restrict__ W2p,
               const float* __restrict__ b2, const float* __restrict__ W3,
               const float* __restrict__ b3, const float* __restrict__ nterm) {
  extern __shared__ char smc[];
  __nv_bfloat16* As  = (__nv_bfloat16*)smc;            // 64 x 264        (33792 B)
  uint32_t* Wc  = (uint32_t*)(smc + 33792);            // 16384 u32       (65536 B)
  __nv_bfloat16* a1s = (__nv_bfloat16*)(smc + 99328);  // 64 x 136        (17408 B)
  uint32_t* W2s = (uint32_t*)(smc + 116736);           // 4096 u32        (16384 B)
  float* a2s = (float*)(smc + 133120);                 // 64 x 68         (17408 B)
  float* W3s = (float*)(smc + 150528);                 // 64
  const int tid = threadIdx.x;     // 256
  const int lane = tid & 31, wid = tid >> 5;
  const int wm = wid & 1, wn = wid >> 1;
  const int wm3 = wid & 3, wn3 = wid >> 2;
  const int g = lane >> 2, t4 = lane & 3;
  const float b3v = b3[0];

  {
    const uint4* src = (const uint4*)Wcatp;
    uint4* dst = (uint4*)Wc;
    #pragma unroll
    for (int it = 0; it < 16; ++it) dst[it*256 + tid] = src[it*256 + tid];
    const uint4* src2 = (const uint4*)W2p;
    uint4* dst2 = (uint4*)W2s;
    #pragma unroll
    for (int it = 0; it < 4; ++it) dst2[it*256 + tid] = src2[it*256 + tid];
    if (tid < 64) W3s[tid] = W3[tid];
  }
  const uint32_t asb = cvta_s(As);
  const uint32_t a1b = cvta_s(a1s);
  const uint4* Wc4 = (const uint4*)Wc;
  const uint4* W2p4 = (const uint4*)W2s;

  for (long long blk = blockIdx.x; blk < BT/64; blk += gridDim.x) {
    const long long m0 = blk * 64;
    __syncthreads();
    #pragma unroll
    for (int it = 0; it < 8; ++it) {
      int idx = it*256 + tid;      // 2048 = 64 rows x 32 (16 copy + 16 mul)
      int r = idx >> 5, q = idx & 31;
      long long row = m0 + r;
      const __nv_bfloat16* hp = hsb + row*128;
      if (q < 16) {
        uint4 v = *(const uint4*)(hp + q*8);
        *(uint4*)(As + r*ATT_AS + q*8) = v;
      } else {
        int qq = q - 16;
        int b = (int)(row / T);
        uint4 v = *(const uint4*)(hp + qq*8);
        const float* nw = inputs + ((long long)b*(T+1) + T)*128 + qq*8;
        float4 n0 = *(const float4*)(nw);
        float4 n1 = *(const float4*)(nw + 4);
        float2 h0 = bf2f(v.x), h1 = bf2f(v.y), h2 = bf2f(v.z), h3 = bf2f(v.w);
        uint4 o;
        o.x = bf2(h0.x*n0.x, h0.y*n0.y);
        o.y = bf2(h1.x*n0.z, h1.y*n0.w);
        o.z = bf2(h2.x*n1.x, h2.y*n1.y);
        o.w = bf2(h3.x*n1.z, h3.y*n1.w);
        *(uint4*)(As + r*ATT_AS + 128 + qq*8) = o;
      }
    }
    __syncthreads();
    float acc[2][4][4];
    #pragma unroll
    for (int mt=0;mt<2;mt++)
      #pragma unroll
      for (int nt=0;nt<4;nt++)
        #pragma unroll
        for (int q=0;q<4;q++) acc[mt][nt][q] = 0.f;
    #pragma unroll
    for (int k16 = 0; k16 < 16; ++k16) {
      uint32_t a[2][4];
      #pragma unroll
      for (int mt=0;mt<2;mt++)
        ldsm4(a[mt], asb + ((wm*32 + mt*16 + (lane & 15))*ATT_AS + k16*16 + ((lane >> 4) << 3))*2);
      uint4 b40 = Wc4[(k16*8 + wn*2    )*32 + lane];
      uint4 b41 = Wc4[(k16*8 + wn*2 + 1)*32 + lane];
      uint32_t bb[4][2];
      bb[0][0]=b40.x; bb[0][1]=b40.y; bb[1][0]=b40.z; bb[1][1]=b40.w;
      bb[2][0]=b41.x; bb[2][1]=b41.y; bb[3][0]=b41.z; bb[3][1]=b41.w;
      #pragma unroll
      for (int mt=0;mt<2;mt++)
        #pragma unroll
        for (int nt=0;nt<4;nt++)
          mma16(acc[mt][nt], a[mt], bb[nt]);
    }
    #pragma unroll
    for (int mt=0;mt<2;mt++) {
      int row0 = wm*32 + mt*16 + g;
      #pragma unroll
      for (int nt=0;nt<4;nt++) {
        int col = wn*32 + nt*8 + 2*t4;
        #pragma unroll
        for (int h=0; h<2; ++h) {
          int row = row0 + 8*h;
          long long rowg = m0 + row;
          const float* np = nterm + (long long)(rowg / T)*128;
          float v0 = fmaxf(acc[mt][nt][2*h+0] + np[col],   0.f);
          float v1 = fmaxf(acc[mt][nt][2*h+1] + np[col+1], 0.f);
          *(uint32_t*)(a1s + row*A_STRIDE + col) = bf2(v0, v1);
        }
      }
    }
    __syncthreads();
    {
      float acc2[4][4];
      #pragma unroll
      for (int nt=0;nt<4;nt++)
        #pragma unroll
        for (int q=0;q<4;q++) acc2[nt][q] = 0.f;
      #pragma unroll
      for (int k16 = 0; k16 < 8; ++k16) {
        uint32_t a[4];
        ldsm4(a, a1b + ((wm3*16 + (lane & 15))*A_STRIDE + k16*16 + ((lane >> 4) << 3))*2);
        uint4 b40 = W2p4[(k16*4 + wn3*2    )*32 + lane];
        uint4 b41 = W2p4[(k16*4 + wn3*2 + 1)*32 + lane];
        uint32_t bb[4][2];
        bb[0][0]=b40.x; bb[0][1]=b40.y; bb[1][0]=b40.z; bb[1][1]=b40.w;
        bb[2][0]=b41.x; bb[2][1]=b41.y; bb[3][0]=b41.z; bb[3][1]=b41.w;
        #pragma unroll
        for (int nt=0;nt<4;nt++)
          mma16(acc2[nt], a, bb[nt]);
      }
      #pragma unroll
      for (int nt=0;nt<4;nt++) {
        int col = wn3*32 + nt*8 + 2*t4;
        float bc0 = b2[col], bc1 = b2[col+1];
        #pragma unroll
        for (int h=0; h<2; ++h) {
          int row = wm3*16 + g + 8*h;
          a2s[row*68 + col]     = fmaxf(acc2[nt][2*h+0] + bc0, 0.f);
          a2s[row*68 + col + 1] = fmaxf(acc2[nt][2*h+1] + bc1, 0.f);
        }
      }
    }
    __syncthreads();
    if (tid < 64) {
      float accv = b3v;
      #pragma unroll 8
      for (int cc=0; cc<64; ++cc) accv = fmaf(a2s[tid*68 + cc], W3s[cc], accv);
      g_ats[m0 + tid] = sigf(accv);
    }
  }
}

// ------------------------------ head ------------------------------
__global__ void head_kernel(const float* __restrict__ inputs,
                            const float* __restrict__ gamma, const float* __restrict__ beta,
                            const float* __restrict__ mean,  const float* __restrict__ var,
                            const float* __restrict__ W1, const float* __restrict__ bb1,
                            const float* __restrict__ W2, const float* __restrict__ bb2,
                            const float* __restrict__ fW, const float* __restrict__ fb,
                            float* __restrict__ out) {
  extern __shared__ float sm[];
  float* xs  = sm;          // 32*256
  float* y1s = xs + 8192;   // 32*256
  float* y2s = y1s + 8192;  // 32*128
  const int tid = threadIdx.x;   // 256
  const int b0 = blockIdx.x * 32;
  for (int r = 0; r < 32; ++r) {
    int k = tid;
    int bb = b0 + r;
    float v = (k < 128) ? g_hfin[bb*128 + k]
                        : inputs[((long long)bb*(T+1) + T)*128 + (k - 128)];
    float nv = (v - mean[k]) * rsqrtf(var[k] + BN_EPS) * gamma[k] + beta[k];
    xs[r*256 + k] = nv;
  }
  __syncthreads();
  {
    float acc[32];
    #pragma unroll
    for (int r=0;r<32;r++) acc[r] = bb1[tid];
    for (int k=0;k<256;++k) {
      float w = W1[k*256 + tid];
      #pragma unroll
      for (int r=0;r<32;r++) acc[r] = fmaf(xs[r*256+k], w, acc[r]);
    }
    #pragma unroll
    for (int r=0;r<32;r++) {
      float v = acc[r];
      y1s[r*256 + tid] = v >= 0.f ? v : LEAKY*v;
    }
  }
  __syncthreads();
  if (tid < 128) {
    float acc[32];
    #pragma unroll
    for (int r=0;r<32;r++) acc[r] = bb2[tid];
    for (int k=0;k<256;++k) {
      float w = W2[k*128 + tid];
      #pragma unroll
      for (int r=0;r<32;r++) acc[r] = fmaf(y1s[r*256+k], w, acc[r]);
    }
    #pragma unroll
    for (int r=0;r<32;r++) {
      float v = acc[r];
      y2s[r*128 + tid] = v >= 0.f ? v : LEAKY*v;
    }
  }
  __syncthreads();
  if (tid < 32) {
    float acc = fb[0];
    for (int k=0;k<128;++k) acc = fmaf(y2s[tid*128+k], fW[k], acc);
    out[b0 + tid] = sigf(acc);
  }
}

// ------------------------------ launch ------------------------------
extern "C" void kernel_launch(void* const* d_in, const int* in_sizes, int n_in,
                              void* d_out, int out_size) {
  (void)in_sizes; (void)n_in; (void)out_size;
  const float* inputs  = (const float*)d_in[0];
  const float* gru_W   = (const float*)d_in[1];
  const float* gru_U   = (const float*)d_in[2];
  const float* gru_b   = (const float*)d_in[3];
  const float* att_W1  = (const float*)d_in[4];
  const float* att_b1  = (const float*)d_in[5];
  const float* att_W2  = (const float*)d_in[6];
  const float* att_b2  = (const float*)d_in[7];
  const float* att_W3  = (const float*)d_in[8];
  const float* att_b3  = (const float*)d_in[9];
  const float* au_Wu   = (const float*)d_in[10];
  const float* au_bu   = (const float*)d_in[11];
  const float* au_Uu   = (const float*)d_in[12];
  const float* au_Wr   = (const float*)d_in[13];
  const float* au_br   = (const float*)d_in[14];
  const float* au_Ur   = (const float*)d_in[15];
  const float* au_Wc   = (const float*)d_in[16];
  const float* au_bc   = (const float*)d_in[17];
  const float* au_Uc   = (const float*)d_in[18];
  const float* bn_gamma= (const float*)d_in[19];
  const float* bn_beta = (const float*)d_in[20];
  const float* bn_mean = (const float*)d_in[21];
  const float* bn_var  = (const float*)d_in[22];
  const float* d_W1    = (const float*)d_in[23];
  const float* d_b1    = (const float*)d_in[24];
  const float* d_W2    = (const float*)d_in[25];
  const float* d_b2    = (const float*)d_in[26];
  const float* f_W     = (const float*)d_in[27];
  const float* f_b     = (const float*)d_in[28];
  float* out = (float*)d_out;

  const size_t sm_gemm  = 64*GAS*2 + 8192*4;                 // 50176
  const size_t sm_gru   = 34816 + 50176;                     // 84992
  const size_t sm_au    = 34816 + 50176 + 256;               // 85248
  const size_t sm_attf  = 150784;
  const size_t sm_head  = (8192*2 + 4096)*sizeof(float);
  cudaFuncSetAttribute(gemm_bf16,      cudaFuncAttributeMaxDynamicSharedMemorySize, (int)sm_gemm);
  cudaFuncSetAttribute(gru_scan_mma,   cudaFuncAttributeMaxDynamicSharedMemorySize, (int)sm_gru);
  cudaFuncSetAttribute(augru_scan_mma, cudaFuncAttributeMaxDynamicSharedMemorySize, (int)sm_au);
  cudaFuncSetAttribute(att_fused,      cudaFuncAttributeMaxDynamicSharedMemorySize, (int)sm_attf);
  cudaFuncSetAttribute(head_kernel,    cudaFuncAttributeMaxDynamicSharedMemorySize, (int)sm_head);

  float *p_Xp, *p_X3, *p_newsterm, *p_bau;
  __nv_bfloat16 *p_hsb;
  uint32_t *p_Ubg, *p_Uba, *p_WbgW, *p_Wbau, *p_Wb1bc, *p_Wbcat, *p_Wbatt2;
  cudaGetSymbolAddress((void**)&p_Xp,       g_Xp);
  cudaGetSymbolAddress((void**)&p_hsb,      g_hsb);
  cudaGetSymbolAddress((void**)&p_X3,       g_X3);
  cudaGetSymbolAddress((void**)&p_newsterm, g_newsterm);
  cudaGetSymbolAddress((void**)&p_bau,      g_bau);
  cudaGetSymbolAddress((void**)&p_Ubg,      g_Ubf_gru);
  cudaGetSymbolAddress((void**)&p_Uba,      g_Ubf_au);
  cudaGetSymbolAddress((void**)&p_WbgW,     g_Wb_gruW);
  cudaGetSymbolAddress((void**)&p_Wbau,     g_Wb_au);
  cudaGetSymbolAddress((void**)&p_Wb1bc,    g_Wb_1bc);
  cudaGetSymbolAddress((void**)&p_Wbcat,    g_Wb_cat);
  cudaGetSymbolAddress((void**)&p_Wbatt2,   g_Wb_att2);

  cudaStream_t s2;
  cudaStreamCreateWithFlags(&s2, cudaStreamNonBlocking);
  cudaEvent_t evPack, evNews, evFork, evJoin;
  cudaEventCreateWithFlags(&evPack, cudaEventDisableTiming);
  cudaEventCreateWithFlags(&evNews, cudaEventDisableTiming);
  cudaEventCreateWithFlags(&evFork, cudaEventDisableTiming);
  cudaEventCreateWithFlags(&evJoin, cudaEventDisableTiming);

  // 1) fold weights, then all bf16 fragment packs
  prep_kernel<<<192, 256>>>(au_Wu, au_bu, au_Wr, au_br, au_Wc, au_bc,
                            au_Uu, au_Ur, au_Uc, att_W1);
  pack_all<<<496, 256>>>(gru_U, gru_W, att_W2);
  cudaEventRecord(evPack, 0);
  cudaStreamWaitEvent(s2, evPack, 0);
  // 2) newsterm = news @ (W1B+W1C) + b1  (side stream; fp32 out)
  gemm_bf16<<<dim3(B/64, 1), 256, sm_gemm, s2>>>(inputs + (long long)T*128, 1, (long long)(T+1)*128, 128,
                                                 p_Wb1bc, 8, att_b1, p_newsterm, 128, 0, 0);
  cudaEventRecord(evNews, s2);
  // 3) Xp = hist @ gru_W + gru_b[0]   (bf16 out)
  gemm_bf16<<<dim3(BT/64, 3), 256, sm_gemm>>>(inputs, T, (long long)(T+1)*128, 128,
                                              p_WbgW, 24, gru_b, p_Xp, 384, 1, 0);
  // 4) GRU recurrence -> hsb (bf16)
  gru_scan_mma<<<B/32, 256, sm_gru>>>((const __nv_bfloat16*)p_Xp, p_Ubg, gru_b + 384, p_hsb);
  // fork: X3 gemm on s2, attention on main stream
  cudaEventRecord(evFork, 0);
  cudaStreamWaitEvent(s2, evFork, 0);
  // 5) X3 = hsb @ [Wu|Wr|Wc] + [bu|br|bc]   (side stream; bf16 A + bf16 out)
  gemm_bf16<<<dim3(BT/64, 3), 256, sm_gemm, s2>>>(p_hsb, 1<<30, 0LL, 128,
                                                  p_Wbau, 24, p_bau, p_X3, 384, 1, 1);
  cudaEventRecord(evJoin, s2);
  // 6) fused attention -> g_ats  (main stream; needs newsterm)
  cudaStreamWaitEvent(0, evNews, 0);
  att_fused<<<148, 256, sm_attf>>>(p_hsb, inputs, p_Wbcat, p_Wbatt2,
                                   att_b2, att_W3, att_b3, p_newsterm);
  cudaStreamWaitEvent(0, evJoin, 0);
  // 7) AUGRU recurrence -> hfin
  augru_scan_mma<<<B/32, 256, sm_au>>>((const __nv_bfloat16*)p_X3, p_Uba);
  // 8) BN + dense head -> out
  head_kernel<<<B/32, 256, sm_head>>>(inputs, bn_gamma, bn_beta, bn_mean, bn_var,
                                      d_W1, d_b1, d_W2, d_b2, f_W, f_b, out);
}

// round 13
// speedup vs baseline: 1.4999x; 1.0092x over previous
#include <cuda_runtime.h>
#include <cuda_bf16.h>
#include <math.h>
#include <stdint.h>

#define B  4096
#define T  50
#define U  128
#define N3 384
#define BT (B*T)
#define BN_EPS 1e-3f
#define LEAKY  3e-4f

// ------------ scratch (device globals; no allocation allowed) ------------
__device__ float g_Xp[BT*N3];            // GRU input projection (bf16 payload)
__device__ __nv_bfloat16 g_hsb[BT*U];    // GRU hidden states (bf16)
__device__ float g_X3[BT*N3];            // AUGRU input projections (bf16 payload)
__device__ float g_ats[BT];              // attention scores
__device__ float g_hfin[B*U];            // AUGRU final state
__device__ float g_newsterm[B*U];        // news@(W1B+W1C)+b1
__device__ float g_Wau[U*N3];            // packed input  [Wu|Wr|Wc]
__device__ float g_Uau[U*N3];            // packed recur  [Uu|Ur|Uc]
__device__ float g_bau[N3];              // packed [bu|br|bc]
__device__ float g_Wcat[2*U*U];          // [W1A-W1B ; W1D]  (256 x 128)
__device__ float g_W1bc[U*U];            // W1B + W1C
__device__ uint32_t g_Ubf_gru[24576];    // bf16 frag gru_U
__device__ uint32_t g_Ubf_au[24576];     // bf16 frag [Uu|Ur|Uc]
__device__ uint32_t g_Wb_gruW[24576];    // bf16 frag gru_W     (K=128,N=384)
__device__ uint32_t g_Wb_au[24576];      // bf16 frag [Wu|Wr|Wc]
__device__ uint32_t g_Wb_1bc[8192];      // bf16 frag W1B+W1C   (K=128,N=128)
__device__ uint32_t g_Wb_cat[16384];     // bf16 frag Wcat      (K=256,N=128)
__device__ uint32_t g_Wb_att2[4096];     // bf16 frag att_W2    (K=128,N=64)

__device__ __forceinline__ float sigf(float x){ return 1.f/(1.f+expf(-x)); }
__device__ __forceinline__ float tanha(float x){
  float y; asm("tanh.approx.f32 %0, %1;" : "=f"(y) : "f"(x)); return y;
}
__device__ __forceinline__ float sigt(float x){ return fmaf(tanha(0.5f*x), 0.5f, 0.5f); }
__device__ __forceinline__ uint32_t bf2(float lo, float hi){
  __nv_bfloat162 v;
  v.x = __float2bfloat16(lo); v.y = __float2bfloat16(hi);
  return *(uint32_t*)&v;
}
__device__ __forceinline__ float2 bf2f(uint32_t u){
  __nv_bfloat162 v = *(__nv_bfloat162*)&u;
  return __bfloat1622float2(v);
}
__device__ __forceinline__ uint32_t cvta_s(const void* p){
  return (uint32_t)__cvta_generic_to_shared(p);
}
__device__ __forceinline__ void ldsm4(uint32_t* r, uint32_t addr){
  asm volatile("ldmatrix.sync.aligned.m8n8.x4.shared.b16 {%0,%1,%2,%3}, [%4];"
               : "=r"(r[0]), "=r"(r[1]), "=r"(r[2]), "=r"(r[3]) : "r"(addr));
}
__device__ __forceinline__ void mma16(float* d, const uint32_t* a, const uint32_t* b){
  asm volatile("mma.sync.aligned.m16n8k16.row.col.f32.bf16.bf16.f32 "
               "{%0,%1,%2,%3}, {%4,%5,%6,%7}, {%8,%9}, {%0,%1,%2,%3};"
               : "+f"(d[0]), "+f"(d[1]), "+f"(d[2]), "+f"(d[3])
               : "r"(a[0]), "r"(a[1]), "r"(a[2]), "r"(a[3]), "r"(b[0]), "r"(b[1]));
}

// ------------------------------- prep -------------------------------
__global__ void prep_kernel(const float* __restrict__ Wu, const float* __restrict__ bu,
                            const float* __restrict__ Wr, const float* __restrict__ br,
                            const float* __restrict__ Wc, const float* __restrict__ bc,
                            const float* __restrict__ Uu, const float* __restrict__ Ur,
                            const float* __restrict__ Uc,
                            const float* __restrict__ attW1) {
  int id = blockIdx.x*blockDim.x + threadIdx.x;
  if (id < U*N3) {
    int k = id / N3, c = id % N3;
    float w, u;
    if (c < 128)      { w = Wu[k*128 + c];       u = Uu[k*128 + c]; }
    else if (c < 256) { w = Wr[k*128 + (c-128)]; u = Ur[k*128 + (c-128)]; }
    else              { w = Wc[k*128 + (c-256)]; u = Uc[k*128 + (c-256)]; }
    g_Wau[id] = w;
    g_Uau[id] = u;
  }
  if (id < N3)
    g_bau[id] = (id < 128) ? bu[id] : (id < 256 ? br[id-128] : bc[id-256]);
  if (id < 2*U*U) {
    int k = id / 128, c = id % 128;
    float v;
    if (k < 128) v = attW1[k*128 + c] - attW1[U*U + k*128 + c];     // W1A - W1B
    else         v = attW1[3*U*U + (k-128)*128 + c];                // W1D
    g_Wcat[id] = v;
  }
  if (id < U*U)
    g_W1bc[id] = attW1[U*U + id] + attW1[2*U*U + id];
}

// --------------- pack all weights bf16 fragment-ordered ---------------
__device__ __forceinline__ void pack_bf16_n(const float* __restrict__ Um,
                                            uint32_t* __restrict__ P, int N, int idx) {
  int q = idx & 3, lane = (idx >> 2) & 31;
  int Ntp = N >> 4;
  int tp = (idx >> 7) % Ntp, k16 = (idx >> 7) / Ntp;
  int tile = 2*tp + (q >> 1), r = q & 1;
  int k = k16*16 + 2*(lane & 3) + 8*r;
  int n = tile*8 + (lane >> 2);
  P[idx] = bf2(Um[k*N + n], Um[(k+1)*N + n]);
}

__global__ void pack_all(const float* __restrict__ gruU, const float* __restrict__ gruW,
                         const float* __restrict__ attW2) {
  int idx = blockIdx.x*256 + threadIdx.x;   // 126976 total
  if (idx < 24576)        pack_bf16_n(gruU,   g_Ubf_gru, 384, idx);
  else if (idx < 49152)   pack_bf16_n(g_Uau,  g_Ubf_au,  384, idx - 24576);
  else if (idx < 73728)   pack_bf16_n(gruW,   g_Wb_gruW, 384, idx - 49152);
  else if (idx < 98304)   pack_bf16_n(g_Wau,  g_Wb_au,   384, idx - 73728);
  else if (idx < 106496)  pack_bf16_n(g_W1bc, g_Wb_1bc,  128, idx - 98304);
  else if (idx < 122880)  pack_bf16_n(g_Wcat, g_Wb_cat,  128, idx - 106496);
  else if (idx < 126976)  pack_bf16_n(attW2,  g_Wb_att2, 64,  idx - 122880);
}

// --------------------- bf16 GEMM, packed-B + ldmatrix-A, K=128 ---------------------
#define GAS 136   // As stride (bf16)
__global__ void gemm_bf16(const void* __restrict__ A, int P, long long GS, int RS,
                          const uint32_t* __restrict__ Bpk, int Ntp,
                          const float* __restrict__ bias, void* __restrict__ C, int ldc,
                          int obf, int abf) {
  extern __shared__ char smc[];
  __nv_bfloat16* As = (__nv_bfloat16*)smc;          // 64 x GAS  (17408 B)
  uint32_t* Bp = (uint32_t*)(smc + 64*GAS*2);       // 8192 u32  (32768 B)
  const int m0 = blockIdx.x * 64;
  const int c0 = blockIdx.y * 128;
  const int tp0 = blockIdx.y * 8;
  const int tid = threadIdx.x;          // 256
  const int kq = tid >> 5, cq = tid & 31;
  const int lane = tid & 31, wid = tid >> 5;
  const int wm = wid & 1, wn = wid >> 1;
  const int g = lane >> 2, t4 = lane & 3;

  if (abf) {
    #pragma unroll
    for (int it = 0; it < 4; ++it) {
      int f = it*256 + tid;
      int r = f >> 4, q = f & 15;
      int m = m0 + r;
      const __nv_bfloat16* ap = (const __nv_bfloat16*)A + (long long)(m/P)*GS + (long long)(m%P)*RS;
      uint4 v = *(const uint4*)(ap + q*8);
      *(uint4*)(As + r*GAS + q*8) = v;
    }
  } else {
    #pragma unroll
    for (int it = 0; it < 8; ++it) {
      int r = kq + 8*it;
      int m = m0 + r;
      const float* ap = (const float*)A + (long long)(m/P)*GS + (long long)(m%P)*RS;
      float4 v = *(const float4*)(ap + 4*cq);
      uint32_t* dst = (uint32_t*)(As + r*GAS + 4*cq);
      dst[0] = bf2(v.x, v.y);
      dst[1] = bf2(v.z, v.w);
    }
  }
  {
    const uint4* src = (const uint4*)Bpk;
    uint4* dst = (uint4*)Bp;
    #pragma unroll
    for (int it = 0; it < 8; ++it) {
      int f = it*256 + tid;
      int k16 = f >> 8, rem = f & 255;
      dst[f] = src[((long long)k16*Ntp + tp0)*32 + rem];
    }
  }
  __syncthreads();

  float acc[2][4][4];
  #pragma unroll
  for (int mt=0;mt<2;mt++)
    #pragma unroll
    for (int nt=0;nt<4;nt++)
      #pragma unroll
      for (int q=0;q<4;q++) acc[mt][nt][q] = 0.f;

  const uint32_t asb = cvta_s(As);
  const uint4* bp4 = (const uint4*)Bp;
  #pragma unroll
  for (int k16 = 0; k16 < 8; ++k16) {
    uint32_t a[2][4];
    #pragma unroll
    for (int mt=0;mt<2;mt++)
      ldsm4(a[mt], asb + ((wm*32 + mt*16 + (lane & 15))*GAS + k16*16 + ((lane >> 4) << 3))*2);
    uint4 b40 = bp4[(k16*8 + wn*2    )*32 + lane];
    uint4 b41 = bp4[(k16*8 + wn*2 + 1)*32 + lane];
    uint32_t bb[4][2];
    bb[0][0]=b40.x; bb[0][1]=b40.y; bb[1][0]=b40.z; bb[1][1]=b40.w;
    bb[2][0]=b41.x; bb[2][1]=b41.y; bb[3][0]=b41.z; bb[3][1]=b41.w;
    #pragma unroll
    for (int mt=0;mt<2;mt++)
      #pragma unroll
      for (int nt=0;nt<4;nt++)
        mma16(acc[mt][nt], a[mt], bb[nt]);
  }
  if (obf) {
    __syncthreads();
    uint32_t* Cs = (uint32_t*)smc;         // 64 x 65 u32
    #pragma unroll
    for (int mt=0;mt<2;mt++) {
      int row0 = wm*32 + mt*16 + g;
      #pragma unroll
      for (int nt=0;nt<4;nt++) {
        int col = wn*32 + nt*8 + 2*t4;
        float bc0 = bias[c0+col], bc1 = bias[c0+col+1];
        #pragma unroll
        for (int h=0; h<2; ++h) {
          int row = row0 + 8*h;
          Cs[row*65 + (col >> 1)] = bf2(acc[mt][nt][2*h+0] + bc0, acc[mt][nt][2*h+1] + bc1);
        }
      }
    }
    __syncthreads();
    #pragma unroll
    for (int it = 0; it < 16; ++it) {
      int f = it*256 + tid;
      int r = f >> 6, q = f & 63;
      *(uint32_t*)((__nv_bfloat16*)C + (long long)(m0+r)*ldc + c0 + 2*q) = Cs[r*65 + q];
    }
  } else {
    #pragma unroll
    for (int mt=0;mt<2;mt++) {
      int row0 = m0 + wm*32 + mt*16 + g;
      #pragma unroll
      for (int nt=0;nt<4;nt++) {
        int col = c0 + wn*32 + nt*8 + 2*t4;
        float bc0 = bias[col], bc1 = bias[col+1];
        #pragma unroll
        for (int h=0; h<2; ++h) {
          int row = row0 + 8*h;
          float2 o = {acc[mt][nt][2*h+0] + bc0, acc[mt][nt][2*h+1] + bc1};
          *(float2*)((float*)C + (long long)row*ldc + col) = o;
        }
      }
    }
  }
}

// -------------------- GRU scan, 512 thr, nt-split warps (32 rows/CTA) --------------------
#define A_STRIDE 136
#define A_BUF    (32*A_STRIDE)
#define XS_STRIDE 392
#define XS_BUF   (32*XS_STRIDE)
// smem: Ab[34816] Xs[50176] = 84992 B
__global__ __launch_bounds__(512, 1)
void gru_scan_mma(const __nv_bfloat16* __restrict__ Xp, const uint32_t* __restrict__ Bpack,
                  const float* __restrict__ brec, __nv_bfloat16* __restrict__ hsb) {
  extern __shared__ char smc[];
  __nv_bfloat16* Ab = (__nv_bfloat16*)smc;
  __nv_bfloat16* Xs = (__nv_bfloat16*)(smc + 34816);
  const int tid = threadIdx.x;    // 512
  const int w2 = tid >> 5, lane = tid & 31;
  const int w = w2 >> 1, ntw = w2 & 1;
  const int g = lane >> 2, t4 = lane & 3;
  const int b0 = blockIdx.x * 32;
  const int csub = w2*8 + 2*t4;   // this warp's column pair base
  // B half-fragments -> registers (24 uint2 = 48 regs)
  uint2 breg[24];
  #pragma unroll
  for (int k16=0;k16<8;++k16)
    #pragma unroll
    for (int j=0;j<3;++j)
      breg[k16*3+j] = ((const uint2*)Bpack)[(((k16*24) + j*8 + w)*32 + lane)*2 + ntw];
  for (int i = tid; i < A_BUF; i += 512) ((uint32_t*)Ab)[i] = 0u;
  #pragma unroll
  for (int it = 0; it < 3; ++it) {
    int f = it*512 + tid;
    int r = f / 48, q = f % 48;
    uint4 v = *(const uint4*)(Xp + ((long long)(b0+r)*T + 0)*N3 + q*8);
    *(uint4*)(Xs + r*XS_STRIDE + q*8) = v;
  }
  float2 bz = *(const float2*)(brec + csub);
  float2 brr = *(const float2*)(brec + 128 + csub);
  float2 bh = *(const float2*)(brec + 256 + csub);
  float h[2][2][2];     // [mt][rh][2]
  #pragma unroll
  for (int a1=0;a1<2;a1++)
    #pragma unroll
    for (int a2=0;a2<2;a2++) { h[a1][a2][0]=0.f; h[a1][a2][1]=0.f; }
  const uint32_t abb = cvta_s(Ab);
  __syncthreads();

  for (int t = 0; t < T; ++t) {
    if (t + 1 < T) {
      __nv_bfloat16* Xw = Xs + ((t+1) & 1) * XS_BUF;
      #pragma unroll
      for (int it = 0; it < 3; ++it) {
        int f = it*512 + tid;
        int r = f / 48, q = f % 48;
        uint4 v = *(const uint4*)(Xp + ((long long)(b0+r)*T + t+1)*N3 + q*8);
        *(uint4*)(Xw + r*XS_STRIDE + q*8) = v;
      }
    }
    if (t >= 1) {
      const uint4* Au = (const uint4*)(Ab + (t & 1) * A_BUF);
      int r = tid >> 4, q = tid & 15;    // 512 = 32 rows x 16 uint4
      *((uint4*)(hsb + ((long long)(b0+r)*T + (t-1))*128) + q) = Au[r*17 + q];
    }
    const __nv_bfloat16* Xc = Xs + (t & 1) * XS_BUF;
    const uint32_t arb = abb + (uint32_t)((t & 1) * A_BUF * 2);
    __nv_bfloat16* Aw = Ab + ((t & 1) ^ 1) * A_BUF;
    float2 xz[2][2], xr[2][2], xh[2][2];
    #pragma unroll
    for (int mt=0;mt<2;mt++)
      #pragma unroll
      for (int rh=0;rh<2;rh++) {
        const __nv_bfloat16* xp = Xc + (mt*16 + rh*8 + g)*XS_STRIDE + csub;
        xz[mt][rh] = bf2f(*(const uint32_t*)(xp));
        xr[mt][rh] = bf2f(*(const uint32_t*)(xp + 128));
        xh[mt][rh] = bf2f(*(const uint32_t*)(xp + 256));
      }
    float acc[2][3][4];
    #pragma unroll
    for (int mt=0;mt<2;mt++)
      #pragma unroll
      for (int j=0;j<3;j++)
        #pragma unroll
        for (int q=0;q<4;q++) acc[mt][j][q] = 0.f;
    #pragma unroll
    for (int k16=0;k16<8;++k16) {
      uint32_t a[2][4];
      #pragma unroll
      for (int mt=0;mt<2;mt++)
        ldsm4(a[mt], arb + ((mt*16 + (lane & 15))*A_STRIDE + k16*16 + ((lane >> 4) << 3))*2);
      #pragma unroll
      for (int mt=0;mt<2;mt++)
        #pragma unroll
        for (int j=0;j<3;j++)
          mma16(acc[mt][j], a[mt], (const uint32_t*)&breg[k16*3+j]);
    }
    #pragma unroll
    for (int mt=0;mt<2;mt++)
      #pragma unroll
      for (int rh=0;rh<2;rh++) {
        int row = mt*16 + rh*8 + g;
        float hn0, hn1;
        {
          float z  = sigt(xz[mt][rh].x + acc[mt][0][rh*2] + bz.x);
          float r  = sigt(xr[mt][rh].x + acc[mt][1][rh*2] + brr.x);
          float hc = tanha(xh[mt][rh].x + r*(acc[mt][2][rh*2] + bh.x));
          float ho = h[mt][rh][0];
          hn0 = z*ho + (1.f - z)*hc;
          h[mt][rh][0] = hn0;
        }
        {
          float z  = sigt(xz[mt][rh].y + acc[mt][0][rh*2+1] + bz.y);
          float r  = sigt(xr[mt][rh].y + acc[mt][1][rh*2+1] + brr.y);
          float hc = tanha(xh[mt][rh].y + r*(acc[mt][2][rh*2+1] + bh.y));
          float ho = h[mt][rh][1];
          hn1 = z*ho + (1.f - z)*hc;
          h[mt][rh][1] = hn1;
        }
        *(uint32_t*)(Aw + row*A_STRIDE + csub) = bf2(hn0, hn1);
      }
    __syncthreads();
  }
  { // final h(T-1) store from buffer 0
    const uint4* Au = (const uint4*)(Ab);
    int r = tid >> 4, q = tid & 15;
    *((uint4*)(hsb + ((long long)(b0+r)*T + (T-1))*128) + q) = Au[r*17 + q];
  }
}

// -------------------- AUGRU scan, 512 thr, nt-split warps --------------------
// smem: Ab[34816] Xs[50176] ats[256] = 85248 B
__global__ __launch_bounds__(512, 1)
void augru_scan_mma(const __nv_bfloat16* __restrict__ X3, const uint32_t* __restrict__ Bpack) {
  extern __shared__ char smc[];
  __nv_bfloat16* Ab = (__nv_bfloat16*)smc;
  __nv_bfloat16* Xs = (__nv_bfloat16*)(smc + 34816);
  float* ats_s = (float*)(smc + 34816 + 50176);   // 2 x 32
  const int tid = threadIdx.x;   // 512
  const int w2 = tid >> 5, lane = tid & 31;
  const int w = w2 >> 1, ntw = w2 & 1;
  const int g = lane >> 2, t4 = lane & 3;
  const int b0 = blockIdx.x * 32;
  const int csub = w2*8 + 2*t4;
  uint2 breg[24];
  #pragma unroll
  for (int k16=0;k16<8;++k16)
    #pragma unroll
    for (int j=0;j<3;++j)
      breg[k16*3+j] = ((const uint2*)Bpack)[(((k16*24) + j*8 + w)*32 + lane)*2 + ntw];
  for (int i = tid; i < A_BUF; i += 512) ((uint32_t*)Ab)[i] = 0u;
  #pragma unroll
  for (int it = 0; it < 3; ++it) {
    int f = it*512 + tid;
    int r = f / 48, q = f % 48;
    uint4 v = *(const uint4*)(X3 + ((long long)(b0+r)*T + 0)*N3 + q*8);
    *(uint4*)(Xs + r*XS_STRIDE + q*8) = v;
  }
  if (tid < 32) ats_s[tid] = g_ats[(long long)(b0+tid)*T + 0];
  float h[2][2][2];
  #pragma unroll
  for (int a1=0;a1<2;a1++)
    #pragma unroll
    for (int a2=0;a2<2;a2++) { h[a1][a2][0]=0.f; h[a1][a2][1]=0.f; }
  const uint32_t abb = cvta_s(Ab);
  __syncthreads();

  for (int t = 0; t < T; ++t) {
    if (t + 1 < T) {
      __nv_bfloat16* Xw = Xs + ((t+1) & 1) * XS_BUF;
      #pragma unroll
      for (int it = 0; it < 3; ++it) {
        int f = it*512 + tid;
        int r = f / 48, q = f % 48;
        uint4 v = *(const uint4*)(X3 + ((long long)(b0+r)*T + t+1)*N3 + q*8);
        *(uint4*)(Xw + r*XS_STRIDE + q*8) = v;
      }
      if (tid < 32) ats_s[((t+1)&1)*32 + tid] = g_ats[(long long)(b0+tid)*T + t+1];
    }
    const __nv_bfloat16* Xc = Xs + (t & 1) * XS_BUF;
    const float* atc = ats_s + (t & 1) * 32;
    const uint32_t arb = abb + (uint32_t)((t & 1) * A_BUF * 2);
    __nv_bfloat16* Aw = Ab + ((t & 1) ^ 1) * A_BUF;
    float2 xu[2][2], xr[2][2], xc[2][2];
    float at[2][2];
    #pragma unroll
    for (int mt=0;mt<2;mt++)
      #pragma unroll
      for (int rh=0;rh<2;rh++) {
        at[mt][rh] = atc[mt*16 + rh*8 + g];
        const __nv_bfloat16* xp = Xc + (mt*16 + rh*8 + g)*XS_STRIDE + csub;
        xu[mt][rh] = bf2f(*(const uint32_t*)(xp));
        xr[mt][rh] = bf2f(*(const uint32_t*)(xp + 128));
        xc[mt][rh] = bf2f(*(const uint32_t*)(xp + 256));
      }
    float acc[2][3][4];
    #pragma unroll
    for (int mt=0;mt<2;mt++)
      #pragma unroll
      for (int j=0;j<3;j++)
        #pragma unroll
        for (int q=0;q<4;q++) acc[mt][j][q] = 0.f;
    #pragma unroll
    for (int k16=0;k16<8;++k16) {
      uint32_t a[2][4];
      #pragma unroll
      for (int mt=0;mt<2;mt++)
        ldsm4(a[mt], arb + ((mt*16 + (lane & 15))*A_STRIDE + k16*16 + ((lane >> 4) << 3))*2);
      #pragma unroll
      for (int mt=0;mt<2;mt++)
        #pragma unroll
        for (int j=0;j<3;j++)
          mma16(acc[mt][j], a[mt], (const uint32_t*)&breg[k16*3+j]);
    }
    #pragma unroll
    for (int mt=0;mt<2;mt++)
      #pragma unroll
      for (int rh=0;rh<2;rh++) {
        int row = mt*16 + rh*8 + g;
        float atv = at[mt][rh];
        float hn0, hn1;
        {
          float u  = sigt(xu[mt][rh].x + acc[mt][0][rh*2]);
          float r  = sigt(xr[mt][rh].x + acc[mt][1][rh*2]);
          float cc = tanha(xc[mt][rh].x + r*acc[mt][2][rh*2]);
          float uu = atv*u;
          float ho = h[mt][rh][0];
          hn0 = (1.f - uu)*ho + uu*cc;
          h[mt][rh][0] = hn0;
        }
        {
          float u  = sigt(xu[mt][rh].y + acc[mt][0][rh*2+1]);
          float r  = sigt(xr[mt][rh].y + acc[mt][1][rh*2+1]);
          float cc = tanha(xc[mt][rh].y + r*acc[mt][2][rh*2+1]);
          float uu = atv*u;
          float ho = h[mt][rh][1];
          hn1 = (1.f - uu)*ho + uu*cc;
          h[mt][rh][1] = hn1;
        }
        *(uint32_t*)(Aw + row*A_STRIDE + csub) = bf2(hn0, hn1);
      }
    __syncthreads();
  }
  #pragma unroll
  for (int mt=0;mt<2;mt++)
    #pragma unroll
    for (int rh=0;rh<2;rh++) {
      int row = mt*16 + rh*8 + g;
      float2 o = {h[mt][rh][0], h[mt][rh][1]};
      *(float2*)(g_hfin + (long long)(b0+row)*128 + csub) = o;
    }
}

// ------------- fused attention (bf16): hs,news -> a1 -> a2 -> ats -------------
#define ATT_AS 264   // As stride (bf16)
__global__ __launch_bounds__(256, 1)
void att_fused(const __nv_bfloat16* __restrict__ hsb, const float* __restrict__ inputs,
               const uint32_t* __restrict__ Wcatp, const uint32_t* __restrict__ W2p,
               const float* __restrict__ b2, const float* __restrict__ W3,
               const float* __restrict__ b3, const float* __restrict__ nterm) {
  extern __shared__ char smc[];
  __nv_bfloat16* As  = (__nv_bfloat16*)smc;            // 64 x 264
  uint32_t* Wc  = (uint32_t*)(smc + 33792);            // 16384 u32
  __nv_bfloat16* a1s = (__nv_bfloat16*)(smc + 99328);  // 64 x 136
  uint32_t* W2s = (uint32_t*)(smc + 116736);           // 4096 u32
  float* a2s = (float*)(smc + 133120);                 // 64 x 68
  float* W3s = (float*)(smc + 150528);                 // 64
  const int tid = threadIdx.x;     // 256
  const int lane = tid & 31, wid = tid >> 5;
  const int wm = wid & 1, wn = wid >> 1;
  const int wm3 = wid & 3, wn3 = wid >> 2;
  const int g = lane >> 2, t4 = lane & 3;
  const float b3v = b3[0];

  {
    const uint4* src = (const uint4*)Wcatp;
    uint4* dst = (uint4*)Wc;
    #pragma unroll
    for (int it = 0; it < 16; ++it) dst[it*256 + tid] = src[it*256 + tid];
    const uint4* src2 = (const uint4*)W2p;
    uint4* dst2 = (uint4*)W2s;
    #pragma unroll
    for (int it = 0; it < 4; ++it) dst2[it*256 + tid] = src2[it*256 + tid];
    if (tid < 64) W3s[tid] = W3[tid];
  }
  const uint32_t asb = cvta_s(As);
  const uint32_t a1b = cvta_s(a1s);
  const uint4* Wc4 = (const uint4*)Wc;
  const uint4* W2p4 = (const uint4*)W2s;

  for (long long blk = blockIdx.x; blk < BT/64; blk += gridDim.x) {
    const long long m0 = blk * 64;
    __syncthreads();
    #pragma unroll
    for (int it = 0; it < 8; ++it) {
      int idx = it*256 + tid;
      int r = idx >> 5, q = idx & 31;
      long long row = m0 + r;
      const __nv_bfloat16* hp = hsb + row*128;
      if (q < 16) {
        uint4 v = *(const uint4*)(hp + q*8);
        *(uint4*)(As + r*ATT_AS + q*8) = v;
      } else {
        int qq = q - 16;
        int b = (int)(row / T);
        uint4 v = *(const uint4*)(hp + qq*8);
        const float* nw = inputs + ((long long)b*(T+1) + T)*128 + qq*8;
        float4 n0 = *(const float4*)(nw);
        float4 n1 = *(const float4*)(nw + 4);
        float2 h0 = bf2f(v.x), h1 = bf2f(v.y), h2 = bf2f(v.z), h3 = bf2f(v.w);
        uint4 o;
        o.x = bf2(h0.x*n0.x, h0.y*n0.y);
        o.y = bf2(h1.x*n0.z, h1.y*n0.w);
        o.z = bf2(h2.x*n1.x, h2.y*n1.y);
        o.w = bf2(h3.x*n1.z, h3.y*n1.w);
        *(uint4*)(As + r*ATT_AS + 128 + qq*8) = o;
      }
    }
    __syncthreads();
    float acc[2][4][4];
    #pragma unroll
    for (int mt=0;mt<2;mt++)
      #pragma unroll
      for (int nt=0;nt<4;nt++)
        #pragma unroll
        for (int q=0;q<4;q++) acc[mt][nt][q] = 0.f;
    #pragma unroll
    for (int k16 = 0; k16 < 16; ++k16) {
      uint32_t a[2][4];
      #pragma unroll
      for (int mt=0;mt<2;mt++)
        ldsm4(a[mt], asb + ((wm*32 + mt*16 + (lane & 15))*ATT_AS + k16*16 + ((lane >> 4) << 3))*2);
      uint4 b40 = Wc4[(k16*8 + wn*2    )*32 + lane];
      uint4 b41 = Wc4[(k16*8 + wn*2 + 1)*32 + lane];
      uint32_t bb[4][2];
      bb[0][0]=b40.x; bb[0][1]=b40.y; bb[1][0]=b40.z; bb[1][1]=b40.w;
      bb[2][0]=b41.x; bb[2][1]=b41.y; bb[3][0]=b41.z; bb[3][1]=b41.w;
      #pragma unroll
      for (int mt=0;mt<2;mt++)
        #pragma unroll
        for (int nt=0;nt<4;nt++)
          mma16(acc[mt][nt], a[mt], bb[nt]);
    }
    #pragma unroll
    for (int mt=0;mt<2;mt++) {
      int row0 = wm*32 + mt*16 + g;
      #pragma unroll
      for (int nt=0;nt<4;nt++) {
        int col = wn*32 + nt*8 + 2*t4;
        #pragma unroll
        for (int h=0; h<2; ++h) {
          int row = row0 + 8*h;
          long long rowg = m0 + row;
          const float* np = nterm + (long long)(rowg / T)*128;
          float v0 = fmaxf(acc[mt][nt][2*h+0] + np[col],   0.f);
          float v1 = fmaxf(acc[mt][nt][2*h+1] + np[col+1], 0.f);
          *(uint32_t*)(a1s + row*A_STRIDE + col) = bf2(v0, v1);
        }
      }
    }
    __syncthreads();
    {
      float acc2[4][4];
      #pragma unroll
      for (int nt=0;nt<4;nt++)
        #pragma unroll
        for (int q=0;q<4;q++) acc2[nt][q] = 0.f;
      #pragma unroll
      for (int k16 = 0; k16 < 8; ++k16) {
        uint32_t a[4];
        ldsm4(a, a1b + ((wm3*16 + (lane & 15))*A_STRIDE + k16*16 + ((lane >> 4) << 3))*2);
        uint4 b40 = W2p4[(k16*4 + wn3*2    )*32 + lane];
        uint4 b41 = W2p4[(k16*4 + wn3*2 + 1)*32 + lane];
        uint32_t bb[4][2];
        bb[0][0]=b40.x; bb[0][1]=b40.y; bb[1][0]=b40.z; bb[1][1]=b40.w;
        bb[2][0]=b41.x; bb[2][1]=b41.y; bb[3][0]=b41.z; bb[3][1]=b41.w;
        #pragma unroll
        for (int nt=0;nt<4;nt++)
          mma16(acc2[nt], a, bb[nt]);
      }
      #pragma unroll
      for (int nt=0;nt<4;nt++) {
        int col = wn3*32 + nt*8 + 2*t4;
        float bc0 = b2[col], bc1 = b2[col+1];
        #pragma unroll
        for (int h=0; h<2; ++h) {
          int row = wm3*16 + g + 8*h;
          a2s[row*68 + col]     = fmaxf(acc2[nt][2*h+0] + bc0, 0.f);
          a2s[row*68 + col + 1] = fmaxf(acc2[nt][2*h+1] + bc1, 0.f);
        }
      }
    }
    __syncthreads();
    if (tid < 64) {
      float accv = b3v;
      #pragma unroll 8
      for (int cc=0; cc<64; ++cc) accv = fmaf(a2s[tid*68 + cc], W3s[cc], accv);
      g_ats[m0 + tid] = sigf(accv);
    }
  }
}

// ------------------------------ head ------------------------------
__global__ void head_kernel(const float* __restrict__ inputs,
                            const float* __restrict__ gamma, const float* __restrict__ beta,
                            const float* __restrict__ mean,  const float* __restrict__ var,
                            const float* __restrict__ W1, const float* __restrict__ bb1,
                            const float* __restrict__ W2, const float* __restrict__ bb2,
                            const float* __restrict__ fW, const float* __restrict__ fb,
                            float* __restrict__ out) {
  extern __shared__ float sm[];
  float* xs  = sm;          // 32*256
  float* y1s = xs + 8192;   // 32*256
  float* y2s = y1s + 8192;  // 32*128
  const int tid = threadIdx.x;   // 256
  const int b0 = blockIdx.x * 32;
  for (int r = 0; r < 32; ++r) {
    int k = tid;
    int bb = b0 + r;
    float v = (k < 128) ? g_hfin[bb*128 + k]
                        : inputs[((long long)bb*(T+1) + T)*128 + (k - 128)];
    float nv = (v - mean[k]) * rsqrtf(var[k] + BN_EPS) * gamma[k] + beta[k];
    xs[r*256 + k] = nv;
  }
  __syncthreads();
  {
    float acc[32];
    #pragma unroll
    for (int r=0;r<32;r++) acc[r] = bb1[tid];
    for (int k=0;k<256;++k) {
      float w = W1[k*256 + tid];
      #pragma unroll
      for (int r=0;r<32;r++) acc[r] = fmaf(xs[r*256+k], w, acc[r]);
    }
    #pragma unroll
    for (int r=0;r<32;r++) {
      float v = acc[r];
      y1s[r*256 + tid] = v >= 0.f ? v : LEAKY*v;
    }
  }
  __syncthreads();
  if (tid < 128) {
    float acc[32];
    #pragma unroll
    for (int r=0;r<32;r++) acc[r] = bb2[tid];
    for (int k=0;k<256;++k) {
      float w = W2[k*128 + tid];
      #pragma unroll
      for (int r=0;r<32;r++) acc[r] = fmaf(y1s[r*256+k], w, acc[r]);
    }
    #pragma unroll
    for (int r=0;r<32;r++) {
      float v = acc[r];
      y2s[r*128 + tid] = v >= 0.f ? v : LEAKY*v;
    }
  }
  __syncthreads();
  if (tid < 32) {
    float acc = fb[0];
    for (int k=0;k<128;++k) acc = fmaf(y2s[tid*128+k], fW[k], acc);
    out[b0 + tid] = sigf(acc);
  }
}

// ------------------------------ launch ------------------------------
extern "C" void kernel_launch(void* const* d_in, const int* in_sizes, int n_in,
                              void* d_out, int out_size) {
  (void)in_sizes; (void)n_in; (void)out_size;
  const float* inputs  = (const float*)d_in[0];
  const float* gru_W   = (const float*)d_in[1];
  const float* gru_U   = (const float*)d_in[2];
  const float* gru_b   = (const float*)d_in[3];
  const float* att_W1  = (const float*)d_in[4];
  const float* att_b1  = (const float*)d_in[5];
  const float* att_W2  = (const float*)d_in[6];
  const float* att_b2  = (const float*)d_in[7];
  const float* att_W3  = (const float*)d_in[8];
  const float* att_b3  = (const float*)d_in[9];
  const float* au_Wu   = (const float*)d_in[10];
  const float* au_bu   = (const float*)d_in[11];
  const float* au_Uu   = (const float*)d_in[12];
  const float* au_Wr   = (const float*)d_in[13];
  const float* au_br   = (const float*)d_in[14];
  const float* au_Ur   = (const float*)d_in[15];
  const float* au_Wc   = (const float*)d_in[16];
  const float* au_bc   = (const float*)d_in[17];
  const float* au_Uc   = (const float*)d_in[18];
  const float* bn_gamma= (const float*)d_in[19];
  const float* bn_beta = (const float*)d_in[20];
  const float* bn_mean = (const float*)d_in[21];
  const float* bn_var  = (const float*)d_in[22];
  const float* d_W1    = (const float*)d_in[23];
  const float* d_b1    = (const float*)d_in[24];
  const float* d_W2    = (const float*)d_in[25];
  const float* d_b2    = (const float*)d_in[26];
  const float* f_W     = (const float*)d_in[27];
  const float* f_b     = (const float*)d_in[28];
  float* out = (float*)d_out;

  const size_t sm_gemm  = 64*GAS*2 + 8192*4;                 // 50176
  const size_t sm_gru   = 34816 + 50176;                     // 84992
  const size_t sm_au    = 34816 + 50176 + 256;               // 85248
  const size_t sm_attf  = 150784;
  const size_t sm_head  = (8192*2 + 4096)*sizeof(float);
  cudaFuncSetAttribute(gemm_bf16,      cudaFuncAttributeMaxDynamicSharedMemorySize, (int)sm_gemm);
  cudaFuncSetAttribute(gru_scan_mma,   cudaFuncAttributeMaxDynamicSharedMemorySize, (int)sm_gru);
  cudaFuncSetAttribute(augru_scan_mma, cudaFuncAttributeMaxDynamicSharedMemorySize, (int)sm_au);
  cudaFuncSetAttribute(att_fused,      cudaFuncAttributeMaxDynamicSharedMemorySize, (int)sm_attf);
  cudaFuncSetAttribute(head_kernel,    cudaFuncAttributeMaxDynamicSharedMemorySize, (int)sm_head);

  float *p_Xp, *p_X3, *p_newsterm, *p_bau;
  __nv_bfloat16 *p_hsb;
  uint32_t *p_Ubg, *p_Uba, *p_WbgW, *p_Wbau, *p_Wb1bc, *p_Wbcat, *p_Wbatt2;
  cudaGetSymbolAddress((void**)&p_Xp,       g_Xp);
  cudaGetSymbolAddress((void**)&p_hsb,      g_hsb);
  cudaGetSymbolAddress((void**)&p_X3,       g_X3);
  cudaGetSymbolAddress((void**)&p_newsterm, g_newsterm);
  cudaGetSymbolAddress((void**)&p_bau,      g_bau);
  cudaGetSymbolAddress((void**)&p_Ubg,      g_Ubf_gru);
  cudaGetSymbolAddress((void**)&p_Uba,      g_Ubf_au);
  cudaGetSymbolAddress((void**)&p_WbgW,     g_Wb_gruW);
  cudaGetSymbolAddress((void**)&p_Wbau,     g_Wb_au);
  cudaGetSymbolAddress((void**)&p_Wb1bc,    g_Wb_1bc);
  cudaGetSymbolAddress((void**)&p_Wbcat,    g_Wb_cat);
  cudaGetSymbolAddress((void**)&p_Wbatt2,   g_Wb_att2);

  cudaStream_t s2;
  cudaStreamCreateWithFlags(&s2, cudaStreamNonBlocking);
  cudaEvent_t evPack, evNews, evFork, evJoin;
  cudaEventCreateWithFlags(&evPack, cudaEventDisableTiming);
  cudaEventCreateWithFlags(&evNews, cudaEventDisableTiming);
  cudaEventCreateWithFlags(&evFork, cudaEventDisableTiming);
  cudaEventCreateWithFlags(&evJoin, cudaEventDisableTiming);

  // 1) fold weights, then all bf16 fragment packs
  prep_kernel<<<192, 256>>>(au_Wu, au_bu, au_Wr, au_br, au_Wc, au_bc,
                            au_Uu, au_Ur, au_Uc, att_W1);
  pack_all<<<496, 256>>>(gru_U, gru_W, att_W2);
  cudaEventRecord(evPack, 0);
  cudaStreamWaitEvent(s2, evPack, 0);
  // 2) newsterm = news @ (W1B+W1C) + b1  (side stream; fp32 out)
  gemm_bf16<<<dim3(B/64, 1), 256, sm_gemm, s2>>>(inputs + (long long)T*128, 1, (long long)(T+1)*128, 128,
                                                 p_Wb1bc, 8, att_b1, p_newsterm, 128, 0, 0);
  cudaEventRecord(evNews, s2);
  // 3) Xp = hist @ gru_W + gru_b[0]   (bf16 out)
  gemm_bf16<<<dim3(BT/64, 3), 256, sm_gemm>>>(inputs, T, (long long)(T+1)*128, 128,
                                              p_WbgW, 24, gru_b, p_Xp, 384, 1, 0);
  // 4) GRU recurrence -> hsb (bf16, 512-thread nt-split)
  gru_scan_mma<<<B/32, 512, sm_gru>>>((const __nv_bfloat16*)p_Xp, p_Ubg, gru_b + 384, p_hsb);
  // fork: X3 gemm on s2, attention on main stream
  cudaEventRecord(evFork, 0);
  cudaStreamWaitEvent(s2, evFork, 0);
  // 5) X3 = hsb @ [Wu|Wr|Wc] + [bu|br|bc]   (side stream; bf16 A + bf16 out)
  gemm_bf16<<<dim3(BT/64, 3), 256, sm_gemm, s2>>>(p_hsb, 1<<30, 0LL, 128,
                                                  p_Wbau, 24, p_bau, p_X3, 384, 1, 1);
  cudaEventRecord(evJoin, s2);
  // 6) fused attention -> g_ats  (main stream; needs newsterm)
  cudaStreamWaitEvent(0, evNews, 0);
  att_fused<<<148, 256, sm_attf>>>(p_hsb, inputs, p_Wbcat, p_Wbatt2,
                                   att_b2, att_W3, att_b3, p_newsterm);
  cudaStreamWaitEvent(0, evJoin, 0);
  // 7) AUGRU recurrence -> hfin (512-thread nt-split)
  augru_scan_mma<<<B/32, 512, sm_au>>>((const __nv_bfloat16*)p_X3, p_Uba);
  // 8) BN + dense head -> out
  head_kernel<<<B/32, 256, sm_head>>>(inputs, bn_gamma, bn_beta, bn_mean, bn_var,
                                      d_W1, d_b1, d_W2, d_b2, f_W, f_b, out);
}

// round 15
// speedup vs baseline: 1.5229x; 1.0153x over previous
#include <cuda_runtime.h>
#include <cuda_bf16.h>
#include <math.h>
#include <stdint.h>

#define B  4096
#define T  50
#define U  128
#define N3 384
#define BT (B*T)
#define BN_EPS 1e-3f
#define LEAKY  3e-4f

// ------------ scratch (device globals; no allocation allowed) ------------
__device__ float g_Xp[BT*N3];            // GRU input projection (bf16 payload)
__device__ __nv_bfloat16 g_hsb[BT*U];    // GRU hidden states (bf16)
__device__ float g_X3[BT*N3];            // AUGRU input projections (bf16 payload)
__device__ float g_ats[BT];              // attention scores
__device__ float g_hfin[B*U];            // AUGRU final state
__device__ float g_newsterm[B*U];        // news@(W1B+W1C)+b1
__device__ float g_Wau[U*N3];            // packed input  [Wu|Wr|Wc]
__device__ float g_Uau[U*N3];            // packed recur  [Uu|Ur|Uc]
__device__ float g_bau[N3];              // packed [bu|br|bc]
__device__ float g_Wcat[2*U*U];          // [W1A-W1B ; W1D]  (256 x 128)
__device__ float g_W1bc[U*U];            // W1B + W1C
__device__ uint32_t g_Ubf_gru[24576];    // bf16 frag gru_U
__device__ uint32_t g_Ubf_au[24576];     // bf16 frag [Uu|Ur|Uc]
__device__ uint32_t g_Wb_gruW[24576];    // bf16 frag gru_W     (K=128,N=384)
__device__ uint32_t g_Wb_au[24576];      // bf16 frag [Wu|Wr|Wc]
__device__ uint32_t g_Wb_1bc[8192];      // bf16 frag W1B+W1C   (K=128,N=128)
__device__ uint32_t g_Wb_cat[16384];     // bf16 frag Wcat      (K=256,N=128)
__device__ uint32_t g_Wb_att2[4096];     // bf16 frag att_W2    (K=128,N=64)

__device__ __forceinline__ float sigf(float x){ return 1.f/(1.f+expf(-x)); }
__device__ __forceinline__ float tanha(float x){
  float y; asm("tanh.approx.f32 %0, %1;" : "=f"(y) : "f"(x)); return y;
}
__device__ __forceinline__ float sigt(float x){ return fmaf(tanha(0.5f*x), 0.5f, 0.5f); }
__device__ __forceinline__ uint32_t bf2(float lo, float hi){
  __nv_bfloat162 v;
  v.x = __float2bfloat16(lo); v.y = __float2bfloat16(hi);
  return *(uint32_t*)&v;
}
__device__ __forceinline__ float2 bf2f(uint32_t u){
  __nv_bfloat162 v = *(__nv_bfloat162*)&u;
  return __bfloat1622float2(v);
}
__device__ __forceinline__ uint32_t cvta_s(const void* p){
  return (uint32_t)__cvta_generic_to_shared(p);
}
__device__ __forceinline__ void ldsm4(uint32_t* r, uint32_t addr){
  asm volatile("ldmatrix.sync.aligned.m8n8.x4.shared.b16 {%0,%1,%2,%3}, [%4];"
               : "=r"(r[0]), "=r"(r[1]), "=r"(r[2]), "=r"(r[3]) : "r"(addr));
}
__device__ __forceinline__ void mma16(float* d, const uint32_t* a, const uint32_t* b){
  asm volatile("mma.sync.aligned.m16n8k16.row.col.f32.bf16.bf16.f32 "
               "{%0,%1,%2,%3}, {%4,%5,%6,%7}, {%8,%9}, {%0,%1,%2,%3};"
               : "+f"(d[0]), "+f"(d[1]), "+f"(d[2]), "+f"(d[3])
               : "r"(a[0]), "r"(a[1]), "r"(a[2]), "r"(a[3]), "r"(b[0]), "r"(b[1]));
}

// ------------------------------- prep -------------------------------
__global__ void prep_kernel(const float* __restrict__ Wu, const float* __restrict__ bu,
                            const float* __restrict__ Wr, const float* __restrict__ br,
                            const float* __restrict__ Wc, const float* __restrict__ bc,
                            const float* __restrict__ Uu, const float* __restrict__ Ur,
                            const float* __restrict__ Uc,
                            const float* __restrict__ attW1) {
  int id = blockIdx.x*blockDim.x + threadIdx.x;
  if (id < U*N3) {
    int k = id / N3, c = id % N3;
    float w, u;
    if (c < 128)      { w = Wu[k*128 + c];       u = Uu[k*128 + c]; }
    else if (c < 256) { w = Wr[k*128 + (c-128)]; u = Ur[k*128 + (c-128)]; }
    else              { w = Wc[k*128 + (c-256)]; u = Uc[k*128 + (c-256)]; }
    g_Wau[id] = w;
    g_Uau[id] = u;
  }
  if (id < N3)
    g_bau[id] = (id < 128) ? bu[id] : (id < 256 ? br[id-128] : bc[id-256]);
  if (id < 2*U*U) {
    int k = id / 128, c = id % 128;
    float v;
    if (k < 128) v = attW1[k*128 + c] - attW1[U*U + k*128 + c];     // W1A - W1B
    else         v = attW1[3*U*U + (k-128)*128 + c];                // W1D
    g_Wcat[id] = v;
  }
  if (id < U*U)
    g_W1bc[id] = attW1[U*U + id] + attW1[2*U*U + id];
}

// --------------- pack weights bf16 fragment-ordered ---------------
__device__ __forceinline__ void pack_bf16_n(const float* __restrict__ Um,
                                            uint32_t* __restrict__ P, int N, int idx) {
  int q = idx & 3, lane = (idx >> 2) & 31;
  int Ntp = N >> 4;
  int tp = (idx >> 7) % Ntp, k16 = (idx >> 7) / Ntp;
  int tile = 2*tp + (q >> 1), r = q & 1;
  int k = k16*16 + 2*(lane & 3) + 8*r;
  int n = tile*8 + (lane >> 2);
  P[idx] = bf2(Um[k*N + n], Um[(k+1)*N + n]);
}

// pack_a: independent of prep (raw inputs)
__global__ void pack_a(const float* __restrict__ gruU, const float* __restrict__ gruW,
                       const float* __restrict__ attW2) {
  int idx = blockIdx.x*256 + threadIdx.x;   // 53248 total
  if (idx < 24576)        pack_bf16_n(gruU,  g_Ubf_gru, 384, idx);
  else if (idx < 49152)   pack_bf16_n(gruW,  g_Wb_gruW, 384, idx - 24576);
  else if (idx < 53248)   pack_bf16_n(attW2, g_Wb_att2, 64,  idx - 49152);
}
// pack_b: consumes prep outputs
__global__ void pack_b() {
  int idx = blockIdx.x*256 + threadIdx.x;   // 73728 total
  if (idx < 24576)        pack_bf16_n(g_Uau,  g_Ubf_au, 384, idx);
  else if (idx < 49152)   pack_bf16_n(g_Wau,  g_Wb_au,  384, idx - 24576);
  else if (idx < 57344)   pack_bf16_n(g_W1bc, g_Wb_1bc, 128, idx - 49152);
  else if (idx < 73728)   pack_bf16_n(g_Wcat, g_Wb_cat, 128, idx - 57344);
}

// --------------------- bf16 GEMM, A-resident, N-chunk loop, K=128 ---------------------
// grid = M/64. Computes all Ntp*16 output columns; A read once per CTA.
// obf=0: C fp32 direct.  obf=1: C bf16, SMEM-staged coalesced stores.
#define GAS 136   // As stride (bf16)
__global__ void gemm_bf16(const void* __restrict__ A, int P, long long GS, int RS,
                          const uint32_t* __restrict__ Bpk, int Ntp,
                          const float* __restrict__ bias, void* __restrict__ C, int ldc,
                          int obf, int abf) {
  extern __shared__ char smc[];
  __nv_bfloat16* As = (__nv_bfloat16*)smc;          // 64 x GAS  (17408 B)
  uint32_t* Bp = (uint32_t*)(smc + 17408);          // 8192 u32  (32768 B)
  uint32_t* Cs = (uint32_t*)(smc + 50176);          // 64 x 65 u32 (16640 B)
  const int m0 = blockIdx.x * 64;
  const int tid = threadIdx.x;          // 256
  const int kq = tid >> 5, cq = tid & 31;
  const int lane = tid & 31, wid = tid >> 5;
  const int wm = wid & 1, wn = wid >> 1;
  const int g = lane >> 2, t4 = lane & 3;

  if (abf) {
    #pragma unroll
    for (int it = 0; it < 4; ++it) {
      int f = it*256 + tid;
      int r = f >> 4, q = f & 15;
      int m = m0 + r;
      const __nv_bfloat16* ap = (const __nv_bfloat16*)A + (long long)(m/P)*GS + (long long)(m%P)*RS;
      uint4 v = *(const uint4*)(ap + q*8);
      *(uint4*)(As + r*GAS + q*8) = v;
    }
  } else {
    #pragma unroll
    for (int it = 0; it < 8; ++it) {
      int r = kq + 8*it;
      int m = m0 + r;
      const float* ap = (const float*)A + (long long)(m/P)*GS + (long long)(m%P)*RS;
      float4 v = *(const float4*)(ap + 4*cq);
      uint32_t* dst = (uint32_t*)(As + r*GAS + 4*cq);
      dst[0] = bf2(v.x, v.y);
      dst[1] = bf2(v.z, v.w);
    }
  }
  const uint32_t asb = cvta_s(As);
  const int nch = Ntp >> 3;
  for (int cc = 0; cc < nch; ++cc) {
    const int tp0 = cc*8, c0 = cc*128;
    if (cc) __syncthreads();   // prior Bp reads + Cs stores done
    {
      const uint4* src = (const uint4*)Bpk;
      uint4* dst = (uint4*)Bp;
      #pragma unroll
      for (int it = 0; it < 8; ++it) {
        int f = it*256 + tid;
        int k16 = f >> 8, rem = f & 255;
        dst[f] = src[((long long)k16*Ntp + tp0)*32 + rem];
      }
    }
    __syncthreads();
    float acc[2][4][4];
    #pragma unroll
    for (int mt=0;mt<2;mt++)
      #pragma unroll
      for (int nt=0;nt<4;nt++)
        #pragma unroll
        for (int q=0;q<4;q++) acc[mt][nt][q] = 0.f;
    const uint4* bp4 = (const uint4*)Bp;
    #pragma unroll
    for (int k16 = 0; k16 < 8; ++k16) {
      uint32_t a[2][4];
      #pragma unroll
      for (int mt=0;mt<2;mt++)
        ldsm4(a[mt], asb + ((wm*32 + mt*16 + (lane & 15))*GAS + k16*16 + ((lane >> 4) << 3))*2);
      uint4 b40 = bp4[(k16*8 + wn*2    )*32 + lane];
      uint4 b41 = bp4[(k16*8 + wn*2 + 1)*32 + lane];
      uint32_t bb[4][2];
      bb[0][0]=b40.x; bb[0][1]=b40.y; bb[1][0]=b40.z; bb[1][1]=b40.w;
      bb[2][0]=b41.x; bb[2][1]=b41.y; bb[3][0]=b41.z; bb[3][1]=b41.w;
      #pragma unroll
      for (int mt=0;mt<2;mt++)
        #pragma unroll
        for (int nt=0;nt<4;nt++)
          mma16(acc[mt][nt], a[mt], bb[nt]);
    }
    if (obf) {
      #pragma unroll
      for (int mt=0;mt<2;mt++) {
        int row0 = wm*32 + mt*16 + g;
        #pragma unroll
        for (int nt=0;nt<4;nt++) {
          int col = wn*32 + nt*8 + 2*t4;
          float bc0 = bias[c0+col], bc1 = bias[c0+col+1];
          #pragma unroll
          for (int h=0; h<2; ++h) {
            int row = row0 + 8*h;
            Cs[row*65 + (col >> 1)] = bf2(acc[mt][nt][2*h+0] + bc0, acc[mt][nt][2*h+1] + bc1);
          }
        }
      }
      __syncthreads();
      #pragma unroll
      for (int it = 0; it < 16; ++it) {
        int f = it*256 + tid;
        int r = f >> 6, q = f & 63;
        *(uint32_t*)((__nv_bfloat16*)C + (long long)(m0+r)*ldc + c0 + 2*q) = Cs[r*65 + q];
      }
    } else {
      #pragma unroll
      for (int mt=0;mt<2;mt++) {
        int row0 = m0 + wm*32 + mt*16 + g;
        #pragma unroll
        for (int nt=0;nt<4;nt++) {
          int col = c0 + wn*32 + nt*8 + 2*t4;
          float bc0 = bias[col], bc1 = bias[col+1];
          #pragma unroll
          for (int h=0; h<2; ++h) {
            int row = row0 + 8*h;
            float2 o = {acc[mt][nt][2*h+0] + bc0, acc[mt][nt][2*h+1] + bc1};
            *(float2*)((float*)C + (long long)row*ldc + col) = o;
          }
        }
      }
    }
  }
}

// -------------------- GRU scan, 512 thr, nt-split warps (32 rows/CTA) --------------------
#define A_STRIDE 136
#define A_BUF    (32*A_STRIDE)
#define XS_STRIDE 392
#define XS_BUF   (32*XS_STRIDE)
__global__ __launch_bounds__(512, 1)
void gru_scan_mma(const __nv_bfloat16* __restrict__ Xp, const uint32_t* __restrict__ Bpack,
                  const float* __restrict__ brec, __nv_bfloat16* __restrict__ hsb) {
  extern __shared__ char smc[];
  __nv_bfloat16* Ab = (__nv_bfloat16*)smc;
  __nv_bfloat16* Xs = (__nv_bfloat16*)(smc + 34816);
  const int tid = threadIdx.x;    // 512
  const int w2 = tid >> 5, lane = tid & 31;
  const int w = w2 >> 1, ntw = w2 & 1;
  const int g = lane >> 2, t4 = lane & 3;
  const int b0 = blockIdx.x * 32;
  const int csub = w2*8 + 2*t4;
  uint2 breg[24];
  #pragma unroll
  for (int k16=0;k16<8;++k16)
    #pragma unroll
    for (int j=0;j<3;++j)
      breg[k16*3+j] = ((const uint2*)Bpack)[(((k16*24) + j*8 + w)*32 + lane)*2 + ntw];
  for (int i = tid; i < A_BUF; i += 512) ((uint32_t*)Ab)[i] = 0u;
  #pragma unroll
  for (int it = 0; it < 3; ++it) {
    int f = it*512 + tid;
    int r = f / 48, q = f % 48;
    uint4 v = *(const uint4*)(Xp + ((long long)(b0+r)*T + 0)*N3 + q*8);
    *(uint4*)(Xs + r*XS_STRIDE + q*8) = v;
  }
  float2 bz = *(const float2*)(brec + csub);
  float2 brr = *(const float2*)(brec + 128 + csub);
  float2 bh = *(const float2*)(brec + 256 + csub);
  float h[2][2][2];
  #pragma unroll
  for (int a1=0;a1<2;a1++)
    #pragma unroll
    for (int a2=0;a2<2;a2++) { h[a1][a2][0]=0.f; h[a1][a2][1]=0.f; }
  const uint32_t abb = cvta_s(Ab);
  __syncthreads();

  for (int t = 0; t < T; ++t) {
    if (t + 1 < T) {
      __nv_bfloat16* Xw = Xs + ((t+1) & 1) * XS_BUF;
      #pragma unroll
      for (int it = 0; it < 3; ++it) {
        int f = it*512 + tid;
        int r = f / 48, q = f % 48;
        uint4 v = *(const uint4*)(Xp + ((long long)(b0+r)*T + t+1)*N3 + q*8);
        *(uint4*)(Xw + r*XS_STRIDE + q*8) = v;
      }
    }
    if (t >= 1) {
      const uint4* Au = (const uint4*)(Ab + (t & 1) * A_BUF);
      int r = tid >> 4, q = tid & 15;
      *((uint4*)(hsb + ((long long)(b0+r)*T + (t-1))*128) + q) = Au[r*17 + q];
    }
    const __nv_bfloat16* Xc = Xs + (t & 1) * XS_BUF;
    const uint32_t arb = abb + (uint32_t)((t & 1) * A_BUF * 2);
    __nv_bfloat16* Aw = Ab + ((t & 1) ^ 1) * A_BUF;
    float2 xz[2][2], xr[2][2], xh[2][2];
    #pragma unroll
    for (int mt=0;mt<2;mt++)
      #pragma unroll
      for (int rh=0;rh<2;rh++) {
        const __nv_bfloat16* xp = Xc + (mt*16 + rh*8 + g)*XS_STRIDE + csub;
        xz[mt][rh] = bf2f(*(const uint32_t*)(xp));
        xr[mt][rh] = bf2f(*(const uint32_t*)(xp + 128));
        xh[mt][rh] = bf2f(*(const uint32_t*)(xp + 256));
      }
    float acc[2][3][4];
    #pragma unroll
    for (int mt=0;mt<2;mt++)
      #pragma unroll
      for (int j=0;j<3;j++)
        #pragma unroll
        for (int q=0;q<4;q++) acc[mt][j][q] = 0.f;
    #pragma unroll
    for (int k16=0;k16<8;++k16) {
      uint32_t a[2][4];
      #pragma unroll
      for (int mt=0;mt<2;mt++)
        ldsm4(a[mt], arb + ((mt*16 + (lane & 15))*A_STRIDE + k16*16 + ((lane >> 4) << 3))*2);
      #pragma unroll
      for (int mt=0;mt<2;mt++)
        #pragma unroll
        for (int j=0;j<3;j++)
          mma16(acc[mt][j], a[mt], (const uint32_t*)&breg[k16*3+j]);
    }
    #pragma unroll
    for (int mt=0;mt<2;mt++)
      #pragma unroll
      for (int rh=0;rh<2;rh++) {
        int row = mt*16 + rh*8 + g;
        float hn0, hn1;
        {
          float z  = sigt(xz[mt][rh].x + acc[mt][0][rh*2] + bz.x);
          float r  = sigt(xr[mt][rh].x + acc[mt][1][rh*2] + brr.x);
          float hc = tanha(xh[mt][rh].x + r*(acc[mt][2][rh*2] + bh.x));
          float ho = h[mt][rh][0];
          hn0 = z*ho + (1.f - z)*hc;
          h[mt][rh][0] = hn0;
        }
        {
          float z  = sigt(xz[mt][rh].y + acc[mt][0][rh*2+1] + bz.y);
          float r  = sigt(xr[mt][rh].y + acc[mt][1][rh*2+1] + brr.y);
          float hc = tanha(xh[mt][rh].y + r*(acc[mt][2][rh*2+1] + bh.y));
          float ho = h[mt][rh][1];
          hn1 = z*ho + (1.f - z)*hc;
          h[mt][rh][1] = hn1;
        }
        *(uint32_t*)(Aw + row*A_STRIDE + csub) = bf2(hn0, hn1);
      }
    __syncthreads();
  }
  {
    const uint4* Au = (const uint4*)(Ab);
    int r = tid >> 4, q = tid & 15;
    *((uint4*)(hsb + ((long long)(b0+r)*T + (T-1))*128) + q) = Au[r*17 + q];
  }
}

// -------------------- AUGRU scan, 512 thr, nt-split warps --------------------
__global__ __launch_bounds__(512, 1)
void augru_scan_mma(const __nv_bfloat16* __restrict__ X3, const uint32_t* __restrict__ Bpack) {
  extern __shared__ char smc[];
  __nv_bfloat16* Ab = (__nv_bfloat16*)smc;
  __nv_bfloat16* Xs = (__nv_bfloat16*)(smc + 34816);
  float* ats_s = (float*)(smc + 34816 + 50176);
  const int tid = threadIdx.x;
  const int w2 = tid >> 5, lane = tid & 31;
  const int w = w2 >> 1, ntw = w2 & 1;
  const int g = lane >> 2, t4 = lane & 3;
  const int b0 = blockIdx.x * 32;
  const int csub = w2*8 + 2*t4;
  uint2 breg[24];
  #pragma unroll
  for (int k16=0;k16<8;++k16)
    #pragma unroll
    for (int j=0;j<3;++j)
      breg[k16*3+j] = ((const uint2*)Bpack)[(((k16*24) + j*8 + w)*32 + lane)*2 + ntw];
  for (int i = tid; i < A_BUF; i += 512) ((uint32_t*)Ab)[i] = 0u;
  #pragma unroll
  for (int it = 0; it < 3; ++it) {
    int f = it*512 + tid;
    int r = f / 48, q = f % 48;
    uint4 v = *(const uint4*)(X3 + ((long long)(b0+r)*T + 0)*N3 + q*8);
    *(uint4*)(Xs + r*XS_STRIDE + q*8) = v;
  }
  if (tid < 32) ats_s[tid] = g_ats[(long long)(b0+tid)*T + 0];
  float h[2][2][2];
  #pragma unroll
  for (int a1=0;a1<2;a1++)
    #pragma unroll
    for (int a2=0;a2<2;a2++) { h[a1][a2][0]=0.f; h[a1][a2][1]=0.f; }
  const uint32_t abb = cvta_s(Ab);
  __syncthreads();

  for (int t = 0; t < T; ++t) {
    if (t + 1 < T) {
      __nv_bfloat16* Xw = Xs + ((t+1) & 1) * XS_BUF;
      #pragma unroll
      for (int it = 0; it < 3; ++it) {
        int f = it*512 + tid;
        int r = f / 48, q = f % 48;
        uint4 v = *(const uint4*)(X3 + ((long long)(b0+r)*T + t+1)*N3 + q*8);
        *(uint4*)(Xw + r*XS_STRIDE + q*8) = v;
      }
      if (tid < 32) ats_s[((t+1)&1)*32 + tid] = g_ats[(long long)(b0+tid)*T + t+1];
    }
    const __nv_bfloat16* Xc = Xs + (t & 1) * XS_BUF;
    const float* atc = ats_s + (t & 1) * 32;
    const uint32_t arb = abb + (uint32_t)((t & 1) * A_BUF * 2);
    __nv_bfloat16* Aw = Ab + ((t & 1) ^ 1) * A_BUF;
    float2 xu[2][2], xr[2][2], xc[2][2];
    float at[2][2];
    #pragma unroll
    for (int mt=0;mt<2;mt++)
      #pragma unroll
      for (int rh=0;rh<2;rh++) {
        at[mt][rh] = atc[mt*16 + rh*8 + g];
        const __nv_bfloat16* xp = Xc + (mt*16 + rh*8 + g)*XS_STRIDE + csub;
        xu[mt][rh] = bf2f(*(const uint32_t*)(xp));
        xr[mt][rh] = bf2f(*(const uint32_t*)(xp + 128));
        xc[mt][rh] = bf2f(*(const uint32_t*)(xp + 256));
      }
    float acc[2][3][4];
    #pragma unroll
    for (int mt=0;mt<2;mt++)
      #pragma unroll
      for (int j=0;j<3;j++)
        #pragma unroll
        for (int q=0;q<4;q++) acc[mt][j][q] = 0.f;
    #pragma unroll
    for (int k16=0;k16<8;++k16) {
      uint32_t a[2][4];
      #pragma unroll
      for (int mt=0;mt<2;mt++)
        ldsm4(a[mt], arb + ((mt*16 + (lane & 15))*A_STRIDE + k16*16 + ((lane >> 4) << 3))*2);
      #pragma unroll
      for (int mt=0;mt<2;mt++)
        #pragma unroll
        for (int j=0;j<3;j++)
          mma16(acc[mt][j], a[mt], (const uint32_t*)&breg[k16*3+j]);
    }
    #pragma unroll
    for (int mt=0;mt<2;mt++)
      #pragma unroll
      for (int rh=0;rh<2;rh++) {
        int row = mt*16 + rh*8 + g;
        float atv = at[mt][rh];
        float hn0, hn1;
        {
          float u  = sigt(xu[mt][rh].x + acc[mt][0][rh*2]);
          float r  = sigt(xr[mt][rh].x + acc[mt][1][rh*2]);
          float cc = tanha(xc[mt][rh].x + r*acc[mt][2][rh*2]);
          float uu = atv*u;
          float ho = h[mt][rh][0];
          hn0 = (1.f - uu)*ho + uu*cc;
          h[mt][rh][0] = hn0;
        }
        {
          float u  = sigt(xu[mt][rh].y + acc[mt][0][rh*2+1]);
          float r  = sigt(xr[mt][rh].y + acc[mt][1][rh*2+1]);
          float cc = tanha(xc[mt][rh].y + r*acc[mt][2][rh*2+1]);
          float uu = atv*u;
          float ho = h[mt][rh][1];
          hn1 = (1.f - uu)*ho + uu*cc;
          h[mt][rh][1] = hn1;
        }
        *(uint32_t*)(Aw + row*A_STRIDE + csub) = bf2(hn0, hn1);
      }
    __syncthreads();
  }
  #pragma unroll
  for (int mt=0;mt<2;mt++)
    #pragma unroll
    for (int rh=0;rh<2;rh++) {
      int row = mt*16 + rh*8 + g;
      float2 o = {h[mt][rh][0], h[mt][rh][1]};
      *(float2*)(g_hfin + (long long)(b0+row)*128 + csub) = o;
    }
}

// ------------- fused attention (bf16): hs,news -> a1 -> a2 -> ats -------------
#define ATT_AS 264
__global__ __launch_bounds__(256, 1)
void att_fused(const __nv_bfloat16* __restrict__ hsb, const float* __restrict__ inputs,
               const uint32_t* __restrict__ Wcatp, const uint32_t* __restrict__ W2p,
               const float* __restrict__ b2, const float* __restrict__ W3,
               const float* __restrict__ b3, const float* __restrict__ nterm) {
  extern __shared__ char smc[];
  __nv_bfloat16* As  = (__nv_bfloat16*)smc;            // 64 x 264
  uint32_t* Wc  = (uint32_t*)(smc + 33792);            // 16384 u32
  __nv_bfloat16* a1s = (__nv_bfloat16*)(smc + 99328);  // 64 x 136
  uint32_t* W2s = (uint32_t*)(smc + 116736);           // 4096 u32
  float* a2s = (float*)(smc + 133120);                 // 64 x 68
  float* W3s = (float*)(smc + 150528);                 // 64
  const int tid = threadIdx.x;     // 256
  const int lane = tid & 31, wid = tid >> 5;
  const int wm = wid & 1, wn = wid >> 1;
  const int wm3 = wid & 3, wn3 = wid >> 2;
  const int g = lane >> 2, t4 = lane & 3;
  const float b3v = b3[0];

  {
    const uint4* src = (const uint4*)Wcatp;
    uint4* dst = (uint4*)Wc;
    #pragma unroll
    for (int it = 0; it < 16; ++it) dst[it*256 + tid] = src[it*256 + tid];
    const uint4* src2 = (const uint4*)W2p;
    uint4* dst2 = (uint4*)W2s;
    #pragma unroll
    for (int it = 0; it < 4; ++it) dst2[it*256 + tid] = src2[it*256 + tid];
    if (tid < 64) W3s[tid] = W3[tid];
  }
  const uint32_t asb = cvta_s(As);
  const uint32_t a1b = cvta_s(a1s);
  const uint4* Wc4 = (const uint4*)Wc;
  const uint4* W2p4 = (const uint4*)W2s;

  for (long long blk = blockIdx.x; blk < BT/64; blk += gridDim.x) {
    const long long m0 = blk * 64;
    __syncthreads();
    #pragma unroll
    for (int it = 0; it < 8; ++it) {
      int idx = it*256 + tid;
      int r = idx >> 5, q = idx & 31;
      long long row = m0 + r;
      const __nv_bfloat16* hp = hsb + row*128;
      if (q < 16) {
        uint4 v = *(const uint4*)(hp + q*8);
        *(uint4*)(As + r*ATT_AS + q*8) = v;
      } else {
        int qq = q - 16;
        int b = (int)(row / T);
        uint4 v = *(const uint4*)(hp + qq*8);
        const float* nw = inputs + ((long long)b*(T+1) + T)*128 + qq*8;
        float4 n0 = *(const float4*)(nw);
        float4 n1 = *(const float4*)(nw + 4);
        float2 h0 = bf2f(v.x), h1 = bf2f(v.y), h2 = bf2f(v.z), h3 = bf2f(v.w);
        uint4 o;
        o.x = bf2(h0.x*n0.x, h0.y*n0.y);
        o.y = bf2(h1.x*n0.z, h1.y*n0.w);
        o.z = bf2(h2.x*n1.x, h2.y*n1.y);
        o.w = bf2(h3.x*n1.z, h3.y*n1.w);
        *(uint4*)(As + r*ATT_AS + 128 + qq*8) = o;
      }
    }
    __syncthreads();
    float acc[2][4][4];
    #pragma unroll
    for (int mt=0;mt<2;mt++)
      #pragma unroll
      for (int nt=0;nt<4;nt++)
        #pragma unroll
        for (int q=0;q<4;q++) acc[mt][nt][q] = 0.f;
    #pragma unroll
    for (int k16 = 0; k16 < 16; ++k16) {
      uint32_t a[2][4];
      #pragma unroll
      for (int mt=0;mt<2;mt++)
        ldsm4(a[mt], asb + ((wm*32 + mt*16 + (lane & 15))*ATT_AS + k16*16 + ((lane >> 4) << 3))*2);
      uint4 b40 = Wc4[(k16*8 + wn*2    )*32 + lane];
      uint4 b41 = Wc4[(k16*8 + wn*2 + 1)*32 + lane];
      uint32_t bb[4][2];
      bb[0][0]=b40.x; bb[0][1]=b40.y; bb[1][0]=b40.z; bb[1][1]=b40.w;
      bb[2][0]=b41.x; bb[2][1]=b41.y; bb[3][0]=b41.z; bb[3][1]=b41.w;
      #pragma unroll
      for (int mt=0;mt<2;mt++)
        #pragma unroll
        for (int nt=0;nt<4;nt++)
          mma16(acc[mt][nt], a[mt], bb[nt]);
    }
    #pragma unroll
    for (int mt=0;mt<2;mt++) {
      int row0 = wm*32 + mt*16 + g;
      #pragma unroll
      for (int nt=0;nt<4;nt++) {
        int col = wn*32 + nt*8 + 2*t4;
        #pragma unroll
        for (int h=0; h<2; ++h) {
          int row = row0 + 8*h;
          long long rowg = m0 + row;
          const float* np = nterm + (long long)(rowg / T)*128;
          float v0 = fmaxf(acc[mt][nt][2*h+0] + np[col],   0.f);
          float v1 = fmaxf(acc[mt][nt][2*h+1] + np[col+1], 0.f);
          *(uint32_t*)(a1s + row*A_STRIDE + col) = bf2(v0, v1);
        }
      }
    }
    __syncthreads();
    {
      float acc2[4][4];
      #pragma unroll
      for (int nt=0;nt<4;nt++)
        #pragma unroll
        for (int q=0;q<4;q++) acc2[nt][q] = 0.f;
      #pragma unroll
      for (int k16 = 0; k16 < 8; ++k16) {
        uint32_t a[4];
        ldsm4(a, a1b + ((wm3*16 + (lane & 15))*A_STRIDE + k16*16 + ((lane >> 4) << 3))*2);
        uint4 b40 = W2p4[(k16*4 + wn3*2    )*32 + lane];
        uint4 b41 = W2p4[(k16*4 + wn3*2 + 1)*32 + lane];
        uint32_t bb[4][2];
        bb[0][0]=b40.x; bb[0][1]=b40.y; bb[1][0]=b40.z; bb[1][1]=b40.w;
        bb[2][0]=b41.x; bb[2][1]=b41.y; bb[3][0]=b41.z; bb[3][1]=b41.w;
        #pragma unroll
        for (int nt=0;nt<4;nt++)
          mma16(acc2[nt], a, bb[nt]);
      }
      #pragma unroll
      for (int nt=0;nt<4;nt++) {
        int col = wn3*32 + nt*8 + 2*t4;
        float bc0 = b2[col], bc1 = b2[col+1];
        #pragma unroll
        for (int h=0; h<2; ++h) {
          int row = wm3*16 + g + 8*h;
          a2s[row*68 + col]     = fmaxf(acc2[nt][2*h+0] + bc0, 0.f);
          a2s[row*68 + col + 1] = fmaxf(acc2[nt][2*h+1] + bc1, 0.f);
        }
      }
    }
    __syncthreads();
    if (tid < 64) {
      float accv = b3v;
      #pragma unroll 8
      for (int cc=0; cc<64; ++cc) accv = fmaf(a2s[tid*68 + cc], W3s[cc], accv);
      g_ats[m0 + tid] = sigf(accv);
    }
  }
}

// ------------------------------ head ------------------------------
__global__ void head_kernel(const float* __restrict__ inputs,
                            const float* __restrict__ gamma, const float* __restrict__ beta,
                            const float* __restrict__ mean,  const float* __restrict__ var,
                            const float* __restrict__ W1, const float* __restrict__ bb1,
                            const float* __restrict__ W2, const float* __restrict__ bb2,
                            const float* __restrict__ fW, const float* __restrict__ fb,
                            float* __restrict__ out) {
  extern __shared__ float sm[];
  float* xs  = sm;          // 32*256
  float* y1s = xs + 8192;   // 32*256
  float* y2s = y1s + 8192;  // 32*128
  const int tid = threadIdx.x;   // 256
  const int b0 = blockIdx.x * 32;
  for (int r = 0; r < 32; ++r) {
    int k = tid;
    int bb = b0 + r;
    float v = (k < 128) ? g_hfin[bb*128 + k]
                        : inputs[((long long)bb*(T+1) + T)*128 + (k - 128)];
    float nv = (v - mean[k]) * rsqrtf(var[k] + BN_EPS) * gamma[k] + beta[k];
    xs[r*256 + k] = nv;
  }
  __syncthreads();
  {
    float acc[32];
    #pragma unroll
    for (int r=0;r<32;r++) acc[r] = bb1[tid];
    for (int k=0;k<256;++k) {
      float w = W1[k*256 + tid];
      #pragma unroll
      for (int r=0;r<32;r++) acc[r] = fmaf(xs[r*256+k], w, acc[r]);
    }
    #pragma unroll
    for (int r=0;r<32;r++) {
      float v = acc[r];
      y1s[r*256 + tid] = v >= 0.f ? v : LEAKY*v;
    }
  }
  __syncthreads();
  if (tid < 128) {
    float acc[32];
    #pragma unroll
    for (int r=0;r<32;r++) acc[r] = bb2[tid];
    for (int k=0;k<256;++k) {
      float w = W2[k*128 + tid];
      #pragma unroll
      for (int r=0;r<32;r++) acc[r] = fmaf(y1s[r*256+k], w, acc[r]);
    }
    #pragma unroll
    for (int r=0;r<32;r++) {
      float v = acc[r];
      y2s[r*128 + tid] = v >= 0.f ? v : LEAKY*v;
    }
  }
  __syncthreads();
  if (tid < 32) {
    float acc = fb[0];
    for (int k=0;k<128;++k) acc = fmaf(y2s[tid*128+k], fW[k], acc);
    out[b0 + tid] = sigf(acc);
  }
}

// ------------------------------ launch ------------------------------
extern "C" void kernel_launch(void* const* d_in, const int* in_sizes, int n_in,
                              void* d_out, int out_size) {
  (void)in_sizes; (void)n_in; (void)out_size;
  const float* inputs  = (const float*)d_in[0];
  const float* gru_W   = (const float*)d_in[1];
  const float* gru_U   = (const float*)d_in[2];
  const float* gru_b   = (const float*)d_in[3];
  const float* att_W1  = (const float*)d_in[4];
  const float* att_b1  = (const float*)d_in[5];
  const float* att_W2  = (const float*)d_in[6];
  const float* att_b2  = (const float*)d_in[7];
  const float* att_W3  = (const float*)d_in[8];
  const float* att_b3  = (const float*)d_in[9];
  const float* au_Wu   = (const float*)d_in[10];
  const float* au_bu   = (const float*)d_in[11];
  const float* au_Uu   = (const float*)d_in[12];
  const float* au_Wr   = (const float*)d_in[13];
  const float* au_br   = (const float*)d_in[14];
  const float* au_Ur   = (const float*)d_in[15];
  const float* au_Wc   = (const float*)d_in[16];
  const float* au_bc   = (const float*)d_in[17];
  const float* au_Uc   = (const float*)d_in[18];
  const float* bn_gamma= (const float*)d_in[19];
  const float* bn_beta = (const float*)d_in[20];
  const float* bn_mean = (const float*)d_in[21];
  const float* bn_var  = (const float*)d_in[22];
  const float* d_W1    = (const float*)d_in[23];
  const float* d_b1    = (const float*)d_in[24];
  const float* d_W2    = (const float*)d_in[25];
  const float* d_b2    = (const float*)d_in[26];
  const float* f_W     = (const float*)d_in[27];
  const float* f_b     = (const float*)d_in[28];
  float* out = (float*)d_out;

  const size_t sm_gemm  = 17408 + 32768 + 16640;             // 66816
  const size_t sm_gru   = 34816 + 50176;                     // 84992
  const size_t sm_au    = 34816 + 50176 + 256;               // 85248
  const size_t sm_attf  = 150784;
  const size_t sm_head  = (8192*2 + 4096)*sizeof(float);
  cudaFuncSetAttribute(gemm_bf16,      cudaFuncAttributeMaxDynamicSharedMemorySize, (int)sm_gemm);
  cudaFuncSetAttribute(gru_scan_mma,   cudaFuncAttributeMaxDynamicSharedMemorySize, (int)sm_gru);
  cudaFuncSetAttribute(augru_scan_mma, cudaFuncAttributeMaxDynamicSharedMemorySize, (int)sm_au);
  cudaFuncSetAttribute(att_fused,      cudaFuncAttributeMaxDynamicSharedMemorySize, (int)sm_attf);
  cudaFuncSetAttribute(head_kernel,    cudaFuncAttributeMaxDynamicSharedMemorySize, (int)sm_head);

  float *p_Xp, *p_X3, *p_newsterm, *p_bau;
  __nv_bfloat16 *p_hsb;
  uint32_t *p_Ubg, *p_Uba, *p_WbgW, *p_Wbau, *p_Wb1bc, *p_Wbcat, *p_Wbatt2;
  cudaGetSymbolAddress((void**)&p_Xp,       g_Xp);
  cudaGetSymbolAddress((void**)&p_hsb,      g_hsb);
  cudaGetSymbolAddress((void**)&p_X3,       g_X3);
  cudaGetSymbolAddress((void**)&p_newsterm, g_newsterm);
  cudaGetSymbolAddress((void**)&p_bau,      g_bau);
  cudaGetSymbolAddress((void**)&p_Ubg,      g_Ubf_gru);
  cudaGetSymbolAddress((void**)&p_Uba,      g_Ubf_au);
  cudaGetSymbolAddress((void**)&p_WbgW,     g_Wb_gruW);
  cudaGetSymbolAddress((void**)&p_Wbau,     g_Wb_au);
  cudaGetSymbolAddress((void**)&p_Wb1bc,    g_Wb_1bc);
  cudaGetSymbolAddress((void**)&p_Wbcat,    g_Wb_cat);
  cudaGetSymbolAddress((void**)&p_Wbatt2,   g_Wb_att2);

  cudaStream_t s2;
  cudaStreamCreateWithFlags(&s2, cudaStreamNonBlocking);
  cudaEvent_t evRoot, evSide, evFork, evJoin;
  cudaEventCreateWithFlags(&evRoot, cudaEventDisableTiming);
  cudaEventCreateWithFlags(&evSide, cudaEventDisableTiming);
  cudaEventCreateWithFlags(&evFork, cudaEventDisableTiming);
  cudaEventCreateWithFlags(&evJoin, cudaEventDisableTiming);

  // fork s2 from the capture-origin stream FIRST (required for graph capture)
  cudaEventRecord(evRoot, 0);
  cudaStreamWaitEvent(s2, evRoot, 0);
  // main: pack_a (gruU/gruW/attW2, no deps) -> Xp -> gru
  pack_a<<<208, 256>>>(gru_U, gru_W, att_W2);
  // side: prep -> pack_b -> newsterm  (overlaps pack_a + Xp)
  prep_kernel<<<192, 256, 0, s2>>>(au_Wu, au_bu, au_Wr, au_br, au_Wc, au_bc,
                                   au_Uu, au_Ur, au_Uc, att_W1);
  pack_b<<<288, 256, 0, s2>>>();
  gemm_bf16<<<B/64, 256, sm_gemm, s2>>>(inputs + (long long)T*128, 1, (long long)(T+1)*128, 128,
                                        p_Wb1bc, 8, att_b1, p_newsterm, 128, 0, 0);
  cudaEventRecord(evSide, s2);
  // Xp = hist @ gru_W + gru_b[0]   (A read once; all 384 cols per CTA)
  gemm_bf16<<<BT/64, 256, sm_gemm>>>(inputs, T, (long long)(T+1)*128, 128,
                                     p_WbgW, 24, gru_b, p_Xp, 384, 1, 0);
  // GRU recurrence -> hsb
  gru_scan_mma<<<B/32, 512, sm_gru>>>((const __nv_bfloat16*)p_Xp, p_Ubg, gru_b + 384, p_hsb);
  // fork: X3 gemm on s2, attention on main
  cudaEventRecord(evFork, 0);
  cudaStreamWaitEvent(s2, evFork, 0);
  gemm_bf16<<<BT/64, 256, sm_gemm, s2>>>(p_hsb, 1<<30, 0LL, 128,
                                         p_Wbau, 24, p_bau, p_X3, 384, 1, 1);
  cudaEventRecord(evJoin, s2);
  // attention (needs newsterm + Wb_cat from side stream)
  cudaStreamWaitEvent(0, evSide, 0);
  att_fused<<<148, 256, sm_attf>>>(p_hsb, inputs, p_Wbcat, p_Wbatt2,
                                   att_b2, att_W3, att_b3, p_newsterm);
  cudaStreamWaitEvent(0, evJoin, 0);
  // AUGRU recurrence -> hfin
  augru_scan_mma<<<B/32, 512, sm_au>>>((const __nv_bfloat16*)p_X3, p_Uba);
  // BN + dense head -> out
  head_kernel<<<B/32, 256, sm_head>>>(inputs, bn_gamma, bn_beta, bn_mean, bn_var,
                                      d_W1, d_b1, d_W2, d_b2, f_W, f_b, out);
}

// round 16
// speedup vs baseline: 1.6380x; 1.0756x over previous
#include <cuda_runtime.h>
#include <cuda_bf16.h>
#include <math.h>
#include <stdint.h>

#define B  4096
#define T  50
#define U  128
#define N3 384
#define BT (B*T)
#define BN_EPS 1e-3f
#define LEAKY  3e-4f

// ------------ scratch (device globals; no allocation allowed) ------------
__device__ float g_Xp[BT*N3];            // GRU input projection (bf16 payload)
__device__ __nv_bfloat16 g_hsb[BT*U];    // GRU hidden states (bf16)
__device__ float g_X3[BT*N3];            // AUGRU input projections (bf16 payload)
__device__ float g_ats[BT];              // attention scores
__device__ float g_hfin[B*U];            // AUGRU final state
__device__ float g_newsterm[B*U];        // news@(W1B+W1C)+b1
__device__ float g_Wau[U*N3];            // packed input  [Wu|Wr|Wc]
__device__ float g_Uau[U*N3];            // packed recur  [Uu|Ur|Uc]
__device__ float g_bau[N3];              // packed [bu|br|bc]
__device__ float g_Wcat[2*U*U];          // [W1A-W1B ; W1D]  (256 x 128)
__device__ float g_W1bc[U*U];            // W1B + W1C
__device__ uint32_t g_Ubf_gru[24576];    // bf16 frag gru_U
__device__ uint32_t g_Ubf_au[24576];     // bf16 frag [Uu|Ur|Uc]
__device__ uint32_t g_Wb_gruW[24576];    // bf16 frag gru_W     (K=128,N=384)
__device__ uint32_t g_Wb_au[24576];      // bf16 frag [Wu|Wr|Wc]
__device__ uint32_t g_Wb_1bc[8192];      // bf16 frag W1B+W1C   (K=128,N=128)
__device__ uint32_t g_Wb_cat[16384];     // bf16 frag Wcat      (K=256,N=128)
__device__ uint32_t g_Wb_att2[4096];     // bf16 frag att_W2    (K=128,N=64)

__device__ __forceinline__ float sigf(float x){ return 1.f/(1.f+expf(-x)); }
__device__ __forceinline__ float tanha(float x){
  float y; asm("tanh.approx.f32 %0, %1;" : "=f"(y) : "f"(x)); return y;
}
__device__ __forceinline__ float sigt(float x){ return fmaf(tanha(0.5f*x), 0.5f, 0.5f); }
__device__ __forceinline__ uint32_t bf2(float lo, float hi){
  __nv_bfloat162 v;
  v.x = __float2bfloat16(lo); v.y = __float2bfloat16(hi);
  return *(uint32_t*)&v;
}
__device__ __forceinline__ float2 bf2f(uint32_t u){
  __nv_bfloat162 v = *(__nv_bfloat162*)&u;
  return __bfloat1622float2(v);
}
__device__ __forceinline__ uint32_t cvta_s(const void* p){
  return (uint32_t)__cvta_generic_to_shared(p);
}
__device__ __forceinline__ void ldsm4(uint32_t* r, uint32_t addr){
  asm volatile("ldmatrix.sync.aligned.m8n8.x4.shared.b16 {%0,%1,%2,%3}, [%4];"
               : "=r"(r[0]), "=r"(r[1]), "=r"(r[2]), "=r"(r[3]) : "r"(addr));
}
__device__ __forceinline__ void mma16(float* d, const uint32_t* a, const uint32_t* b){
  asm volatile("mma.sync.aligned.m16n8k16.row.col.f32.bf16.bf16.f32 "
               "{%0,%1,%2,%3}, {%4,%5,%6,%7}, {%8,%9}, {%0,%1,%2,%3};"
               : "+f"(d[0]), "+f"(d[1]), "+f"(d[2]), "+f"(d[3])
               : "r"(a[0]), "r"(a[1]), "r"(a[2]), "r"(a[3]), "r"(b[0]), "r"(b[1]));
}
__device__ __forceinline__ void cpa16(uint32_t saddr, const void* g){
  asm volatile("cp.async.cg.shared.global [%0], [%1], 16;" :: "r"(saddr), "l"(g));
}
#define CPA_COMMIT() asm volatile("cp.async.commit_group;" ::: "memory")
#define CPA_WAIT0()  asm volatile("cp.async.wait_group 0;" ::: "memory")

// ------------------------------- prep -------------------------------
__global__ void prep_kernel(const float* __restrict__ Wu, const float* __restrict__ bu,
                            const float* __restrict__ Wr, const float* __restrict__ br,
                            const float* __restrict__ Wc, const float* __restrict__ bc,
                            const float* __restrict__ Uu, const float* __restrict__ Ur,
                            const float* __restrict__ Uc,
                            const float* __restrict__ attW1) {
  int id = blockIdx.x*blockDim.x + threadIdx.x;
  if (id < U*N3) {
    int k = id / N3, c = id % N3;
    float w, u;
    if (c < 128)      { w = Wu[k*128 + c];       u = Uu[k*128 + c]; }
    else if (c < 256) { w = Wr[k*128 + (c-128)]; u = Ur[k*128 + (c-128)]; }
    else              { w = Wc[k*128 + (c-256)]; u = Uc[k*128 + (c-256)]; }
    g_Wau[id] = w;
    g_Uau[id] = u;
  }
  if (id < N3)
    g_bau[id] = (id < 128) ? bu[id] : (id < 256 ? br[id-128] : bc[id-256]);
  if (id < 2*U*U) {
    int k = id / 128, c = id % 128;
    float v;
    if (k < 128) v = attW1[k*128 + c] - attW1[U*U + k*128 + c];     // W1A - W1B
    else         v = attW1[3*U*U + (k-128)*128 + c];                // W1D
    g_Wcat[id] = v;
  }
  if (id < U*U)
    g_W1bc[id] = attW1[U*U + id] + attW1[2*U*U + id];
}

// --------------- pack weights bf16 fragment-ordered ---------------
__device__ __forceinline__ void pack_bf16_n(const float* __restrict__ Um,
                                            uint32_t* __restrict__ P, int N, int idx) {
  int q = idx & 3, lane = (idx >> 2) & 31;
  int Ntp = N >> 4;
  int tp = (idx >> 7) % Ntp, k16 = (idx >> 7) / Ntp;
  int tile = 2*tp + (q >> 1), r = q & 1;
  int k = k16*16 + 2*(lane & 3) + 8*r;
  int n = tile*8 + (lane >> 2);
  P[idx] = bf2(Um[k*N + n], Um[(k+1)*N + n]);
}

__global__ void pack_a(const float* __restrict__ gruU, const float* __restrict__ gruW,
                       const float* __restrict__ attW2) {
  int idx = blockIdx.x*256 + threadIdx.x;   // 53248 total
  if (idx < 24576)        pack_bf16_n(gruU,  g_Ubf_gru, 384, idx);
  else if (idx < 49152)   pack_bf16_n(gruW,  g_Wb_gruW, 384, idx - 24576);
  else if (idx < 53248)   pack_bf16_n(attW2, g_Wb_att2, 64,  idx - 49152);
}
__global__ void pack_b() {
  int idx = blockIdx.x*256 + threadIdx.x;   // 73728 total
  if (idx < 24576)        pack_bf16_n(g_Uau,  g_Ubf_au, 384, idx);
  else if (idx < 49152)   pack_bf16_n(g_Wau,  g_Wb_au,  384, idx - 24576);
  else if (idx < 57344)   pack_bf16_n(g_W1bc, g_Wb_1bc, 128, idx - 49152);
  else if (idx < 73728)   pack_bf16_n(g_Wcat, g_Wb_cat, 128, idx - 57344);
}

// --------------------- bf16 GEMM, A-resident, N-chunk loop, K=128 ---------------------
#define GAS 136   // As stride (bf16)
__global__ void gemm_bf16(const void* __restrict__ A, int P, long long GS, int RS,
                          const uint32_t* __restrict__ Bpk, int Ntp,
                          const float* __restrict__ bias, void* __restrict__ C, int ldc,
                          int obf, int abf) {
  extern __shared__ char smc[];
  __nv_bfloat16* As = (__nv_bfloat16*)smc;          // 64 x GAS  (17408 B)
  uint32_t* Bp = (uint32_t*)(smc + 17408);          // 8192 u32  (32768 B)
  uint32_t* Cs = (uint32_t*)(smc + 50176);          // 64 x 65 u32 (16640 B)
  const int m0 = blockIdx.x * 64;
  const int tid = threadIdx.x;          // 256
  const int kq = tid >> 5, cq = tid & 31;
  const int lane = tid & 31, wid = tid >> 5;
  const int wm = wid & 1, wn = wid >> 1;
  const int g = lane >> 2, t4 = lane & 3;

  if (abf) {
    #pragma unroll
    for (int it = 0; it < 4; ++it) {
      int f = it*256 + tid;
      int r = f >> 4, q = f & 15;
      int m = m0 + r;
      const __nv_bfloat16* ap = (const __nv_bfloat16*)A + (long long)(m/P)*GS + (long long)(m%P)*RS;
      uint4 v = *(const uint4*)(ap + q*8);
      *(uint4*)(As + r*GAS + q*8) = v;
    }
  } else {
    #pragma unroll
    for (int it = 0; it < 8; ++it) {
      int r = kq + 8*it;
      int m = m0 + r;
      const float* ap = (const float*)A + (long long)(m/P)*GS + (long long)(m%P)*RS;
      float4 v = *(const float4*)(ap + 4*cq);
      uint32_t* dst = (uint32_t*)(As + r*GAS + 4*cq);
      dst[0] = bf2(v.x, v.y);
      dst[1] = bf2(v.z, v.w);
    }
  }
  const uint32_t asb = cvta_s(As);
  const int nch = Ntp >> 3;
  for (int cc = 0; cc < nch; ++cc) {
    const int tp0 = cc*8, c0 = cc*128;
    if (cc) __syncthreads();
    {
      const uint4* src = (const uint4*)Bpk;
      uint4* dst = (uint4*)Bp;
      #pragma unroll
      for (int it = 0; it < 8; ++it) {
        int f = it*256 + tid;
        int k16 = f >> 8, rem = f & 255;
        dst[f] = src[((long long)k16*Ntp + tp0)*32 + rem];
      }
    }
    __syncthreads();
    float acc[2][4][4];
    #pragma unroll
    for (int mt=0;mt<2;mt++)
      #pragma unroll
      for (int nt=0;nt<4;nt++)
        #pragma unroll
        for (int q=0;q<4;q++) acc[mt][nt][q] = 0.f;
    const uint4* bp4 = (const uint4*)Bp;
    #pragma unroll
    for (int k16 = 0; k16 < 8; ++k16) {
      uint32_t a[2][4];
      #pragma unroll
      for (int mt=0;mt<2;mt++)
        ldsm4(a[mt], asb + ((wm*32 + mt*16 + (lane & 15))*GAS + k16*16 + ((lane >> 4) << 3))*2);
      uint4 b40 = bp4[(k16*8 + wn*2    )*32 + lane];
      uint4 b41 = bp4[(k16*8 + wn*2 + 1)*32 + lane];
      uint32_t bb[4][2];
      bb[0][0]=b40.x; bb[0][1]=b40.y; bb[1][0]=b40.z; bb[1][1]=b40.w;
      bb[2][0]=b41.x; bb[2][1]=b41.y; bb[3][0]=b41.z; bb[3][1]=b41.w;
      #pragma unroll
      for (int mt=0;mt<2;mt++)
        #pragma unroll
        for (int nt=0;nt<4;nt++)
          mma16(acc[mt][nt], a[mt], bb[nt]);
    }
    if (obf) {
      #pragma unroll
      for (int mt=0;mt<2;mt++) {
        int row0 = wm*32 + mt*16 + g;
        #pragma unroll
        for (int nt=0;nt<4;nt++) {
          int col = wn*32 + nt*8 + 2*t4;
          float bc0 = bias[c0+col], bc1 = bias[c0+col+1];
          #pragma unroll
          for (int h=0; h<2; ++h) {
            int row = row0 + 8*h;
            Cs[row*65 + (col >> 1)] = bf2(acc[mt][nt][2*h+0] + bc0, acc[mt][nt][2*h+1] + bc1);
          }
        }
      }
      __syncthreads();
      #pragma unroll
      for (int it = 0; it < 16; ++it) {
        int f = it*256 + tid;
        int r = f >> 6, q = f & 63;
        *(uint32_t*)((__nv_bfloat16*)C + (long long)(m0+r)*ldc + c0 + 2*q) = Cs[r*65 + q];
      }
    } else {
      #pragma unroll
      for (int mt=0;mt<2;mt++) {
        int row0 = m0 + wm*32 + mt*16 + g;
        #pragma unroll
        for (int nt=0;nt<4;nt++) {
          int col = c0 + wn*32 + nt*8 + 2*t4;
          float bc0 = bias[col], bc1 = bias[col+1];
          #pragma unroll
          for (int h=0; h<2; ++h) {
            int row = row0 + 8*h;
            float2 o = {acc[mt][nt][2*h+0] + bc0, acc[mt][nt][2*h+1] + bc1};
            *(float2*)((float*)C + (long long)row*ldc + col) = o;
          }
        }
      }
    }
  }
}

// -------------------- GRU scan, 512 thr, cp.async staging (32 rows/CTA) --------------------
#define A_STRIDE 136
#define A_BUF    (32*A_STRIDE)
#define XS_STRIDE 392
#define XS_BUF   (32*XS_STRIDE)
__global__ __launch_bounds__(512, 1)
void gru_scan_mma(const __nv_bfloat16* __restrict__ Xp, const uint32_t* __restrict__ Bpack,
                  const float* __restrict__ brec, __nv_bfloat16* __restrict__ hsb) {
  extern __shared__ char smc[];
  __nv_bfloat16* Ab = (__nv_bfloat16*)smc;
  __nv_bfloat16* Xs = (__nv_bfloat16*)(smc + 34816);
  const int tid = threadIdx.x;    // 512
  const int w2 = tid >> 5, lane = tid & 31;
  const int w = w2 >> 1, ntw = w2 & 1;
  const int g = lane >> 2, t4 = lane & 3;
  const int b0 = blockIdx.x * 32;
  const int csub = w2*8 + 2*t4;
  const uint32_t abb = cvta_s(Ab);
  const uint32_t xsb = cvta_s(Xs);
  // staging indices for x prefetch (3 chunks of 512)
  const int xr0 = tid / 48 + 0,  xq0 = tid % 48;            // f = tid
  const int xr1 = (512+tid)/48,  xq1 = (512+tid)%48;
  const int xr2 = (1024+tid)/48, xq2 = (1024+tid)%48;
  uint2 breg[24];
  #pragma unroll
  for (int k16=0;k16<8;++k16)
    #pragma unroll
    for (int j=0;j<3;++j)
      breg[k16*3+j] = ((const uint2*)Bpack)[(((k16*24) + j*8 + w)*32 + lane)*2 + ntw];
  for (int i = tid; i < A_BUF; i += 512) ((uint32_t*)Ab)[i] = 0u;
  // async-stage x(0) into Xs buf 0
  cpa16(xsb + (xr0*XS_STRIDE + xq0*8)*2, Xp + ((long long)(b0+xr0)*T + 0)*N3 + xq0*8);
  cpa16(xsb + (xr1*XS_STRIDE + xq1*8)*2, Xp + ((long long)(b0+xr1)*T + 0)*N3 + xq1*8);
  cpa16(xsb + (xr2*XS_STRIDE + xq2*8)*2, Xp + ((long long)(b0+xr2)*T + 0)*N3 + xq2*8);
  CPA_COMMIT();
  float2 bz = *(const float2*)(brec + csub);
  float2 brr = *(const float2*)(brec + 128 + csub);
  float2 bh = *(const float2*)(brec + 256 + csub);
  float h[2][2][2];
  #pragma unroll
  for (int a1=0;a1<2;a1++)
    #pragma unroll
    for (int a2=0;a2<2;a2++) { h[a1][a2][0]=0.f; h[a1][a2][1]=0.f; }

  for (int t = 0; t < T; ++t) {
    CPA_WAIT0();          // x(t) landed (this warp's copies)
    __syncthreads();      // publish x(t) + Aw(t-1) across warps
    if (t + 1 < T) {      // prefetch x(t+1) into other buffer (lands by next head)
      uint32_t xw = xsb + (uint32_t)(((t+1) & 1) * XS_BUF * 2);
      cpa16(xw + (xr0*XS_STRIDE + xq0*8)*2, Xp + ((long long)(b0+xr0)*T + t+1)*N3 + xq0*8);
      cpa16(xw + (xr1*XS_STRIDE + xq1*8)*2, Xp + ((long long)(b0+xr1)*T + t+1)*N3 + xq1*8);
      cpa16(xw + (xr2*XS_STRIDE + xq2*8)*2, Xp + ((long long)(b0+xr2)*T + t+1)*N3 + xq2*8);
      CPA_COMMIT();
    }
    if (t >= 1) {
      const uint4* Au = (const uint4*)(Ab + (t & 1) * A_BUF);
      int r = tid >> 4, q = tid & 15;
      *((uint4*)(hsb + ((long long)(b0+r)*T + (t-1))*128) + q) = Au[r*17 + q];
    }
    const __nv_bfloat16* Xc = Xs + (t & 1) * XS_BUF;
    const uint32_t arb = abb + (uint32_t)((t & 1) * A_BUF * 2);
    __nv_bfloat16* Aw = Ab + ((t & 1) ^ 1) * A_BUF;
    float2 xz[2][2], xr[2][2], xh[2][2];
    #pragma unroll
    for (int mt=0;mt<2;mt++)
      #pragma unroll
      for (int rh=0;rh<2;rh++) {
        const __nv_bfloat16* xp = Xc + (mt*16 + rh*8 + g)*XS_STRIDE + csub;
        xz[mt][rh] = bf2f(*(const uint32_t*)(xp));
        xr[mt][rh] = bf2f(*(const uint32_t*)(xp + 128));
        xh[mt][rh] = bf2f(*(const uint32_t*)(xp + 256));
      }
    float acc[2][3][4];
    #pragma unroll
    for (int mt=0;mt<2;mt++)
      #pragma unroll
      for (int j=0;j<3;j++)
        #pragma unroll
        for (int q=0;q<4;q++) acc[mt][j][q] = 0.f;
    #pragma unroll
    for (int k16=0;k16<8;++k16) {
      uint32_t a[2][4];
      #pragma unroll
      for (int mt=0;mt<2;mt++)
        ldsm4(a[mt], arb + ((mt*16 + (lane & 15))*A_STRIDE + k16*16 + ((lane >> 4) << 3))*2);
      #pragma unroll
      for (int mt=0;mt<2;mt++)
        #pragma unroll
        for (int j=0;j<3;j++)
          mma16(acc[mt][j], a[mt], (const uint32_t*)&breg[k16*3+j]);
    }
    #pragma unroll
    for (int mt=0;mt<2;mt++)
      #pragma unroll
      for (int rh=0;rh<2;rh++) {
        int row = mt*16 + rh*8 + g;
        float hn0, hn1;
        {
          float z  = sigt(xz[mt][rh].x + acc[mt][0][rh*2] + bz.x);
          float r  = sigt(xr[mt][rh].x + acc[mt][1][rh*2] + brr.x);
          float hc = tanha(xh[mt][rh].x + r*(acc[mt][2][rh*2] + bh.x));
          float ho = h[mt][rh][0];
          hn0 = z*ho + (1.f - z)*hc;
          h[mt][rh][0] = hn0;
        }
        {
          float z  = sigt(xz[mt][rh].y + acc[mt][0][rh*2+1] + bz.y);
          float r  = sigt(xr[mt][rh].y + acc[mt][1][rh*2+1] + brr.y);
          float hc = tanha(xh[mt][rh].y + r*(acc[mt][2][rh*2+1] + bh.y));
          float ho = h[mt][rh][1];
          hn1 = z*ho + (1.f - z)*hc;
          h[mt][rh][1] = hn1;
        }
        *(uint32_t*)(Aw + row*A_STRIDE + csub) = bf2(hn0, hn1);
      }
  }
  __syncthreads();     // publish Aw(T-1) writes
  {
    const uint4* Au = (const uint4*)(Ab);   // ((T-1)&1)^1 = 0
    int r = tid >> 4, q = tid & 15;
    *((uint4*)(hsb + ((long long)(b0+r)*T + (T-1))*128) + q) = Au[r*17 + q];
  }
}

// -------------------- AUGRU scan, 512 thr, cp.async staging --------------------
__global__ __launch_bounds__(512, 1)
void augru_scan_mma(const __nv_bfloat16* __restrict__ X3, const uint32_t* __restrict__ Bpack) {
  extern __shared__ char smc[];
  __nv_bfloat16* Ab = (__nv_bfloat16*)smc;
  __nv_bfloat16* Xs = (__nv_bfloat16*)(smc + 34816);
  float* ats_s = (float*)(smc + 34816 + 50176);
  const int tid = threadIdx.x;
  const int w2 = tid >> 5, lane = tid & 31;
  const int w = w2 >> 1, ntw = w2 & 1;
  const int g = lane >> 2, t4 = lane & 3;
  const int b0 = blockIdx.x * 32;
  const int csub = w2*8 + 2*t4;
  const uint32_t abb = cvta_s(Ab);
  const uint32_t xsb = cvta_s(Xs);
  const uint32_t atb = cvta_s(ats_s);
  const int xr0 = tid / 48,      xq0 = tid % 48;
  const int xr1 = (512+tid)/48,  xq1 = (512+tid)%48;
  const int xr2 = (1024+tid)/48, xq2 = (1024+tid)%48;
  uint2 breg[24];
  #pragma unroll
  for (int k16=0;k16<8;++k16)
    #pragma unroll
    for (int j=0;j<3;++j)
      breg[k16*3+j] = ((const uint2*)Bpack)[(((k16*24) + j*8 + w)*32 + lane)*2 + ntw];
  for (int i = tid; i < A_BUF; i += 512) ((uint32_t*)Ab)[i] = 0u;
  cpa16(xsb + (xr0*XS_STRIDE + xq0*8)*2, X3 + ((long long)(b0+xr0)*T + 0)*N3 + xq0*8);
  cpa16(xsb + (xr1*XS_STRIDE + xq1*8)*2, X3 + ((long long)(b0+xr1)*T + 0)*N3 + xq1*8);
  cpa16(xsb + (xr2*XS_STRIDE + xq2*8)*2, X3 + ((long long)(b0+xr2)*T + 0)*N3 + xq2*8);
  if (tid < 32) {
    asm volatile("cp.async.ca.shared.global [%0], [%1], 4;"
                 :: "r"(atb + tid*4), "l"(g_ats + (long long)(b0+tid)*T + 0));
  }
  CPA_COMMIT();
  float h[2][2][2];
  #pragma unroll
  for (int a1=0;a1<2;a1++)
    #pragma unroll
    for (int a2=0;a2<2;a2++) { h[a1][a2][0]=0.f; h[a1][a2][1]=0.f; }

  for (int t = 0; t < T; ++t) {
    CPA_WAIT0();
    __syncthreads();
    if (t + 1 < T) {
      uint32_t xw = xsb + (uint32_t)(((t+1) & 1) * XS_BUF * 2);
      cpa16(xw + (xr0*XS_STRIDE + xq0*8)*2, X3 + ((long long)(b0+xr0)*T + t+1)*N3 + xq0*8);
      cpa16(xw + (xr1*XS_STRIDE + xq1*8)*2, X3 + ((long long)(b0+xr1)*T + t+1)*N3 + xq1*8);
      cpa16(xw + (xr2*XS_STRIDE + xq2*8)*2, X3 + ((long long)(b0+xr2)*T + t+1)*N3 + xq2*8);
      if (tid < 32) {
        asm volatile("cp.async.ca.shared.global [%0], [%1], 4;"
                     :: "r"(atb + (((t+1)&1)*32 + tid)*4),
                        "l"(g_ats + (long long)(b0+tid)*T + t+1));
      }
      CPA_COMMIT();
    }
    const __nv_bfloat16* Xc = Xs + (t & 1) * XS_BUF;
    const float* atc = ats_s + (t & 1) * 32;
    const uint32_t arb = abb + (uint32_t)((t & 1) * A_BUF * 2);
    __nv_bfloat16* Aw = Ab + ((t & 1) ^ 1) * A_BUF;
    float2 xu[2][2], xr[2][2], xc[2][2];
    float at[2][2];
    #pragma unroll
    for (int mt=0;mt<2;mt++)
      #pragma unroll
      for (int rh=0;rh<2;rh++) {
        at[mt][rh] = atc[mt*16 + rh*8 + g];
        const __nv_bfloat16* xp = Xc + (mt*16 + rh*8 + g)*XS_STRIDE + csub;
        xu[mt][rh] = bf2f(*(const uint32_t*)(xp));
        xr[mt][rh] = bf2f(*(const uint32_t*)(xp + 128));
        xc[mt][rh] = bf2f(*(const uint32_t*)(xp + 256));
      }
    float acc[2][3][4];
    #pragma unroll
    for (int mt=0;mt<2;mt++)
      #pragma unroll
      for (int j=0;j<3;j++)
        #pragma unroll
        for (int q=0;q<4;q++) acc[mt][j][q] = 0.f;
    #pragma unroll
    for (int k16=0;k16<8;++k16) {
      uint32_t a[2][4];
      #pragma unroll
      for (int mt=0;mt<2;mt++)
        ldsm4(a[mt], arb + ((mt*16 + (lane & 15))*A_STRIDE + k16*16 + ((lane >> 4) << 3))*2);
      #pragma unroll
      for (int mt=0;mt<2;mt++)
        #pragma unroll
        for (int j=0;j<3;j++)
          mma16(acc[mt][j], a[mt], (const uint32_t*)&breg[k16*3+j]);
    }
    #pragma unroll
    for (int mt=0;mt<2;mt++)
      #pragma unroll
      for (int rh=0;rh<2;rh++) {
        int row = mt*16 + rh*8 + g;
        float atv = at[mt][rh];
        float hn0, hn1;
        {
          float u  = sigt(xu[mt][rh].x + acc[mt][0][rh*2]);
          float r  = sigt(xr[mt][rh].x + acc[mt][1][rh*2]);
          float cc = tanha(xc[mt][rh].x + r*acc[mt][2][rh*2]);
          float uu = atv*u;
          float ho = h[mt][rh][0];
          hn0 = (1.f - uu)*ho + uu*cc;
          h[mt][rh][0] = hn0;
        }
        {
          float u  = sigt(xu[mt][rh].y + acc[mt][0][rh*2+1]);
          float r  = sigt(xr[mt][rh].y + acc[mt][1][rh*2+1]);
          float cc = tanha(xc[mt][rh].y + r*acc[mt][2][rh*2+1]);
          float uu = atv*u;
          float ho = h[mt][rh][1];
          hn1 = (1.f - uu)*ho + uu*cc;
          h[mt][rh][1] = hn1;
        }
        *(uint32_t*)(Aw + row*A_STRIDE + csub) = bf2(hn0, hn1);
      }
  }
  #pragma unroll
  for (int mt=0;mt<2;mt++)
    #pragma unroll
    for (int rh=0;rh<2;rh++) {
      int row = mt*16 + rh*8 + g;
      float2 o = {h[mt][rh][0], h[mt][rh][1]};
      *(float2*)(g_hfin + (long long)(b0+row)*128 + csub) = o;
    }
}

// ------------- fused attention (bf16): hs,news -> a1 -> a2 -> ats -------------
#define ATT_AS 264
__global__ __launch_bounds__(256, 1)
void att_fused(const __nv_bfloat16* __restrict__ hsb, const float* __restrict__ inputs,
               const uint32_t* __restrict__ Wcatp, const uint32_t* __restrict__ W2p,
               const float* __restrict__ b2, const float* __restrict__ W3,
               const float* __restrict__ b3, const float* __restrict__ nterm) {
  extern __shared__ char smc[];
  __nv_bfloat16* As  = (__nv_bfloat16*)smc;            // 64 x 264
  uint32_t* Wc  = (uint32_t*)(smc + 33792);            // 16384 u32
  __nv_bfloat16* a1s = (__nv_bfloat16*)(smc + 99328);  // 64 x 136
  uint32_t* W2s = (uint32_t*)(smc + 116736);           // 4096 u32
  float* a2s = (float*)(smc + 133120);                 // 64 x 68
  float* W3s = (float*)(smc + 150528);                 // 64
  const int tid = threadIdx.x;     // 256
  const int lane = tid & 31, wid = tid >> 5;
  const int wm = wid & 1, wn = wid >> 1;
  const int wm3 = wid & 3, wn3 = wid >> 2;
  const int g = lane >> 2, t4 = lane & 3;
  const float b3v = b3[0];

  {
    const uint4* src = (const uint4*)Wcatp;
    uint4* dst = (uint4*)Wc;
    #pragma unroll
    for (int it = 0; it < 16; ++it) dst[it*256 + tid] = src[it*256 + tid];
    const uint4* src2 = (const uint4*)W2p;
    uint4* dst2 = (uint4*)W2s;
    #pragma unroll
    for (int it = 0; it < 4; ++it) dst2[it*256 + tid] = src2[it*256 + tid];
    if (tid < 64) W3s[tid] = W3[tid];
  }
  const uint32_t asb = cvta_s(As);
  const uint32_t a1b = cvta_s(a1s);
  const uint4* Wc4 = (const uint4*)Wc;
  const uint4* W2p4 = (const uint4*)W2s;

  for (long long blk = blockIdx.x; blk < BT/64; blk += gridDim.x) {
    const long long m0 = blk * 64;
    __syncthreads();
    #pragma unroll
    for (int it = 0; it < 8; ++it) {
      int idx = it*256 + tid;
      int r = idx >> 5, q = idx & 31;
      long long row = m0 + r;
      const __nv_bfloat16* hp = hsb + row*128;
      if (q < 16) {
        cpa16(asb + (r*ATT_AS + q*8)*2, hp + q*8);      // async copy of hs half
      } else {
        int qq = q - 16;
        int b = (int)(row / T);
        uint4 v = *(const uint4*)(hp + qq*8);
        const float* nw = inputs + ((long long)b*(T+1) + T)*128 + qq*8;
        float4 n0 = *(const float4*)(nw);
        float4 n1 = *(const float4*)(nw + 4);
        float2 h0 = bf2f(v.x), h1 = bf2f(v.y), h2 = bf2f(v.z), h3 = bf2f(v.w);
        uint4 o;
        o.x = bf2(h0.x*n0.x, h0.y*n0.y);
        o.y = bf2(h1.x*n0.z, h1.y*n0.w);
        o.z = bf2(h2.x*n1.x, h2.y*n1.y);
        o.w = bf2(h3.x*n1.z, h3.y*n1.w);
        *(uint4*)(As + r*ATT_AS + 128 + qq*8) = o;
      }
    }
    CPA_COMMIT();
    CPA_WAIT0();
    __syncthreads();
    float acc[2][4][4];
    #pragma unroll
    for (int mt=0;mt<2;mt++)
      #pragma unroll
      for (int nt=0;nt<4;nt++)
        #pragma unroll
        for (int q=0;q<4;q++) acc[mt][nt][q] = 0.f;
    #pragma unroll
    for (int k16 = 0; k16 < 16; ++k16) {
      uint32_t a[2][4];
      #pragma unroll
      for (int mt=0;mt<2;mt++)
        ldsm4(a[mt], asb + ((wm*32 + mt*16 + (lane & 15))*ATT_AS + k16*16 + ((lane >> 4) << 3))*2);
      uint4 b40 = Wc4[(k16*8 + wn*2    )*32 + lane];
      uint4 b41 = Wc4[(k16*8 + wn*2 + 1)*32 + lane];
      uint32_t bb[4][2];
      bb[0][0]=b40.x; bb[0][1]=b40.y; bb[1][0]=b40.z; bb[1][1]=b40.w;
      bb[2][0]=b41.x; bb[2][1]=b41.y; bb[3][0]=b41.z; bb[3][1]=b41.w;
      #pragma unroll
      for (int mt=0;mt<2;mt++)
        #pragma unroll
        for (int nt=0;nt<4;nt++)
          mma16(acc[mt][nt], a[mt], bb[nt]);
    }
    #pragma unroll
    for (int mt=0;mt<2;mt++) {
      int row0 = wm*32 + mt*16 + g;
      #pragma unroll
      for (int nt=0;nt<4;nt++) {
        int col = wn*32 + nt*8 + 2*t4;
        #pragma unroll
        for (int h=0; h<2; ++h) {
          int row = row0 + 8*h;
          long long rowg = m0 + row;
          const float* np = nterm + (long long)(rowg / T)*128;
          float v0 = fmaxf(acc[mt][nt][2*h+0] + np[col],   0.f);
          float v1 = fmaxf(acc[mt][nt][2*h+1] + np[col+1], 0.f);
          *(uint32_t*)(a1s + row*A_STRIDE + col) = bf2(v0, v1);
        }
      }
    }
    __syncthreads();
    {
      float acc2[4][4];
      #pragma unroll
      for (int nt=0;nt<4;nt++)
        #pragma unroll
        for (int q=0;q<4;q++) acc2[nt][q] = 0.f;
      #pragma unroll
      for (int k16 = 0; k16 < 8; ++k16) {
        uint32_t a[4];
        ldsm4(a, a1b + ((wm3*16 + (lane & 15))*A_STRIDE + k16*16 + ((lane >> 4) << 3))*2);
        uint4 b40 = W2p4[(k16*4 + wn3*2    )*32 + lane];
        uint4 b41 = W2p4[(k16*4 + wn3*2 + 1)*32 + lane];
        uint32_t bb[4][2];
        bb[0][0]=b40.x; bb[0][1]=b40.y; bb[1][0]=b40.z; bb[1][1]=b40.w;
        bb[2][0]=b41.x; bb[2][1]=b41.y; bb[3][0]=b41.z; bb[3][1]=b41.w;
        #pragma unroll
        for (int nt=0;nt<4;nt++)
          mma16(acc2[nt], a, bb[nt]);
      }
      #pragma unroll
      for (int nt=0;nt<4;nt++) {
        int col = wn3*32 + nt*8 + 2*t4;
        float bc0 = b2[col], bc1 = b2[col+1];
        #pragma unroll
        for (int h=0; h<2; ++h) {
          int row = wm3*16 + g + 8*h;
          a2s[row*68 + col]     = fmaxf(acc2[nt][2*h+0] + bc0, 0.f);
          a2s[row*68 + col + 1] = fmaxf(acc2[nt][2*h+1] + bc1, 0.f);
        }
      }
    }
    __syncthreads();
    if (tid < 64) {
      float accv = b3v;
      #pragma unroll 8
      for (int cc=0; cc<64; ++cc) accv = fmaf(a2s[tid*68 + cc], W3s[cc], accv);
      g_ats[m0 + tid] = sigf(accv);
    }
  }
}

// ------------------------------ head ------------------------------
__global__ void head_kernel(const float* __restrict__ inputs,
                            const float* __restrict__ gamma, const float* __restrict__ beta,
                            const float* __restrict__ mean,  const float* __restrict__ var,
                            const float* __restrict__ W1, const float* __restrict__ bb1,
                            const float* __restrict__ W2, const float* __restrict__ bb2,
                            const float* __restrict__ fW, const float* __restrict__ fb,
                            float* __restrict__ out) {
  extern __shared__ float sm[];
  float* xs  = sm;          // 32*256
  float* y1s = xs + 8192;   // 32*256
  float* y2s = y1s + 8192;  // 32*128
  const int tid = threadIdx.x;   // 256
  const int b0 = blockIdx.x * 32;
  for (int r = 0; r < 32; ++r) {
    int k = tid;
    int bb = b0 + r;
    float v = (k < 128) ? g_hfin[bb*128 + k]
                        : inputs[((long long)bb*(T+1) + T)*128 + (k - 128)];
    float nv = (v - mean[k]) * rsqrtf(var[k] + BN_EPS) * gamma[k] + beta[k];
    xs[r*256 + k] = nv;
  }
  __syncthreads();
  {
    float acc[32];
    #pragma unroll
    for (int r=0;r<32;r++) acc[r] = bb1[tid];
    for (int k=0;k<256;++k) {
      float w = W1[k*256 + tid];
      #pragma unroll
      for (int r=0;r<32;r++) acc[r] = fmaf(xs[r*256+k], w, acc[r]);
    }
    #pragma unroll
    for (int r=0;r<32;r++) {
      float v = acc[r];
      y1s[r*256 + tid] = v >= 0.f ? v : LEAKY*v;
    }
  }
  __syncthreads();
  if (tid < 128) {
    float acc[32];
    #pragma unroll
    for (int r=0;r<32;r++) acc[r] = bb2[tid];
    for (int k=0;k<256;++k) {
      float w = W2[k*128 + tid];
      #pragma unroll
      for (int r=0;r<32;r++) acc[r] = fmaf(y1s[r*256+k], w, acc[r]);
    }
    #pragma unroll
    for (int r=0;r<32;r++) {
      float v = acc[r];
      y2s[r*128 + tid] = v >= 0.f ? v : LEAKY*v;
    }
  }
  __syncthreads();
  if (tid < 32) {
    float acc = fb[0];
    for (int k=0;k<128;++k) acc = fmaf(y2s[tid*128+k], fW[k], acc);
    out[b0 + tid] = sigf(acc);
  }
}

// ------------------------------ launch ------------------------------
extern "C" void kernel_launch(void* const* d_in, const int* in_sizes, int n_in,
                              void* d_out, int out_size) {
  (void)in_sizes; (void)n_in; (void)out_size;
  const float* inputs  = (const float*)d_in[0];
  const float* gru_W   = (const float*)d_in[1];
  const float* gru_U   = (const float*)d_in[2];
  const float* gru_b   = (const float*)d_in[3];
  const float* att_W1  = (const float*)d_in[4];
  const float* att_b1  = (const float*)d_in[5];
  const float* att_W2  = (const float*)d_in[6];
  const float* att_b2  = (const float*)d_in[7];
  const float* att_W3  = (const float*)d_in[8];
  const float* att_b3  = (const float*)d_in[9];
  const float* au_Wu   = (const float*)d_in[10];
  const float* au_bu   = (const float*)d_in[11];
  const float* au_Uu   = (const float*)d_in[12];
  const float* au_Wr   = (const float*)d_in[13];
  const float* au_br   = (const float*)d_in[14];
  const float* au_Ur   = (const float*)d_in[15];
  const float* au_Wc   = (const float*)d_in[16];
  const float* au_bc   = (const float*)d_in[17];
  const float* au_Uc   = (const float*)d_in[18];
  const float* bn_gamma= (const float*)d_in[19];
  const float* bn_beta = (const float*)d_in[20];
  const float* bn_mean = (const float*)d_in[21];
  const float* bn_var  = (const float*)d_in[22];
  const float* d_W1    = (const float*)d_in[23];
  const float* d_b1    = (const float*)d_in[24];
  const float* d_W2    = (const float*)d_in[25];
  const float* d_b2    = (const float*)d_in[26];
  const float* f_W     = (const float*)d_in[27];
  const float* f_b     = (const float*)d_in[28];
  float* out = (float*)d_out;

  const size_t sm_gemm  = 17408 + 32768 + 16640;             // 66816
  const size_t sm_gru   = 34816 + 50176;                     // 84992
  const size_t sm_au    = 34816 + 50176 + 256;               // 85248
  const size_t sm_attf  = 150784;
  const size_t sm_head  = (8192*2 + 4096)*sizeof(float);
  cudaFuncSetAttribute(gemm_bf16,      cudaFuncAttributeMaxDynamicSharedMemorySize, (int)sm_gemm);
  cudaFuncSetAttribute(gru_scan_mma,   cudaFuncAttributeMaxDynamicSharedMemorySize, (int)sm_gru);
  cudaFuncSetAttribute(augru_scan_mma, cudaFuncAttributeMaxDynamicSharedMemorySize, (int)sm_au);
  cudaFuncSetAttribute(att_fused,      cudaFuncAttributeMaxDynamicSharedMemorySize, (int)sm_attf);
  cudaFuncSetAttribute(head_kernel,    cudaFuncAttributeMaxDynamicSharedMemorySize, (int)sm_head);

  float *p_Xp, *p_X3, *p_newsterm, *p_bau;
  __nv_bfloat16 *p_hsb;
  uint32_t *p_Ubg, *p_Uba, *p_WbgW, *p_Wbau, *p_Wb1bc, *p_Wbcat, *p_Wbatt2;
  cudaGetSymbolAddress((void**)&p_Xp,       g_Xp);
  cudaGetSymbolAddress((void**)&p_hsb,      g_hsb);
  cudaGetSymbolAddress((void**)&p_X3,       g_X3);
  cudaGetSymbolAddress((void**)&p_newsterm, g_newsterm);
  cudaGetSymbolAddress((void**)&p_bau,      g_bau);
  cudaGetSymbolAddress((void**)&p_Ubg,      g_Ubf_gru);
  cudaGetSymbolAddress((void**)&p_Uba,      g_Ubf_au);
  cudaGetSymbolAddress((void**)&p_WbgW,     g_Wb_gruW);
  cudaGetSymbolAddress((void**)&p_Wbau,     g_Wb_au);
  cudaGetSymbolAddress((void**)&p_Wb1bc,    g_Wb_1bc);
  cudaGetSymbolAddress((void**)&p_Wbcat,    g_Wb_cat);
  cudaGetSymbolAddress((void**)&p_Wbatt2,   g_Wb_att2);

  cudaStream_t s2;
  cudaStreamCreateWithFlags(&s2, cudaStreamNonBlocking);
  cudaEvent_t evRoot, evSide, evFork, evJoin;
  cudaEventCreateWithFlags(&evRoot, cudaEventDisableTiming);
  cudaEventCreateWithFlags(&evSide, cudaEventDisableTiming);
  cudaEventCreateWithFlags(&evFork, cudaEventDisableTiming);
  cudaEventCreateWithFlags(&evJoin, cudaEventDisableTiming);

  // fork s2 from the capture-origin stream FIRST (required for graph capture)
  cudaEventRecord(evRoot, 0);
  cudaStreamWaitEvent(s2, evRoot, 0);
  // main: pack_a -> Xp -> gru
  pack_a<<<208, 256>>>(gru_U, gru_W, att_W2);
  // side: prep -> pack_b -> newsterm
  prep_kernel<<<192, 256, 0, s2>>>(au_Wu, au_bu, au_Wr, au_br, au_Wc, au_bc,
                                   au_Uu, au_Ur, au_Uc, att_W1);
  pack_b<<<288, 256, 0, s2>>>();
  gemm_bf16<<<B/64, 256, sm_gemm, s2>>>(inputs + (long long)T*128, 1, (long long)(T+1)*128, 128,
                                        p_Wb1bc, 8, att_b1, p_newsterm, 128, 0, 0);
  cudaEventRecord(evSide, s2);
  // Xp = hist @ gru_W + gru_b[0]
  gemm_bf16<<<BT/64, 256, sm_gemm>>>(inputs, T, (long long)(T+1)*128, 128,
                                     p_WbgW, 24, gru_b, p_Xp, 384, 1, 0);
  // GRU recurrence -> hsb
  gru_scan_mma<<<B/32, 512, sm_gru>>>((const __nv_bfloat16*)p_Xp, p_Ubg, gru_b + 384, p_hsb);
  // fork: X3 gemm on s2, attention on main
  cudaEventRecord(evFork, 0);
  cudaStreamWaitEvent(s2, evFork, 0);
  gemm_bf16<<<BT/64, 256, sm_gemm, s2>>>(p_hsb, 1<<30, 0LL, 128,
                                         p_Wbau, 24, p_bau, p_X3, 384, 1, 1);
  cudaEventRecord(evJoin, s2);
  // attention (needs newsterm + Wb_cat from side stream)
  cudaStreamWaitEvent(0, evSide, 0);
  att_fused<<<148, 256, sm_attf>>>(p_hsb, inputs, p_Wbcat, p_Wbatt2,
                                   att_b2, att_W3, att_b3, p_newsterm);
  cudaStreamWaitEvent(0, evJoin, 0);
  // AUGRU recurrence -> hfin
  augru_scan_mma<<<B/32, 512, sm_au>>>((const __nv_bfloat16*)p_X3, p_Uba);
  // BN + dense head -> out
  head_kernel<<<B/32, 256, sm_head>>>(inputs, bn_gamma, bn_beta, bn_mean, bn_var,
                                      d_W1, d_b1, d_W2, d_b2, f_W, f_b, out);
}

// round 17
// speedup vs baseline: 1.6683x; 1.0185x over previous
#include <cuda_runtime.h>
#include <cuda_bf16.h>
#include <math.h>
#include <stdint.h>

#define B  4096
#define T  50
#define U  128
#define N3 384
#define BT (B*T)
#define BN_EPS 1e-3f
#define LEAKY  3e-4f

// ------------ scratch (device globals; no allocation allowed) ------------
__device__ float g_Xp[BT*N3];            // GRU input projection (bf16 payload)
__device__ __nv_bfloat16 g_hsb[BT*U];    // GRU hidden states (bf16)
__device__ float g_X3[BT*N3];            // AUGRU input projections (bf16 payload)
__device__ float g_ats[BT];              // attention scores
__device__ float g_hfin[B*U];            // AUGRU final state
__device__ float g_newsterm[B*U];        // news@(W1B+W1C)+b1
__device__ float g_Wau[U*N3];            // packed input  [Wu|Wr|Wc]
__device__ float g_Uau[U*N3];            // packed recur  [Uu|Ur|Uc]
__device__ float g_bau[N3];              // packed [bu|br|bc]
__device__ float g_Wcat[2*U*U];          // [W1A-W1B ; W1D]  (256 x 128)
__device__ float g_W1bc[U*U];            // W1B + W1C
__device__ uint32_t g_Ubf_gru[24576];    // bf16 frag gru_U
__device__ uint32_t g_Ubf_au[24576];     // bf16 frag [Uu|Ur|Uc]
__device__ uint32_t g_Wb_gruW[24576];    // bf16 frag gru_W     (K=128,N=384)
__device__ uint32_t g_Wb_au[24576];      // bf16 frag [Wu|Wr|Wc]
__device__ uint32_t g_Wb_1bc[8192];      // bf16 frag W1B+W1C   (K=128,N=128)
__device__ uint32_t g_Wb_cat[16384];     // bf16 frag Wcat      (K=256,N=128)
__device__ uint32_t g_Wb_att2[4096];     // bf16 frag att_W2    (K=128,N=64)

__device__ __forceinline__ float sigf(float x){ return 1.f/(1.f+expf(-x)); }
__device__ __forceinline__ float tanha(float x){
  float y; asm("tanh.approx.f32 %0, %1;" : "=f"(y) : "f"(x)); return y;
}
__device__ __forceinline__ float sigt(float x){ return fmaf(tanha(0.5f*x), 0.5f, 0.5f); }
__device__ __forceinline__ uint32_t bf2(float lo, float hi){
  __nv_bfloat162 v;
  v.x = __float2bfloat16(lo); v.y = __float2bfloat16(hi);
  return *(uint32_t*)&v;
}
__device__ __forceinline__ float2 bf2f(uint32_t u){
  __nv_bfloat162 v = *(__nv_bfloat162*)&u;
  return __bfloat1622float2(v);
}
__device__ __forceinline__ uint32_t cvta_s(const void* p){
  return (uint32_t)__cvta_generic_to_shared(p);
}
__device__ __forceinline__ void ldsm4(uint32_t* r, uint32_t addr){
  asm volatile("ldmatrix.sync.aligned.m8n8.x4.shared.b16 {%0,%1,%2,%3}, [%4];"
               : "=r"(r[0]), "=r"(r[1]), "=r"(r[2]), "=r"(r[3]) : "r"(addr));
}
__device__ __forceinline__ void mma16(float* d, const uint32_t* a, const uint32_t* b){
  asm volatile("mma.sync.aligned.m16n8k16.row.col.f32.bf16.bf16.f32 "
               "{%0,%1,%2,%3}, {%4,%5,%6,%7}, {%8,%9}, {%0,%1,%2,%3};"
               : "+f"(d[0]), "+f"(d[1]), "+f"(d[2]), "+f"(d[3])
               : "r"(a[0]), "r"(a[1]), "r"(a[2]), "r"(a[3]), "r"(b[0]), "r"(b[1]));
}
__device__ __forceinline__ void cpa16(uint32_t saddr, const void* g){
  asm volatile("cp.async.cg.shared.global [%0], [%1], 16;" :: "r"(saddr), "l"(g));
}
#define CPA_COMMIT() asm volatile("cp.async.commit_group;" ::: "memory")
#define CPA_WAIT0()  asm volatile("cp.async.wait_group 0;" ::: "memory")
#define CPA_WAIT1()  asm volatile("cp.async.wait_group 1;" ::: "memory")

// ------------------------------- prep -------------------------------
__global__ void prep_kernel(const float* __restrict__ Wu, const float* __restrict__ bu,
                            const float* __restrict__ Wr, const float* __restrict__ br,
                            const float* __restrict__ Wc, const float* __restrict__ bc,
                            const float* __restrict__ Uu, const float* __restrict__ Ur,
                            const float* __restrict__ Uc,
                            const float* __restrict__ attW1) {
  int id = blockIdx.x*blockDim.x + threadIdx.x;
  if (id < U*N3) {
    int k = id / N3, c = id % N3;
    float w, u;
    if (c < 128)      { w = Wu[k*128 + c];       u = Uu[k*128 + c]; }
    else if (c < 256) { w = Wr[k*128 + (c-128)]; u = Ur[k*128 + (c-128)]; }
    else              { w = Wc[k*128 + (c-256)]; u = Uc[k*128 + (c-256)]; }
    g_Wau[id] = w;
    g_Uau[id] = u;
  }
  if (id < N3)
    g_bau[id] = (id < 128) ? bu[id] : (id < 256 ? br[id-128] : bc[id-256]);
  if (id < 2*U*U) {
    int k = id / 128, c = id % 128;
    float v;
    if (k < 128) v = attW1[k*128 + c] - attW1[U*U + k*128 + c];     // W1A - W1B
    else         v = attW1[3*U*U + (k-128)*128 + c];                // W1D
    g_Wcat[id] = v;
  }
  if (id < U*U)
    g_W1bc[id] = attW1[U*U + id] + attW1[2*U*U + id];
}

// --------------- pack weights bf16 fragment-ordered ---------------
__device__ __forceinline__ void pack_bf16_n(const float* __restrict__ Um,
                                            uint32_t* __restrict__ P, int N, int idx) {
  int q = idx & 3, lane = (idx >> 2) & 31;
  int Ntp = N >> 4;
  int tp = (idx >> 7) % Ntp, k16 = (idx >> 7) / Ntp;
  int tile = 2*tp + (q >> 1), r = q & 1;
  int k = k16*16 + 2*(lane & 3) + 8*r;
  int n = tile*8 + (lane >> 2);
  P[idx] = bf2(Um[k*N + n], Um[(k+1)*N + n]);
}

__global__ void pack_a(const float* __restrict__ gruU, const float* __restrict__ gruW,
                       const float* __restrict__ attW2) {
  int idx = blockIdx.x*256 + threadIdx.x;   // 53248 total
  if (idx < 24576)        pack_bf16_n(gruU,  g_Ubf_gru, 384, idx);
  else if (idx < 49152)   pack_bf16_n(gruW,  g_Wb_gruW, 384, idx - 24576);
  else if (idx < 53248)   pack_bf16_n(attW2, g_Wb_att2, 64,  idx - 49152);
}
__global__ void pack_b() {
  int idx = blockIdx.x*256 + threadIdx.x;   // 73728 total
  if (idx < 24576)        pack_bf16_n(g_Uau,  g_Ubf_au, 384, idx);
  else if (idx < 49152)   pack_bf16_n(g_Wau,  g_Wb_au,  384, idx - 24576);
  else if (idx < 57344)   pack_bf16_n(g_W1bc, g_Wb_1bc, 128, idx - 49152);
  else if (idx < 73728)   pack_bf16_n(g_Wcat, g_Wb_cat, 128, idx - 57344);
}

// --------------------- bf16 GEMM, A-resident, cp.async-pipelined B chunks ---------------------
// grid = M/64. Computes all Ntp*16 output columns; A read once per CTA.
// obf=0: C fp32 direct.  obf=1: C bf16, SMEM-staged coalesced stores.
#define GAS 136   // As stride (bf16)
__global__ void gemm_bf16(const void* __restrict__ A, int P, long long GS, int RS,
                          const uint32_t* __restrict__ Bpk, int Ntp,
                          const float* __restrict__ bias, void* __restrict__ C, int ldc,
                          int obf, int abf) {
  extern __shared__ char smc[];
  __nv_bfloat16* As = (__nv_bfloat16*)smc;          // 64 x GAS        (17408 B)
  char* BpBase = smc + 17408;                        // 2 x 32768 B
  uint32_t* Cs = (uint32_t*)(smc + 17408 + 65536);  // 64 x 65 u32     (16640 B)
  const int m0 = blockIdx.x * 64;
  const int tid = threadIdx.x;          // 256
  const int kq = tid >> 5, cq = tid & 31;
  const int lane = tid & 31, wid = tid >> 5;
  const int wm = wid & 1, wn = wid >> 1;
  const int g = lane >> 2, t4 = lane & 3;
  const uint32_t bpb = cvta_s(BpBase);
  const uint4* bsrc = (const uint4*)Bpk;
  const int nch = Ntp >> 3;

  // stage B chunk 0 asynchronously while A is staged synchronously
  {
    const int tp0 = 0;
    #pragma unroll
    for (int it = 0; it < 8; ++it) {
      int f = it*256 + tid;
      int k16 = f >> 8, rem = f & 255;
      cpa16(bpb + f*16, bsrc + ((long long)k16*Ntp + tp0)*32 + rem);
    }
    CPA_COMMIT();
  }
  if (abf) {
    #pragma unroll
    for (int it = 0; it < 4; ++it) {
      int f = it*256 + tid;
      int r = f >> 4, q = f & 15;
      int m = m0 + r;
      const __nv_bfloat16* ap = (const __nv_bfloat16*)A + (long long)(m/P)*GS + (long long)(m%P)*RS;
      uint4 v = *(const uint4*)(ap + q*8);
      *(uint4*)(As + r*GAS + q*8) = v;
    }
  } else {
    #pragma unroll
    for (int it = 0; it < 8; ++it) {
      int r = kq + 8*it;
      int m = m0 + r;
      const float* ap = (const float*)A + (long long)(m/P)*GS + (long long)(m%P)*RS;
      float4 v = *(const float4*)(ap + 4*cq);
      uint32_t* dst = (uint32_t*)(As + r*GAS + 4*cq);
      dst[0] = bf2(v.x, v.y);
      dst[1] = bf2(v.z, v.w);
    }
  }
  const uint32_t asb = cvta_s(As);
  for (int cc = 0; cc < nch; ++cc) {
    const int c0 = cc*128;
    // prefetch next B chunk
    if (cc + 1 < nch) {
      const int tp1 = (cc+1)*8;
      uint32_t dstb = bpb + ((cc+1) & 1) * 32768;
      #pragma unroll
      for (int it = 0; it < 8; ++it) {
        int f = it*256 + tid;
        int k16 = f >> 8, rem = f & 255;
        cpa16(dstb + f*16, bsrc + ((long long)k16*Ntp + tp1)*32 + rem);
      }
      CPA_COMMIT();
      CPA_WAIT1();     // chunk cc landed; chunk cc+1 may be in flight
    } else {
      CPA_WAIT0();
    }
    __syncthreads();   // publish B chunk cc (+ A on first iter; Cs stores of cc-1 done)
    float acc[2][4][4];
    #pragma unroll
    for (int mt=0;mt<2;mt++)
      #pragma unroll
      for (int nt=0;nt<4;nt++)
        #pragma unroll
        for (int q=0;q<4;q++) acc[mt][nt][q] = 0.f;
    const uint4* bp4 = (const uint4*)(BpBase + (cc & 1) * 32768);
    #pragma unroll
    for (int k16 = 0; k16 < 8; ++k16) {
      uint32_t a[2][4];
      #pragma unroll
      for (int mt=0;mt<2;mt++)
        ldsm4(a[mt], asb + ((wm*32 + mt*16 + (lane & 15))*GAS + k16*16 + ((lane >> 4) << 3))*2);
      uint4 b40 = bp4[(k16*8 + wn*2    )*32 + lane];
      uint4 b41 = bp4[(k16*8 + wn*2 + 1)*32 + lane];
      uint32_t bb[4][2];
      bb[0][0]=b40.x; bb[0][1]=b40.y; bb[1][0]=b40.z; bb[1][1]=b40.w;
      bb[2][0]=b41.x; bb[2][1]=b41.y; bb[3][0]=b41.z; bb[3][1]=b41.w;
      #pragma unroll
      for (int mt=0;mt<2;mt++)
        #pragma unroll
        for (int nt=0;nt<4;nt++)
          mma16(acc[mt][nt], a[mt], bb[nt]);
    }
    if (obf) {
      #pragma unroll
      for (int mt=0;mt<2;mt++) {
        int row0 = wm*32 + mt*16 + g;
        #pragma unroll
        for (int nt=0;nt<4;nt++) {
          int col = wn*32 + nt*8 + 2*t4;
          float bc0 = bias[c0+col], bc1 = bias[c0+col+1];
          #pragma unroll
          for (int h=0; h<2; ++h) {
            int row = row0 + 8*h;
            Cs[row*65 + (col >> 1)] = bf2(acc[mt][nt][2*h+0] + bc0, acc[mt][nt][2*h+1] + bc1);
          }
        }
      }
      __syncthreads();
      #pragma unroll
      for (int it = 0; it < 16; ++it) {
        int f = it*256 + tid;
        int r = f >> 6, q = f & 63;
        *(uint32_t*)((__nv_bfloat16*)C + (long long)(m0+r)*ldc + c0 + 2*q) = Cs[r*65 + q];
      }
    } else {
      #pragma unroll
      for (int mt=0;mt<2;mt++) {
        int row0 = m0 + wm*32 + mt*16 + g;
        #pragma unroll
        for (int nt=0;nt<4;nt++) {
          int col = c0 + wn*32 + nt*8 + 2*t4;
          float bc0 = bias[col], bc1 = bias[col+1];
          #pragma unroll
          for (int h=0; h<2; ++h) {
            int row = row0 + 8*h;
            float2 o = {acc[mt][nt][2*h+0] + bc0, acc[mt][nt][2*h+1] + bc1};
            *(float2*)((float*)C + (long long)row*ldc + col) = o;
          }
        }
      }
    }
  }
}

// -------------------- GRU scan, 512 thr, cp.async staging (32 rows/CTA) --------------------
#define A_STRIDE 136
#define A_BUF    (32*A_STRIDE)
#define XS_STRIDE 392
#define XS_BUF   (32*XS_STRIDE)
__global__ __launch_bounds__(512, 1)
void gru_scan_mma(const __nv_bfloat16* __restrict__ Xp, const uint32_t* __restrict__ Bpack,
                  const float* __restrict__ brec, __nv_bfloat16* __restrict__ hsb) {
  extern __shared__ char smc[];
  __nv_bfloat16* Ab = (__nv_bfloat16*)smc;
  __nv_bfloat16* Xs = (__nv_bfloat16*)(smc + 34816);
  const int tid = threadIdx.x;    // 512
  const int w2 = tid >> 5, lane = tid & 31;
  const int w = w2 >> 1, ntw = w2 & 1;
  const int g = lane >> 2, t4 = lane & 3;
  const int b0 = blockIdx.x * 32;
  const int csub = w2*8 + 2*t4;
  const uint32_t abb = cvta_s(Ab);
  const uint32_t xsb = cvta_s(Xs);
  const int xr0 = tid / 48 + 0,  xq0 = tid % 48;
  const int xr1 = (512+tid)/48,  xq1 = (512+tid)%48;
  const int xr2 = (1024+tid)/48, xq2 = (1024+tid)%48;
  uint2 breg[24];
  #pragma unroll
  for (int k16=0;k16<8;++k16)
    #pragma unroll
    for (int j=0;j<3;++j)
      breg[k16*3+j] = ((const uint2*)Bpack)[(((k16*24) + j*8 + w)*32 + lane)*2 + ntw];
  for (int i = tid; i < A_BUF; i += 512) ((uint32_t*)Ab)[i] = 0u;
  cpa16(xsb + (xr0*XS_STRIDE + xq0*8)*2, Xp + ((long long)(b0+xr0)*T + 0)*N3 + xq0*8);
  cpa16(xsb + (xr1*XS_STRIDE + xq1*8)*2, Xp + ((long long)(b0+xr1)*T + 0)*N3 + xq1*8);
  cpa16(xsb + (xr2*XS_STRIDE + xq2*8)*2, Xp + ((long long)(b0+xr2)*T + 0)*N3 + xq2*8);
  CPA_COMMIT();
  float2 bz = *(const float2*)(brec + csub);
  float2 brr = *(const float2*)(brec + 128 + csub);
  float2 bh = *(const float2*)(brec + 256 + csub);
  float h[2][2][2];
  #pragma unroll
  for (int a1=0;a1<2;a1++)
    #pragma unroll
    for (int a2=0;a2<2;a2++) { h[a1][a2][0]=0.f; h[a1][a2][1]=0.f; }

  for (int t = 0; t < T; ++t) {
    CPA_WAIT0();
    __syncthreads();
    if (t + 1 < T) {
      uint32_t xw = xsb + (uint32_t)(((t+1) & 1) * XS_BUF * 2);
      cpa16(xw + (xr0*XS_STRIDE + xq0*8)*2, Xp + ((long long)(b0+xr0)*T + t+1)*N3 + xq0*8);
      cpa16(xw + (xr1*XS_STRIDE + xq1*8)*2, Xp + ((long long)(b0+xr1)*T + t+1)*N3 + xq1*8);
      cpa16(xw + (xr2*XS_STRIDE + xq2*8)*2, Xp + ((long long)(b0+xr2)*T + t+1)*N3 + xq2*8);
      CPA_COMMIT();
    }
    if (t >= 1) {
      const uint4* Au = (const uint4*)(Ab + (t & 1) * A_BUF);
      int r = tid >> 4, q = tid & 15;
      *((uint4*)(hsb + ((long long)(b0+r)*T + (t-1))*128) + q) = Au[r*17 + q];
    }
    const __nv_bfloat16* Xc = Xs + (t & 1) * XS_BUF;
    const uint32_t arb = abb + (uint32_t)((t & 1) * A_BUF * 2);
    __nv_bfloat16* Aw = Ab + ((t & 1) ^ 1) * A_BUF;
    float2 xz[2][2], xr[2][2], xh[2][2];
    #pragma unroll
    for (int mt=0;mt<2;mt++)
      #pragma unroll
      for (int rh=0;rh<2;rh++) {
        const __nv_bfloat16* xp = Xc + (mt*16 + rh*8 + g)*XS_STRIDE + csub;
        xz[mt][rh] = bf2f(*(const uint32_t*)(xp));
        xr[mt][rh] = bf2f(*(const uint32_t*)(xp + 128));
        xh[mt][rh] = bf2f(*(const uint32_t*)(xp + 256));
      }
    float acc[2][3][4];
    #pragma unroll
    for (int mt=0;mt<2;mt++)
      #pragma unroll
      for (int j=0;j<3;j++)
        #pragma unroll
        for (int q=0;q<4;q++) acc[mt][j][q] = 0.f;
    #pragma unroll
    for (int k16=0;k16<8;++k16) {
      uint32_t a[2][4];
      #pragma unroll
      for (int mt=0;mt<2;mt++)
        ldsm4(a[mt], arb + ((mt*16 + (lane & 15))*A_STRIDE + k16*16 + ((lane >> 4) << 3))*2);
      #pragma unroll
      for (int mt=0;mt<2;mt++)
        #pragma unroll
        for (int j=0;j<3;j++)
          mma16(acc[mt][j], a[mt], (const uint32_t*)&breg[k16*3+j]);
    }
    #pragma unroll
    for (int mt=0;mt<2;mt++)
      #pragma unroll
      for (int rh=0;rh<2;rh++) {
        int row = mt*16 + rh*8 + g;
        float hn0, hn1;
        {
          float z  = sigt(xz[mt][rh].x + acc[mt][0][rh*2] + bz.x);
          float r  = sigt(xr[mt][rh].x + acc[mt][1][rh*2] + brr.x);
          float hc = tanha(xh[mt][rh].x + r*(acc[mt][2][rh*2] + bh.x));
          float ho = h[mt][rh][0];
          hn0 = z*ho + (1.f - z)*hc;
          h[mt][rh][0] = hn0;
        }
        {
          float z  = sigt(xz[mt][rh].y + acc[mt][0][rh*2+1] + bz.y);
          float r  = sigt(xr[mt][rh].y + acc[mt][1][rh*2+1] + brr.y);
          float hc = tanha(xh[mt][rh].y + r*(acc[mt][2][rh*2+1] + bh.y));
          float ho = h[mt][rh][1];
          hn1 = z*ho + (1.f - z)*hc;
          h[mt][rh][1] = hn1;
        }
        *(uint32_t*)(Aw + row*A_STRIDE + csub) = bf2(hn0, hn1);
      }
  }
  __syncthreads();
  {
    const uint4* Au = (const uint4*)(Ab);
    int r = tid >> 4, q = tid & 15;
    *((uint4*)(hsb + ((long long)(b0+r)*T + (T-1))*128) + q) = Au[r*17 + q];
  }
}

// -------------------- AUGRU scan, 512 thr, cp.async staging --------------------
__global__ __launch_bounds__(512, 1)
void augru_scan_mma(const __nv_bfloat16* __restrict__ X3, const uint32_t* __restrict__ Bpack) {
  extern __shared__ char smc[];
  __nv_bfloat16* Ab = (__nv_bfloat16*)smc;
  __nv_bfloat16* Xs = (__nv_bfloat16*)(smc + 34816);
  float* ats_s = (float*)(smc + 34816 + 50176);
  const int tid = threadIdx.x;
  const int w2 = tid >> 5, lane = tid & 31;
  const int w = w2 >> 1, ntw = w2 & 1;
  const int g = lane >> 2, t4 = lane & 3;
  const int b0 = blockIdx.x * 32;
  const int csub = w2*8 + 2*t4;
  const uint32_t abb = cvta_s(Ab);
  const uint32_t xsb = cvta_s(Xs);
  const uint32_t atb = cvta_s(ats_s);
  const int xr0 = tid / 48,      xq0 = tid % 48;
  const int xr1 = (512+tid)/48,  xq1 = (512+tid)%48;
  const int xr2 = (1024+tid)/48, xq2 = (1024+tid)%48;
  uint2 breg[24];
  #pragma unroll
  for (int k16=0;k16<8;++k16)
    #pragma unroll
    for (int j=0;j<3;++j)
      breg[k16*3+j] = ((const uint2*)Bpack)[(((k16*24) + j*8 + w)*32 + lane)*2 + ntw];
  for (int i = tid; i < A_BUF; i += 512) ((uint32_t*)Ab)[i] = 0u;
  cpa16(xsb + (xr0*XS_STRIDE + xq0*8)*2, X3 + ((long long)(b0+xr0)*T + 0)*N3 + xq0*8);
  cpa16(xsb + (xr1*XS_STRIDE + xq1*8)*2, X3 + ((long long)(b0+xr1)*T + 0)*N3 + xq1*8);
  cpa16(xsb + (xr2*XS_STRIDE + xq2*8)*2, X3 + ((long long)(b0+xr2)*T + 0)*N3 + xq2*8);
  if (tid < 32) {
    asm volatile("cp.async.ca.shared.global [%0], [%1], 4;"
                 :: "r"(atb + tid*4), "l"(g_ats + (long long)(b0+tid)*T + 0));
  }
  CPA_COMMIT();
  float h[2][2][2];
  #pragma unroll
  for (int a1=0;a1<2;a1++)
    #pragma unroll
    for (int a2=0;a2<2;a2++) { h[a1][a2][0]=0.f; h[a1][a2][1]=0.f; }

  for (int t = 0; t < T; ++t) {
    CPA_WAIT0();
    __syncthreads();
    if (t + 1 < T) {
      uint32_t xw = xsb + (uint32_t)(((t+1) & 1) * XS_BUF * 2);
      cpa16(xw + (xr0*XS_STRIDE + xq0*8)*2, X3 + ((long long)(b0+xr0)*T + t+1)*N3 + xq0*8);
      cpa16(xw + (xr1*XS_STRIDE + xq1*8)*2, X3 + ((long long)(b0+xr1)*T + t+1)*N3 + xq1*8);
      cpa16(xw + (xr2*XS_STRIDE + xq2*8)*2, X3 + ((long long)(b0+xr2)*T + t+1)*N3 + xq2*8);
      if (tid < 32) {
        asm volatile("cp.async.ca.shared.global [%0], [%1], 4;"
                     :: "r"(atb + (((t+1)&1)*32 + tid)*4),
                        "l"(g_ats + (long long)(b0+tid)*T + t+1));
      }
      CPA_COMMIT();
    }
    const __nv_bfloat16* Xc = Xs + (t & 1) * XS_BUF;
    const float* atc = ats_s + (t & 1) * 32;
    const uint32_t arb = abb + (uint32_t)((t & 1) * A_BUF * 2);
    __nv_bfloat16* Aw = Ab + ((t & 1) ^ 1) * A_BUF;
    float2 xu[2][2], xr[2][2], xc[2][2];
    float at[2][2];
    #pragma unroll
    for (int mt=0;mt<2;mt++)
      #pragma unroll
      for (int rh=0;rh<2;rh++) {
        at[mt][rh] = atc[mt*16 + rh*8 + g];
        const __nv_bfloat16* xp = Xc + (mt*16 + rh*8 + g)*XS_STRIDE + csub;
        xu[mt][rh] = bf2f(*(const uint32_t*)(xp));
        xr[mt][rh] = bf2f(*(const uint32_t*)(xp + 128));
        xc[mt][rh] = bf2f(*(const uint32_t*)(xp + 256));
      }
    float acc[2][3][4];
    #pragma unroll
    for (int mt=0;mt<2;mt++)
      #pragma unroll
      for (int j=0;j<3;j++)
        #pragma unroll
        for (int q=0;q<4;q++) acc[mt][j][q] = 0.f;
    #pragma unroll
    for (int k16=0;k16<8;++k16) {
      uint32_t a[2][4];
      #pragma unroll
      for (int mt=0;mt<2;mt++)
        ldsm4(a[mt], arb + ((mt*16 + (lane & 15))*A_STRIDE + k16*16 + ((lane >> 4) << 3))*2);
      #pragma unroll
      for (int mt=0;mt<2;mt++)
        #pragma unroll
        for (int j=0;j<3;j++)
          mma16(acc[mt][j], a[mt], (const uint32_t*)&breg[k16*3+j]);
    }
    #pragma unroll
    for (int mt=0;mt<2;mt++)
      #pragma unroll
      for (int rh=0;rh<2;rh++) {
        int row = mt*16 + rh*8 + g;
        float atv = at[mt][rh];
        float hn0, hn1;
        {
          float u  = sigt(xu[mt][rh].x + acc[mt][0][rh*2]);
          float r  = sigt(xr[mt][rh].x + acc[mt][1][rh*2]);
          float cc = tanha(xc[mt][rh].x + r*acc[mt][2][rh*2]);
          float uu = atv*u;
          float ho = h[mt][rh][0];
          hn0 = (1.f - uu)*ho + uu*cc;
          h[mt][rh][0] = hn0;
        }
        {
          float u  = sigt(xu[mt][rh].y + acc[mt][0][rh*2+1]);
          float r  = sigt(xr[mt][rh].y + acc[mt][1][rh*2+1]);
          float cc = tanha(xc[mt][rh].y + r*acc[mt][2][rh*2+1]);
          float uu = atv*u;
          float ho = h[mt][rh][1];
          hn1 = (1.f - uu)*ho + uu*cc;
          h[mt][rh][1] = hn1;
        }
        *(uint32_t*)(Aw + row*A_STRIDE + csub) = bf2(hn0, hn1);
      }
  }
  #pragma unroll
  for (int mt=0;mt<2;mt++)
    #pragma unroll
    for (int rh=0;rh<2;rh++) {
      int row = mt*16 + rh*8 + g;
      float2 o = {h[mt][rh][0], h[mt][rh][1]};
      *(float2*)(g_hfin + (long long)(b0+row)*128 + csub) = o;
    }
}

// ------------- fused attention (bf16): hs,news -> a1 -> a2 -> ats -------------
#define ATT_AS 264
__global__ __launch_bounds__(256, 1)
void att_fused(const __nv_bfloat16* __restrict__ hsb, const float* __restrict__ inputs,
               const uint32_t* __restrict__ Wcatp, const uint32_t* __restrict__ W2p,
               const float* __restrict__ b2, const float* __restrict__ W3,
               const float* __restrict__ b3, const float* __restrict__ nterm) {
  extern __shared__ char smc[];
  __nv_bfloat16* As  = (__nv_bfloat16*)smc;            // 64 x 264
  uint32_t* Wc  = (uint32_t*)(smc + 33792);            // 16384 u32
  __nv_bfloat16* a1s = (__nv_bfloat16*)(smc + 99328);  // 64 x 136
  uint32_t* W2s = (uint32_t*)(smc + 116736);           // 4096 u32
  float* a2s = (float*)(smc + 133120);                 // 64 x 68
  float* W3s = (float*)(smc + 150528);                 // 64
  const int tid = threadIdx.x;     // 256
  const int lane = tid & 31, wid = tid >> 5;
  const int wm = wid & 1, wn = wid >> 1;
  const int wm3 = wid & 3, wn3 = wid >> 2;
  const int g = lane >> 2, t4 = lane & 3;
  const float b3v = b3[0];

  {
    const uint4* src = (const uint4*)Wcatp;
    uint4* dst = (uint4*)Wc;
    #pragma unroll
    for (int it = 0; it < 16; ++it) dst[it*256 + tid] = src[it*256 + tid];
    const uint4* src2 = (const uint4*)W2p;
    uint4* dst2 = (uint4*)W2s;
    #pragma unroll
    for (int it = 0; it < 4; ++it) dst2[it*256 + tid] = src2[it*256 + tid];
    if (tid < 64) W3s[tid] = W3[tid];
  }
  const uint32_t asb = cvta_s(As);
  const uint32_t a1b = cvta_s(a1s);
  const uint4* Wc4 = (const uint4*)Wc;
  const uint4* W2p4 = (const uint4*)W2s;

  for (long long blk = blockIdx.x; blk < BT/64; blk += gridDim.x) {
    const long long m0 = blk * 64;
    __syncthreads();
    #pragma unroll
    for (int it = 0; it < 8; ++it) {
      int idx = it*256 + tid;
      int r = idx >> 5, q = idx & 31;
      long long row = m0 + r;
      const __nv_bfloat16* hp = hsb + row*128;
      if (q < 16) {
        cpa16(asb + (r*ATT_AS + q*8)*2, hp + q*8);
      } else {
        int qq = q - 16;
        int b = (int)(row / T);
        uint4 v = *(const uint4*)(hp + qq*8);
        const float* nw = inputs + ((long long)b*(T+1) + T)*128 + qq*8;
        float4 n0 = *(const float4*)(nw);
        float4 n1 = *(const float4*)(nw + 4);
        float2 h0 = bf2f(v.x), h1 = bf2f(v.y), h2 = bf2f(v.z), h3 = bf2f(v.w);
        uint4 o;
        o.x = bf2(h0.x*n0.x, h0.y*n0.y);
        o.y = bf2(h1.x*n0.z, h1.y*n0.w);
        o.z = bf2(h2.x*n1.x, h2.y*n1.y);
        o.w = bf2(h3.x*n1.z, h3.y*n1.w);
        *(uint4*)(As + r*ATT_AS + 128 + qq*8) = o;
      }
    }
    CPA_COMMIT();
    CPA_WAIT0();
    __syncthreads();
    float acc[2][4][4];
    #pragma unroll
    for (int mt=0;mt<2;mt++)
      #pragma unroll
      for (int nt=0;nt<4;nt++)
        #pragma unroll
        for (int q=0;q<4;q++) acc[mt][nt][q] = 0.f;
    #pragma unroll
    for (int k16 = 0; k16 < 16; ++k16) {
      uint32_t a[2][4];
      #pragma unroll
      for (int mt=0;mt<2;mt++)
        ldsm4(a[mt], asb + ((wm*32 + mt*16 + (lane & 15))*ATT_AS + k16*16 + ((lane >> 4) << 3))*2);
      uint4 b40 = Wc4[(k16*8 + wn*2    )*32 + lane];
      uint4 b41 = Wc4[(k16*8 + wn*2 + 1)*32 + lane];
      uint32_t bb[4][2];
      bb[0][0]=b40.x; bb[0][1]=b40.y; bb[1][0]=b40.z; bb[1][1]=b40.w;
      bb[2][0]=b41.x; bb[2][1]=b41.y; bb[3][0]=b41.z; bb[3][1]=b41.w;
      #pragma unroll
      for (int mt=0;mt<2;mt++)
        #pragma unroll
        for (int nt=0;nt<4;nt++)
          mma16(acc[mt][nt], a[mt], bb[nt]);
    }
    #pragma unroll
    for (int mt=0;mt<2;mt++) {
      int row0 = wm*32 + mt*16 + g;
      #pragma unroll
      for (int nt=0;nt<4;nt++) {
        int col = wn*32 + nt*8 + 2*t4;
        #pragma unroll
        for (int h=0; h<2; ++h) {
          int row = row0 + 8*h;
          long long rowg = m0 + row;
          const float* np = nterm + (long long)(rowg / T)*128;
          float v0 = fmaxf(acc[mt][nt][2*h+0] + np[col],   0.f);
          float v1 = fmaxf(acc[mt][nt][2*h+1] + np[col+1], 0.f);
          *(uint32_t*)(a1s + row*A_STRIDE + col) = bf2(v0, v1);
        }
      }
    }
    __syncthreads();
    {
      float acc2[4][4];
      #pragma unroll
      for (int nt=0;nt<4;nt++)
        #pragma unroll
        for (int q=0;q<4;q++) acc2[nt][q] = 0.f;
      #pragma unroll
      for (int k16 = 0; k16 < 8; ++k16) {
        uint32_t a[4];
        ldsm4(a, a1b + ((wm3*16 + (lane & 15))*A_STRIDE + k16*16 + ((lane >> 4) << 3))*2);
        uint4 b40 = W2p4[(k16*4 + wn3*2    )*32 + lane];
        uint4 b41 = W2p4[(k16*4 + wn3*2 + 1)*32 + lane];
        uint32_t bb[4][2];
        bb[0][0]=b40.x; bb[0][1]=b40.y; bb[1][0]=b40.z; bb[1][1]=b40.w;
        bb[2][0]=b41.x; bb[2][1]=b41.y; bb[3][0]=b41.z; bb[3][1]=b41.w;
        #pragma unroll
        for (int nt=0;nt<4;nt++)
          mma16(acc2[nt], a, bb[nt]);
      }
      #pragma unroll
      for (int nt=0;nt<4;nt++) {
        int col = wn3*32 + nt*8 + 2*t4;
        float bc0 = b2[col], bc1 = b2[col+1];
        #pragma unroll
        for (int h=0; h<2; ++h) {
          int row = wm3*16 + g + 8*h;
          a2s[row*68 + col]     = fmaxf(acc2[nt][2*h+0] + bc0, 0.f);
          a2s[row*68 + col + 1] = fmaxf(acc2[nt][2*h+1] + bc1, 0.f);
        }
      }
    }
    __syncthreads();
    if (tid < 64) {
      float accv = b3v;
      #pragma unroll 8
      for (int cc=0; cc<64; ++cc) accv = fmaf(a2s[tid*68 + cc], W3s[cc], accv);
      g_ats[m0 + tid] = sigf(accv);
    }
  }
}

// ------------------------------ head ------------------------------
__global__ void head_kernel(const float* __restrict__ inputs,
                            const float* __restrict__ gamma, const float* __restrict__ beta,
                            const float* __restrict__ mean,  const float* __restrict__ var,
                            const float* __restrict__ W1, const float* __restrict__ bb1,
                            const float* __restrict__ W2, const float* __restrict__ bb2,
                            const float* __restrict__ fW, const float* __restrict__ fb,
                            float* __restrict__ out) {
  extern __shared__ float sm[];
  float* xs  = sm;          // 32*256
  float* y1s = xs + 8192;   // 32*256
  float* y2s = y1s + 8192;  // 32*128
  const int tid = threadIdx.x;   // 256
  const int b0 = blockIdx.x * 32;
  for (int r = 0; r < 32; ++r) {
    int k = tid;
    int bb = b0 + r;
    float v = (k < 128) ? g_hfin[bb*128 + k]
                        : inputs[((long long)bb*(T+1) + T)*128 + (k - 128)];
    float nv = (v - mean[k]) * rsqrtf(var[k] + BN_EPS) * gamma[k] + beta[k];
    xs[r*256 + k] = nv;
  }
  __syncthreads();
  {
    float acc[32];
    #pragma unroll
    for (int r=0;r<32;r++) acc[r] = bb1[tid];
    for (int k=0;k<256;++k) {
      float w = W1[k*256 + tid];
      #pragma unroll
      for (int r=0;r<32;r++) acc[r] = fmaf(xs[r*256+k], w, acc[r]);
    }
    #pragma unroll
    for (int r=0;r<32;r++) {
      float v = acc[r];
      y1s[r*256 + tid] = v >= 0.f ? v : LEAKY*v;
    }
  }
  __syncthreads();
  if (tid < 128) {
    float acc[32];
    #pragma unroll
    for (int r=0;r<32;r++) acc[r] = bb2[tid];
    for (int k=0;k<256;++k) {
      float w = W2[k*128 + tid];
      #pragma unroll
      for (int r=0;r<32;r++) acc[r] = fmaf(y1s[r*256+k], w, acc[r]);
    }
    #pragma unroll
    for (int r=0;r<32;r++) {
      float v = acc[r];
      y2s[r*128 + tid] = v >= 0.f ? v : LEAKY*v;
    }
  }
  __syncthreads();
  if (tid < 32) {
    float acc = fb[0];
    for (int k=0;k<128;++k) acc = fmaf(y2s[tid*128+k], fW[k], acc);
    out[b0 + tid] = sigf(acc);
  }
}

// ------------------------------ launch ------------------------------
extern "C" void kernel_launch(void* const* d_in, const int* in_sizes, int n_in,
                              void* d_out, int out_size) {
  (void)in_sizes; (void)n_in; (void)out_size;
  const float* inputs  = (const float*)d_in[0];
  const float* gru_W   = (const float*)d_in[1];
  const float* gru_U   = (const float*)d_in[2];
  const float* gru_b   = (const float*)d_in[3];
  const float* att_W1  = (const float*)d_in[4];
  const float* att_b1  = (const float*)d_in[5];
  const float* att_W2  = (const float*)d_in[6];
  const float* att_b2  = (const float*)d_in[7];
  const float* att_W3  = (const float*)d_in[8];
  const float* att_b3  = (const float*)d_in[9];
  const float* au_Wu   = (const float*)d_in[10];
  const float* au_bu   = (const float*)d_in[11];
  const float* au_Uu   = (const float*)d_in[12];
  const float* au_Wr   = (const float*)d_in[13];
  const float* au_br   = (const float*)d_in[14];
  const float* au_Ur   = (const float*)d_in[15];
  const float* au_Wc   = (const float*)d_in[16];
  const float* au_bc   = (const float*)d_in[17];
  const float* au_Uc   = (const float*)d_in[18];
  const float* bn_gamma= (const float*)d_in[19];
  const float* bn_beta = (const float*)d_in[20];
  const float* bn_mean = (const float*)d_in[21];
  const float* bn_var  = (const float*)d_in[22];
  const float* d_W1    = (const float*)d_in[23];
  const float* d_b1    = (const float*)d_in[24];
  const float* d_W2    = (const float*)d_in[25];
  const float* d_b2    = (const float*)d_in[26];
  const float* f_W     = (const float*)d_in[27];
  const float* f_b     = (const float*)d_in[28];
  float* out = (float*)d_out;

  const size_t sm_gemm  = 17408 + 65536 + 16640;             // 99584
  const size_t sm_gru   = 34816 + 50176;                     // 84992
  const size_t sm_au    = 34816 + 50176 + 256;               // 85248
  const size_t sm_attf  = 150784;
  const size_t sm_head  = (8192*2 + 4096)*sizeof(float);
  cudaFuncSetAttribute(gemm_bf16,      cudaFuncAttributeMaxDynamicSharedMemorySize, (int)sm_gemm);
  cudaFuncSetAttribute(gru_scan_mma,   cudaFuncAttributeMaxDynamicSharedMemorySize, (int)sm_gru);
  cudaFuncSetAttribute(augru_scan_mma, cudaFuncAttributeMaxDynamicSharedMemorySize, (int)sm_au);
  cudaFuncSetAttribute(att_fused,      cudaFuncAttributeMaxDynamicSharedMemorySize, (int)sm_attf);
  cudaFuncSetAttribute(head_kernel,    cudaFuncAttributeMaxDynamicSharedMemorySize, (int)sm_head);

  float *p_Xp, *p_X3, *p_newsterm, *p_bau;
  __nv_bfloat16 *p_hsb;
  uint32_t *p_Ubg, *p_Uba, *p_WbgW, *p_Wbau, *p_Wb1bc, *p_Wbcat, *p_Wbatt2;
  cudaGetSymbolAddress((void**)&p_Xp,       g_Xp);
  cudaGetSymbolAddress((void**)&p_hsb,      g_hsb);
  cudaGetSymbolAddress((void**)&p_X3,       g_X3);
  cudaGetSymbolAddress((void**)&p_newsterm, g_newsterm);
  cudaGetSymbolAddress((void**)&p_bau,      g_bau);
  cudaGetSymbolAddress((void**)&p_Ubg,      g_Ubf_gru);
  cudaGetSymbolAddress((void**)&p_Uba,      g_Ubf_au);
  cudaGetSymbolAddress((void**)&p_WbgW,     g_Wb_gruW);
  cudaGetSymbolAddress((void**)&p_Wbau,     g_Wb_au);
  cudaGetSymbolAddress((void**)&p_Wb1bc,    g_Wb_1bc);
  cudaGetSymbolAddress((void**)&p_Wbcat,    g_Wb_cat);
  cudaGetSymbolAddress((void**)&p_Wbatt2,   g_Wb_att2);

  cudaStream_t s2;
  cudaStreamCreateWithFlags(&s2, cudaStreamNonBlocking);
  cudaEvent_t evRoot, evSide, evFork, evJoin;
  cudaEventCreateWithFlags(&evRoot, cudaEventDisableTiming);
  cudaEventCreateWithFlags(&evSide, cudaEventDisableTiming);
  cudaEventCreateWithFlags(&evFork, cudaEventDisableTiming);
  cudaEventCreateWithFlags(&evJoin, cudaEventDisableTiming);

  // fork s2 from the capture-origin stream FIRST (required for graph capture)
  cudaEventRecord(evRoot, 0);
  cudaStreamWaitEvent(s2, evRoot, 0);
  // main: pack_a -> Xp -> gru
  pack_a<<<208, 256>>>(gru_U, gru_W, att_W2);
  // side: prep -> pack_b -> newsterm
  prep_kernel<<<192, 256, 0, s2>>>(au_Wu, au_bu, au_Wr, au_br, au_Wc, au_bc,
                                   au_Uu, au_Ur, au_Uc, att_W1);
  pack_b<<<288, 256, 0, s2>>>();
  gemm_bf16<<<B/64, 256, sm_gemm, s2>>>(inputs + (long long)T*128, 1, (long long)(T+1)*128, 128,
                                        p_Wb1bc, 8, att_b1, p_newsterm, 128, 0, 0);
  cudaEventRecord(evSide, s2);
  // Xp = hist @ gru_W + gru_b[0]
  gemm_bf16<<<BT/64, 256, sm_gemm>>>(inputs, T, (long long)(T+1)*128, 128,
                                     p_WbgW, 24, gru_b, p_Xp, 384, 1, 0);
  // GRU recurrence -> hsb
  gru_scan_mma<<<B/32, 512, sm_gru>>>((const __nv_bfloat16*)p_Xp, p_Ubg, gru_b + 384, p_hsb);
  // fork: X3 gemm on s2, attention on main
  cudaEventRecord(evFork, 0);
  cudaStreamWaitEvent(s2, evFork, 0);
  gemm_bf16<<<BT/64, 256, sm_gemm, s2>>>(p_hsb, 1<<30, 0LL, 128,
                                         p_Wbau, 24, p_bau, p_X3, 384, 1, 1);
  cudaEventRecord(evJoin, s2);
  // attention (needs newsterm + Wb_cat from side stream)
  cudaStreamWaitEvent(0, evSide, 0);
  att_fused<<<148, 256, sm_attf>>>(p_hsb, inputs, p_Wbcat, p_Wbatt2,
                                   att_b2, att_W3, att_b3, p_newsterm);
  cudaStreamWaitEvent(0, evJoin, 0);
  // AUGRU recurrence -> hfin
  augru_scan_mma<<<B/32, 512, sm_au>>>((const __nv_bfloat16*)p_X3, p_Uba);
  // BN + dense head -> out
  head_kernel<<<B/32, 256, sm_head>>>(inputs, bn_gamma, bn_beta, bn_mean, bn_var,
                                      d_W1, d_b1, d_W2, d_b2, f_W, f_b, out);
}